// round 9
// baseline (speedup 1.0000x reference)
#include <cuda_runtime.h>
#include <cuda_bf16.h>
#include <math.h>
#include <stdint.h>

// ---------------- problem constants ----------------
#define ND   8
#define FF   64
#define RR   36
#define DD   1024
#define MS   16
#define WW   10
#define BH   768
#define HH   1024
#define ED   20
#define SD   2324
#define NSPAN (ND*MS)          // 128
#define NPAIR (NSPAN*NSPAN)    // 16384
#define NEGV (-1e10f)

#define KPAD1 2368             // 74 * 32
#define KPAD2 1024             // 32 * 32
#define NT1   (KPAD1/32)
#define NT2   (KPAD2/32)

// ---------------- scratch ----------------
__device__ __align__(16) float g_hspan[1280*HH];
__device__ __align__(16) float g_scores[1280];
__device__ __align__(16) float g_spans[NSPAN*SD + 64];   // +pad for over-read
__device__ __align__(16) float g_a[NSPAN*HH];
__device__ __align__(16) float g_b[NSPAN*HH];
__device__ __align__(16) __nv_bfloat16 g_B1hi[HH*KPAD1]; // [n][k] = pw1[2SD+k][n]
__device__ __align__(16) __nv_bfloat16 g_B1lo[HH*KPAD1];
__device__ __align__(16) __nv_bfloat16 g_W2hi[HH*KPAD2]; // [n][k] = pw2[k][n]
__device__ __align__(16) __nv_bfloat16 g_W2lo[HH*KPAD2];
__device__ __align__(16) __nv_bfloat16 g_h1hi[(long)NPAIR*HH];
__device__ __align__(16) __nv_bfloat16 g_h1lo[(long)NPAIR*HH];
__device__ __align__(16) float g_ts[NPAIR];
__device__ __align__(16) float g_att[64*FF*RR];
__device__ float g_Sg[64];
__device__ float g_Sc[64];

#define FMA2(d,a,b) asm("fma.rn.f32x2 %0, %1, %2, %0;" : "+l"(d) : "l"(a), "l"(b))

// ---------------- warp MMA helpers (generic sm_80+ path; no tcgen05) ----------------
__device__ __forceinline__ unsigned smem_u32(const void* p) {
    unsigned a;
    asm("{ .reg .u64 t; cvta.to.shared.u64 t, %1; cvt.u32.u64 %0, t; }" : "=r"(a) : "l"(p));
    return a;
}
__device__ __forceinline__ void ldsm_x4(unsigned& r0, unsigned& r1, unsigned& r2, unsigned& r3,
                                        unsigned addr) {
    asm volatile("ldmatrix.sync.aligned.m8n8.x4.shared.b16 {%0,%1,%2,%3}, [%4];"
                 : "=r"(r0), "=r"(r1), "=r"(r2), "=r"(r3) : "r"(addr));
}
__device__ __forceinline__ void mma_bf16(float (&c)[4], const unsigned (&a)[4],
                                         unsigned b0, unsigned b1) {
    asm volatile(
        "mma.sync.aligned.m16n8k16.row.col.f32.bf16.bf16.f32 "
        "{%0,%1,%2,%3}, {%4,%5,%6,%7}, {%8,%9}, {%0,%1,%2,%3};"
        : "+f"(c[0]), "+f"(c[1]), "+f"(c[2]), "+f"(c[3])
        : "r"(a[0]), "r"(a[1]), "r"(a[2]), "r"(a[3]), "r"(b0), "r"(b1));
}
__device__ __forceinline__ void bf16_split(float v, unsigned short& h, unsigned short& l) {
    __nv_bfloat16 hb = __float2bfloat16(v);
    __nv_bfloat16 lb = __float2bfloat16(v - __bfloat162float(hb));
    h = __bfloat16_as_ushort(hb);
    l = __bfloat16_as_ushort(lb);
}

// smem tile: [128 rows][40 bf16]  (80B stride -> conflict-free ldmatrix)
#define TROW 40

// ---------------- prep: split W1c/W2 into bf16 hi/lo [n][k]; init g_ts=pb3 ----------------
// Mapping: consecutive threads cover consecutive n -> coalesced reads of pw1/pw2 rows.
#define PREP_G1 (HH*(KPAD1/8))
#define PREP_G2 (HH*(KPAD2/8))
__global__ void prep_kernel(const float* __restrict__ pw1, const float* __restrict__ pw2,
                            const float* __restrict__ pb3)
{
    int gid = blockIdx.x*256 + threadIdx.x;
    if (gid < PREP_G1) {
        int n = gid % HH, kg = gid / HH;
        union { uint4 q; unsigned short us[8]; } H, L;
        #pragma unroll
        for (int e = 0; e < 8; e++) {
            int k = kg*8 + e;
            float v = (k < SD) ? pw1[((long)(2*SD + k))*HH + n] : 0.f;
            bf16_split(v, H.us[e], L.us[e]);
        }
        *(uint4*)(g_B1hi + (long)n*KPAD1 + kg*8) = H.q;
        *(uint4*)(g_B1lo + (long)n*KPAD1 + kg*8) = L.q;
    } else if (gid < PREP_G1 + PREP_G2) {
        int j = gid - PREP_G1;
        int n = j % HH, kg = j / HH;
        union { uint4 q; unsigned short us[8]; } H, L;
        #pragma unroll
        for (int e = 0; e < 8; e++) {
            int k = kg*8 + e;
            float v = pw2[(long)k*HH + n];
            bf16_split(v, H.us[e], L.us[e]);
        }
        *(uint4*)(g_W2hi + (long)n*KPAD2 + kg*8) = H.q;
        *(uint4*)(g_W2lo + (long)n*KPAD2 + kg*8) = L.q;
    } else {
        int i = gid - PREP_G1 - PREP_G2;
        if (i < NPAIR) g_ts[i] = pb3[0];
    }
}

// ---------------- h1 HMMA kernel: h1 = relu(prod @ W1c + a + b + b1) -> bf16 hi/lo ----------------
// Register-prefetch pipeline: LDGs for tile t+1 issue right after the pre-MMA sync,
// overlapping the MMA phase; split+STS happen post-MMA from landed registers.
__global__ void __launch_bounds__(256)
h1_mma_kernel(const float* __restrict__ pb1)
{
    __shared__ __align__(16) __nv_bfloat16 sAhi[128*TROW], sAlo[128*TROW];
    __shared__ __align__(16) __nv_bfloat16 sBhi[128*TROW], sBlo[128*TROW];
    unsigned sbAhi = smem_u32(sAhi), sbAlo = smem_u32(sAlo);
    unsigned sbBhi = smem_u32(sBhi), sbBlo = smem_u32(sBlo);

    int tid = threadIdx.x, lane = tid & 31, wid = tid >> 5;
    int wy = wid & 3, wx = wid >> 2;
    int m0 = blockIdx.y*128, n0 = blockIdx.x*128;

    int lrow = tid >> 1, lks = (tid & 1)*16;
    int lgrow = m0 + lrow;
    int lii = (lgrow >> 4) & 15, ljj = lgrow & 15, lsv = lgrow >> 8;
    const float* pa  = g_spans + (long)((lsv >> 3)*MS + lii)*SD;
    const float* pbs = g_spans + (long)((lsv & 7)*MS + ljj)*SD;
    const __nv_bfloat16* bhsrc = g_B1hi + (long)(n0 + lrow)*KPAD1;
    const __nv_bfloat16* blsrc = g_B1lo + (long)(n0 + lrow)*KPAD1;

    float c[2][8][4];
    #pragma unroll
    for (int i = 0; i < 2; i++)
        #pragma unroll
        for (int j = 0; j < 8; j++)
            #pragma unroll
            for (int e = 0; e < 4; e++) c[i][j][e] = 0.f;

    float p[16];
    uint4 bhv[2], blv[2];

    // prefetch tile 0
    {
        int kk = lks;
        #pragma unroll
        for (int q = 0; q < 4; q++) {
            float4 x = *(const float4*)(pa  + kk + q*4);
            float4 y = *(const float4*)(pbs + kk + q*4);
            p[q*4+0] = x.x*y.x; p[q*4+1] = x.y*y.y;
            p[q*4+2] = x.z*y.z; p[q*4+3] = x.w*y.w;
        }
        bhv[0] = *(const uint4*)(bhsrc + kk);
        bhv[1] = *(const uint4*)(bhsrc + kk + 8);
        blv[0] = *(const uint4*)(blsrc + kk);
        blv[1] = *(const uint4*)(blsrc + kk + 8);
    }

    for (int t = 0; t < NT1; t++) {
        // split+store current tile (registers -> smem)
        {
            int kk = t*32 + lks;
            if (kk + 16 > SD) {
                #pragma unroll
                for (int e = 0; e < 16; e++) if (kk + e >= SD) p[e] = 0.f;
            }
            union { uint4 q[2]; unsigned short us[16]; } H, L;
            #pragma unroll
            for (int e = 0; e < 16; e++) bf16_split(p[e], H.us[e], L.us[e]);
            *(uint4*)&sAhi[lrow*TROW + lks]     = H.q[0];
            *(uint4*)&sAhi[lrow*TROW + lks + 8] = H.q[1];
            *(uint4*)&sAlo[lrow*TROW + lks]     = L.q[0];
            *(uint4*)&sAlo[lrow*TROW + lks + 8] = L.q[1];
            *(uint4*)&sBhi[lrow*TROW + lks]     = bhv[0];
            *(uint4*)&sBhi[lrow*TROW + lks + 8] = bhv[1];
            *(uint4*)&sBlo[lrow*TROW + lks]     = blv[0];
            *(uint4*)&sBlo[lrow*TROW + lks + 8] = blv[1];
        }
        __syncthreads();

        // prefetch next tile (LDGs overlap the MMA phase)
        if (t + 1 < NT1) {
            int kk = (t+1)*32 + lks;
            #pragma unroll
            for (int q = 0; q < 4; q++) {
                float4 x = *(const float4*)(pa  + kk + q*4);
                float4 y = *(const float4*)(pbs + kk + q*4);
                p[q*4+0] = x.x*y.x; p[q*4+1] = x.y*y.y;
                p[q*4+2] = x.z*y.z; p[q*4+3] = x.w*y.w;
            }
            bhv[0] = *(const uint4*)(bhsrc + kk);
            bhv[1] = *(const uint4*)(bhsrc + kk + 8);
            blv[0] = *(const uint4*)(blsrc + kk);
            blv[1] = *(const uint4*)(blsrc + kk + 8);
        }

        #pragma unroll
        for (int kt = 0; kt < 2; kt++) {
            unsigned ah[2][4], al[2][4], bh[4][4], bl[4][4];
            int arow = lane & 15, acol = (lane >> 4)*8;
            #pragma unroll
            for (int mt = 0; mt < 2; mt++) {
                unsigned off = (unsigned)(((wy*32 + mt*16 + arow)*TROW + kt*16 + acol)*2);
                ldsm_x4(ah[mt][0], ah[mt][1], ah[mt][2], ah[mt][3], sbAhi + off);
                ldsm_x4(al[mt][0], al[mt][1], al[mt][2], al[mt][3], sbAlo + off);
            }
            int nrow = (lane & 7) + ((lane >> 4) << 3), kc = lane & 8;
            #pragma unroll
            for (int np = 0; np < 4; np++) {
                unsigned off = (unsigned)(((wx*64 + np*16 + nrow)*TROW + kt*16 + kc)*2);
                ldsm_x4(bh[np][0], bh[np][1], bh[np][2], bh[np][3], sbBhi + off);
                ldsm_x4(bl[np][0], bl[np][1], bl[np][2], bl[np][3], sbBlo + off);
            }
            #pragma unroll
            for (int mt = 0; mt < 2; mt++)
                #pragma unroll
                for (int nt = 0; nt < 8; nt++) {
                    int np = nt >> 1, h = (nt & 1)*2;
                    mma_bf16(c[mt][nt], ah[mt], bh[np][h], bh[np][h+1]);
                    mma_bf16(c[mt][nt], ah[mt], bl[np][h], bl[np][h+1]);
                    mma_bf16(c[mt][nt], al[mt], bh[np][h], bh[np][h+1]);
                }
        }
        __syncthreads();
    }

    // epilogue: +bias +a +b, relu, split, store bf16 hi/lo
    int g = lane >> 2, t4 = lane & 3;
    #pragma unroll
    for (int mt = 0; mt < 2; mt++) {
        #pragma unroll
        for (int rr = 0; rr < 2; rr++) {
            int grow = m0 + wy*32 + mt*16 + rr*8 + g;
            int ii = (grow >> 4) & 15, jj = grow & 15, sv = grow >> 8;
            int rA = (sv >> 3)*MS + ii, rB = (sv & 7)*MS + jj;
            #pragma unroll
            for (int nt = 0; nt < 8; nt++) {
                int col = n0 + wx*64 + nt*8 + 2*t4;
                float v0 = c[mt][nt][rr*2+0] + pb1[col]
                         + g_a[rA*HH + col] + g_b[rB*HH + col];
                float v1 = c[mt][nt][rr*2+1] + pb1[col+1]
                         + g_a[rA*HH + col+1] + g_b[rB*HH + col+1];
                v0 = fmaxf(v0, 0.f); v1 = fmaxf(v1, 0.f);
                unsigned short h0, l0, h1, l1;
                bf16_split(v0, h0, l0); bf16_split(v1, h1, l1);
                *(unsigned*)&g_h1hi[(long)grow*HH + col] = (unsigned)h0 | ((unsigned)h1 << 16);
                *(unsigned*)&g_h1lo[(long)grow*HH + col] = (unsigned)l0 | ((unsigned)l1 << 16);
            }
        }
    }
}

// ---------------- h2 HMMA kernel: ts += (relu(h1@W2 + b2)) @ w3 ----------------
__global__ void __launch_bounds__(256)
h2_mma_kernel(const float* __restrict__ pb2, const float* __restrict__ pw3)
{
    __shared__ __align__(16) __nv_bfloat16 sAhi[128*TROW], sAlo[128*TROW];
    __shared__ __align__(16) __nv_bfloat16 sBhi[128*TROW], sBlo[128*TROW];
    __shared__ float w3s[128], pb2s[128];
    unsigned sbAhi = smem_u32(sAhi), sbAlo = smem_u32(sAlo);
    unsigned sbBhi = smem_u32(sBhi), sbBlo = smem_u32(sBlo);

    int tid = threadIdx.x, lane = tid & 31, wid = tid >> 5;
    int wy = wid & 3, wx = wid >> 2;
    int m0 = blockIdx.y*128, n0 = blockIdx.x*128;

    if (tid < 128) { w3s[tid] = pw3[n0 + tid]; pb2s[tid] = pb2[n0 + tid]; }

    int lrow = tid >> 1, lks = (tid & 1)*16;
    const __nv_bfloat16* ahsrc = g_h1hi + (long)(m0 + lrow)*HH;
    const __nv_bfloat16* alsrc = g_h1lo + (long)(m0 + lrow)*HH;
    const __nv_bfloat16* bhsrc = g_W2hi + (long)(n0 + lrow)*KPAD2;
    const __nv_bfloat16* blsrc = g_W2lo + (long)(n0 + lrow)*KPAD2;

    float c[2][8][4];
    #pragma unroll
    for (int i = 0; i < 2; i++)
        #pragma unroll
        for (int j = 0; j < 8; j++)
            #pragma unroll
            for (int e = 0; e < 4; e++) c[i][j][e] = 0.f;

    uint4 ahv[2], alv[2], bhv[2], blv[2];
    {
        int kk = lks;
        ahv[0] = *(const uint4*)(ahsrc + kk); ahv[1] = *(const uint4*)(ahsrc + kk + 8);
        alv[0] = *(const uint4*)(alsrc + kk); alv[1] = *(const uint4*)(alsrc + kk + 8);
        bhv[0] = *(const uint4*)(bhsrc + kk); bhv[1] = *(const uint4*)(bhsrc + kk + 8);
        blv[0] = *(const uint4*)(blsrc + kk); blv[1] = *(const uint4*)(blsrc + kk + 8);
    }

    for (int t = 0; t < NT2; t++) {
        *(uint4*)&sAhi[lrow*TROW + lks]     = ahv[0];
        *(uint4*)&sAhi[lrow*TROW + lks + 8] = ahv[1];
        *(uint4*)&sAlo[lrow*TROW + lks]     = alv[0];
        *(uint4*)&sAlo[lrow*TROW + lks + 8] = alv[1];
        *(uint4*)&sBhi[lrow*TROW + lks]     = bhv[0];
        *(uint4*)&sBhi[lrow*TROW + lks + 8] = bhv[1];
        *(uint4*)&sBlo[lrow*TROW + lks]     = blv[0];
        *(uint4*)&sBlo[lrow*TROW + lks + 8] = blv[1];
        __syncthreads();

        if (t + 1 < NT2) {
            int kk = (t+1)*32 + lks;
            ahv[0] = *(const uint4*)(ahsrc + kk); ahv[1] = *(const uint4*)(ahsrc + kk + 8);
            alv[0] = *(const uint4*)(alsrc + kk); alv[1] = *(const uint4*)(alsrc + kk + 8);
            bhv[0] = *(const uint4*)(bhsrc + kk); bhv[1] = *(const uint4*)(bhsrc + kk + 8);
            blv[0] = *(const uint4*)(blsrc + kk); blv[1] = *(const uint4*)(blsrc + kk + 8);
        }

        #pragma unroll
        for (int kt = 0; kt < 2; kt++) {
            unsigned ah[2][4], al[2][4], bh[4][4], bl[4][4];
            int arow = lane & 15, acol = (lane >> 4)*8;
            #pragma unroll
            for (int mt = 0; mt < 2; mt++) {
                unsigned off = (unsigned)(((wy*32 + mt*16 + arow)*TROW + kt*16 + acol)*2);
                ldsm_x4(ah[mt][0], ah[mt][1], ah[mt][2], ah[mt][3], sbAhi + off);
                ldsm_x4(al[mt][0], al[mt][1], al[mt][2], al[mt][3], sbAlo + off);
            }
            int nrow = (lane & 7) + ((lane >> 4) << 3), kc = lane & 8;
            #pragma unroll
            for (int np = 0; np < 4; np++) {
                unsigned off = (unsigned)(((wx*64 + np*16 + nrow)*TROW + kt*16 + kc)*2);
                ldsm_x4(bh[np][0], bh[np][1], bh[np][2], bh[np][3], sbBhi + off);
                ldsm_x4(bl[np][0], bl[np][1], bl[np][2], bl[np][3], sbBlo + off);
            }
            #pragma unroll
            for (int mt = 0; mt < 2; mt++)
                #pragma unroll
                for (int nt = 0; nt < 8; nt++) {
                    int np = nt >> 1, h = (nt & 1)*2;
                    mma_bf16(c[mt][nt], ah[mt], bh[np][h], bh[np][h+1]);
                    mma_bf16(c[mt][nt], ah[mt], bl[np][h], bl[np][h+1]);
                    mma_bf16(c[mt][nt], al[mt], bh[np][h], bh[np][h+1]);
                }
        }
        __syncthreads();
    }

    // epilogue: relu(+b2) dot w3 over this block's 128 cols; reduce; atomicAdd into g_ts
    int g = lane >> 2, t4 = lane & 3;
    #pragma unroll
    for (int mt = 0; mt < 2; mt++) {
        float p0 = 0.f, p1 = 0.f;
        #pragma unroll
        for (int nt = 0; nt < 8; nt++) {
            int lc = wx*64 + nt*8 + 2*t4;
            p0 += fmaxf(c[mt][nt][0] + pb2s[lc],   0.f)*w3s[lc]
                + fmaxf(c[mt][nt][1] + pb2s[lc+1], 0.f)*w3s[lc+1];
            p1 += fmaxf(c[mt][nt][2] + pb2s[lc],   0.f)*w3s[lc]
                + fmaxf(c[mt][nt][3] + pb2s[lc+1], 0.f)*w3s[lc+1];
        }
        p0 += __shfl_xor_sync(0xffffffffu, p0, 1);
        p0 += __shfl_xor_sync(0xffffffffu, p0, 2);
        p1 += __shfl_xor_sync(0xffffffffu, p1, 1);
        p1 += __shfl_xor_sync(0xffffffffu, p1, 2);
        if (t4 == 0) {
            atomicAdd(&g_ts[m0 + wy*32 + mt*16 + g],     p0);
            atomicAdd(&g_ts[m0 + wy*32 + mt*16 + 8 + g], p1);
        }
    }
}

// ---------------- SIMT span GEMM (1280x1024x768, bias+relu; also zeroes g_a/g_b) ----------------
#define BM 128
#define BN 128
#define BK 16
#define TM 8
#define TN 8

__global__ __launch_bounds__(256, 2)
void span_gemm_kernel(const float* __restrict__ A, const float* __restrict__ B,
                      const float* __restrict__ bias)
{
    const int N = HH, K = BH;
    float* C = g_hspan;

    __shared__ __align__(16) float2 As2[2][BK][BM];
    __shared__ __align__(16) float  Bs[2][BK][BN];

    int tid = threadIdx.x;
    {   // zero g_a/g_b for split-K atomics
        float4 z = make_float4(0.f,0.f,0.f,0.f);
        int gt = (blockIdx.y*gridDim.x + blockIdx.x)*256 + tid;
        int nb = gridDim.x*gridDim.y*256;
        for (int i = gt; i < NSPAN*HH/4; i += nb) {
            ((float4*)g_a)[i] = z;
            ((float4*)g_b)[i] = z;
        }
    }
    int m0 = blockIdx.y * BM;
    int n0 = blockIdx.x * BN;

    int la_row = tid >> 1, la_cb = (tid & 1) * 8;
    int lb_row = tid >> 4, lb_col = (tid & 15) * 8;

    unsigned long long acc2[TM][TN/2];
    #pragma unroll
    for (int i = 0; i < TM; i++)
        #pragma unroll
        for (int j = 0; j < TN/2; j++) acc2[i][j] = 0ull;

    int tx = tid & 15, ty = tid >> 4;
    int ntiles = K / BK;

    float4 aR[2], bR[2];
    #pragma unroll
    for (int c = 0; c < 2; c++) {
        aR[c] = *(const float4*)(A + (long)(m0+la_row)*K + la_cb + c*4);
        bR[c] = *(const float4*)(B + (long)lb_row*N + n0 + lb_col + c*4);
    }
    #pragma unroll
    for (int c = 0; c < 2; c++) {
        int kc = la_cb + c*4;
        As2[0][kc+0][la_row] = make_float2(aR[c].x, aR[c].x);
        As2[0][kc+1][la_row] = make_float2(aR[c].y, aR[c].y);
        As2[0][kc+2][la_row] = make_float2(aR[c].z, aR[c].z);
        As2[0][kc+3][la_row] = make_float2(aR[c].w, aR[c].w);
        *(float4*)&Bs[0][lb_row][lb_col + c*4] = bR[c];
    }
    __syncthreads();

    for (int t = 0; t < ntiles; t++) {
        int cur = t & 1, nxt = cur ^ 1;
        bool more = (t + 1 < ntiles);
        if (more) {
            int k0 = (t + 1) * BK;
            #pragma unroll
            for (int c = 0; c < 2; c++) {
                aR[c] = *(const float4*)(A + (long)(m0+la_row)*K + k0 + la_cb + c*4);
                bR[c] = *(const float4*)(B + (long)(k0+lb_row)*N + n0 + lb_col + c*4);
            }
        }
        #pragma unroll
        for (int kk = 0; kk < BK; kk++) {
            unsigned long long rm2[TM], rb2[TN/2];
            #pragma unroll
            for (int i = 0; i < TM; i += 2) {
                ulonglong2 v = *(const ulonglong2*)&As2[cur][kk][ty*TM + i];
                rm2[i] = v.x; rm2[i+1] = v.y;
            }
            #pragma unroll
            for (int j = 0; j < TN/2; j += 2) {
                ulonglong2 v = *(const ulonglong2*)&Bs[cur][kk][tx*TN + 2*j];
                rb2[j] = v.x; rb2[j+1] = v.y;
            }
            #pragma unroll
            for (int i = 0; i < TM; i++)
                #pragma unroll
                for (int j = 0; j < TN/2; j++)
                    FMA2(acc2[i][j], rm2[i], rb2[j]);
        }
        if (more) {
            #pragma unroll
            for (int c = 0; c < 2; c++) {
                int kc = la_cb + c*4;
                As2[nxt][kc+0][la_row] = make_float2(aR[c].x, aR[c].x);
                As2[nxt][kc+1][la_row] = make_float2(aR[c].y, aR[c].y);
                As2[nxt][kc+2][la_row] = make_float2(aR[c].z, aR[c].z);
                As2[nxt][kc+3][la_row] = make_float2(aR[c].w, aR[c].w);
                *(float4*)&Bs[nxt][lb_row][lb_col + c*4] = bR[c];
            }
        }
        __syncthreads();
    }

    #pragma unroll
    for (int i = 0; i < TM; i++) {
        int row = m0 + ty*TM + i;
        #pragma unroll
        for (int q = 0; q < 2; q++) {
            int col = n0 + tx*TN + q*4;
            float v0 = __uint_as_float((unsigned)(acc2[i][2*q]   & 0xffffffffull));
            float v1 = __uint_as_float((unsigned)(acc2[i][2*q]   >> 32));
            float v2 = __uint_as_float((unsigned)(acc2[i][2*q+1] & 0xffffffffull));
            float v3 = __uint_as_float((unsigned)(acc2[i][2*q+1] >> 32));
            float4 bv = *(const float4*)(bias + col);
            v0 = fmaxf(v0 + bv.x, 0.f); v1 = fmaxf(v1 + bv.y, 0.f);
            v2 = fmaxf(v2 + bv.z, 0.f); v3 = fmaxf(v3 + bv.w, 0.f);
            *(float4*)(C + (long)row*N + col) = make_float4(v0, v1, v2, v3);
        }
    }
}

// ---------------- split-K GEMM computing g_a and g_b together ----------------
#define KS 8
#define KSLC 292   // multiple of 4 (float4 alignment); 8*292 >= 2324

__global__ __launch_bounds__(256, 2)
void gemm_ab_kernel(const float* __restrict__ pw1)
{
    __shared__ __align__(16) float2 As2[BK][BM];
    __shared__ __align__(16) float  Bs[BK][BN];

    int tid = threadIdx.x;
    int n0 = blockIdx.x * BN;
    int kstart = blockIdx.y * KSLC;
    int kend = min(kstart + KSLC, SD);

    const float* Bsel = (n0 < HH) ? pw1 + n0 : pw1 + (long)SD*HH + (n0 - HH);
    float* Cout = (n0 < HH) ? g_a + n0 : g_b + (n0 - HH);

    int la_row = tid >> 1, la_cb = (tid & 1) * 8;
    int lb_row = tid >> 4, lb_col = (tid & 15) * 8;

    unsigned long long acc2[TM][TN/2];
    #pragma unroll
    for (int i = 0; i < TM; i++)
        #pragma unroll
        for (int j = 0; j < TN/2; j++) acc2[i][j] = 0ull;

    int tx = tid & 15, ty = tid >> 4;

    for (int k0 = kstart; k0 < kend; k0 += BK) {
        #pragma unroll
        for (int c = 0; c < 2; c++) {
            int k = k0 + la_cb + c*4;
            float4 v = make_float4(0.f,0.f,0.f,0.f);
            if (k < kend) v = *(const float4*)(g_spans + (long)la_row*SD + k);
            int kc = la_cb + c*4;
            As2[kc+0][la_row] = make_float2(v.x, v.x);
            As2[kc+1][la_row] = make_float2(v.y, v.y);
            As2[kc+2][la_row] = make_float2(v.z, v.z);
            As2[kc+3][la_row] = make_float2(v.w, v.w);
            int kb = k0 + lb_row;
            float4 w = make_float4(0.f,0.f,0.f,0.f);
            if (kb < kend) w = *(const float4*)(Bsel + (long)kb*HH + lb_col + c*4);
            *(float4*)&Bs[lb_row][lb_col + c*4] = w;
        }
        __syncthreads();
        #pragma unroll
        for (int kk = 0; kk < BK; kk++) {
            unsigned long long rm2[TM], rb2[TN/2];
            #pragma unroll
            for (int i = 0; i < TM; i += 2) {
                ulonglong2 v = *(const ulonglong2*)&As2[kk][ty*TM + i];
                rm2[i] = v.x; rm2[i+1] = v.y;
            }
            #pragma unroll
            for (int j = 0; j < TN/2; j += 2) {
                ulonglong2 v = *(const ulonglong2*)&Bs[kk][tx*TN + 2*j];
                rb2[j] = v.x; rb2[j+1] = v.y;
            }
            #pragma unroll
            for (int i = 0; i < TM; i++)
                #pragma unroll
                for (int j = 0; j < TN/2; j++)
                    FMA2(acc2[i][j], rm2[i], rb2[j]);
        }
        __syncthreads();
    }

    #pragma unroll
    for (int i = 0; i < TM; i++) {
        int row = ty*TM + i;
        #pragma unroll
        for (int j = 0; j < TN/2; j++) {
            int col = tx*TN + 2*j;
            float v0 = __uint_as_float((unsigned)(acc2[i][j] & 0xffffffffull));
            float v1 = __uint_as_float((unsigned)(acc2[i][j] >> 32));
            atomicAdd(Cout + (long)row*HH + col,     v0);
            atomicAdd(Cout + (long)row*HH + col + 1, v1);
        }
    }
}

// ---------------- matvec for span scores ----------------
__global__ void matvec_scores(const float* __restrict__ w, const float* __restrict__ bias)
{
    int warp = (blockIdx.x*blockDim.x + threadIdx.x) >> 5;
    int lane = threadIdx.x & 31;
    if (warp >= 1280) return;
    const float4* a4 = (const float4*)(g_hspan + (long)warp*1024);
    const float4* w4 = (const float4*)w;
    float s = 0.f;
    #pragma unroll 4
    for (int c = lane; c < 256; c += 32) {
        float4 x = a4[c], y = w4[c];
        s += x.x*y.x + x.y*y.y + x.z*y.z + x.w*y.w;
    }
    #pragma unroll
    for (int o = 16; o > 0; o >>= 1) s += __shfl_xor_sync(0xffffffffu, s, o);
    if (lane == 0) g_scores[warp] = s + bias[0];
}

// ---------------- span softmax + assemble spans ----------------
__global__ void assemble_kernel(const float* __restrict__ se, const float* __restrict__ cont,
                                const int* __restrict__ width, const float* __restrict__ wemb)
{
    int b = blockIdx.x;
    int tid = threadIdx.x;
    __shared__ float attn[WW];
    int w = width[b];
    if (tid == 0) {
        float sc[WW]; float mx = -INFINITY;
        for (int t = 0; t < WW; t++) {
            sc[t] = (t < w) ? g_scores[b*WW + t] : NEGV;
            mx = fmaxf(mx, sc[t]);
        }
        float sum = 0.f;
        for (int t = 0; t < WW; t++) { sc[t] = expf(sc[t] - mx); sum += sc[t]; }
        for (int t = 0; t < WW; t++) attn[t] = sc[t]/sum;
    }
    __syncthreads();
    float* row = g_spans + (long)b*SD;
    for (int k = tid; k < 2*BH; k += 256) row[k] = se[(long)b*2*BH + k];
    for (int d = tid; d < BH; d += 256) {
        float acc = 0.f;
        #pragma unroll
        for (int t = 0; t < WW; t++) acc += attn[t]*cont[((long)b*WW + t)*BH + d];
        row[2*BH + d] = acc;
    }
    if (tid < ED) row[2*BH + BH + tid] = wemb[min(w,4)*ED + tid];
}

// ---------------- grounding: att[s,v,i,j] = doc[s,i,:]·img[v,j,:] ----------------
__global__ void att_kernel(const float* __restrict__ doc, const float* __restrict__ img)
{
    int b = blockIdx.x, s = b >> 3, v = b & 7;
    for (int idx = threadIdx.x; idx < FF*RR; idx += blockDim.x) {
        int i = idx / RR, j = idx % RR;
        const float4* dr = (const float4*)(doc + (long)(s*FF + i)*DD);
        const float4* ir = (const float4*)(img + (long)(v*RR + j)*DD);
        float acc = 0.f;
        #pragma unroll 8
        for (int c = 0; c < DD/4; c++) {
            float4 x = dr[c], y = ir[c];
            acc += x.x*y.x + x.y*y.y + x.z*y.z + x.w*y.w;
        }
        g_att[((long)b*FF + i)*RR + j] = acc;
    }
}

// ---------------- grounding reduce -> S_g ----------------
__global__ void ground_reduce(const float* __restrict__ tm, const float* __restrict__ im)
{
    __shared__ float sh[FF][RR+1];
    __shared__ float stm[FF], sim[RR];
    __shared__ float red[FF];
    int b = blockIdx.x, s = b >> 3, v = b & 7;
    int tid = threadIdx.x; // 64
    if (tid < FF) stm[tid] = tm[s*FF + tid];
    if (tid < RR) sim[tid] = im[v*RR + tid];
    __syncthreads();
    for (int idx = tid; idx < FF*RR; idx += 64) {
        int i = idx / RR, j = idx % RR;
        float a = g_att[((long)b*FF + i)*RR + j];
        float m = stm[i]*sim[j];
        a *= m;
        if (a == 0.f) a = NEGV;
        sh[i][j] = a;
    }
    __syncthreads();
    float part = 0.f;
    {
        int i = tid;
        float mx = -INFINITY;
        for (int j = 0; j < RR; j++) mx = fmaxf(mx, sh[i][j]*sim[j]);
        float ssum = 0.f;
        for (int j = 0; j < RR; j++) ssum += expf(sh[i][j]*sim[j] - mx);
        for (int j = 0; j < RR; j++) {
            float aw = expf(sh[i][j]*sim[j] - mx)/ssum * stm[i]*sim[j];
            part += aw * sh[i][j];
        }
    }
    if (tid < RR) {
        int j = tid;
        float mx = -INFINITY;
        for (int i = 0; i < FF; i++) mx = fmaxf(mx, sh[i][j]);
        float ssum = 0.f;
        for (int i = 0; i < FF; i++) ssum += expf(sh[i][j] - mx);
        for (int i = 0; i < FF; i++) {
            float aw = expf(sh[i][j] - mx)/ssum * stm[i]*sim[j];
            part += aw * sh[i][j];
        }
    }
    red[tid] = part;
    __syncthreads();
    for (int o = 32; o > 0; o >>= 1) {
        if (tid < o) red[tid] += red[tid+o];
        __syncthreads();
    }
    if (tid == 0) g_Sg[b] = red[0];
}

// ---------------- adaptive S_c ----------------
__global__ void sc_kernel(const float* __restrict__ m1)
{
    int b = blockIdx.x, s = b >> 3, v = b & 7;
    const float* T = g_ts + (long)b*MS*MS;
    int lane = threadIdx.x;
    float cs = 0.f, cv = 0.f;
    for (int k = 0; k < MS; k++) { cs += m1[s*MS+k]; cv += m1[v*MS+k]; }
    float max1 = -INFINITY, max2 = -INFINITY;
    if (lane < MS) {
        float rm = 0.f;
        for (int j = 0; j < MS; j++) rm += T[lane*MS+j]*m1[v*MS+j];
        rm /= cv;
        if (m1[s*MS+lane] > 0.f) max1 = rm;
        float cm = 0.f;
        for (int i = 0; i < MS; i++) cm += T[i*MS+lane]*m1[s*MS+i];
        cm /= cs;
        if (m1[v*MS+lane] > 0.f) max2 = cm;
    }
    for (int o = 16; o > 0; o >>= 1) {
        max1 = fmaxf(max1, __shfl_xor_sync(0xffffffffu, max1, o));
        max2 = fmaxf(max2, __shfl_xor_sync(0xffffffffu, max2, o));
    }
    if (lane == 0) g_Sc[b] = 0.5f*(max1 + max2);
}

// ---------------- final loss ----------------
__global__ void loss_kernel(float* __restrict__ out)
{
    if (threadIdx.x != 0) return;
    float mg[8][8], mgT[8][8], mc[8][8];
    for (int s = 0; s < 8; s++) {
        float mx = -INFINITY;
        for (int v = 0; v < 8; v++) mx = fmaxf(mx, g_Sg[s*8+v]);
        float sum = 0.f;
        for (int v = 0; v < 8; v++) { mg[s][v] = expf(g_Sg[s*8+v]-mx); sum += mg[s][v]; }
        for (int v = 0; v < 8; v++) mg[s][v] /= sum;
    }
    for (int v = 0; v < 8; v++) {
        float mx = -INFINITY;
        for (int s = 0; s < 8; s++) mx = fmaxf(mx, g_Sg[s*8+v]);
        float sum = 0.f;
        for (int s = 0; s < 8; s++) { mgT[v][s] = expf(g_Sg[s*8+v]-mx); sum += mgT[v][s]; }
        for (int s = 0; s < 8; s++) mgT[v][s] /= sum;
    }
    for (int s = 0; s < 8; s++) {
        float mx = -INFINITY;
        for (int v = 0; v < 8; v++) mx = fmaxf(mx, g_Sc[s*8+v]);
        float sum = 0.f;
        for (int v = 0; v < 8; v++) { mc[s][v] = expf(g_Sc[s*8+v]-mx); sum += mc[s][v]; }
        for (int v = 0; v < 8; v++) mc[s][v] /= sum;
    }
    float loss = 0.f;
    for (int s = 0; s < 8; s++) {
        float t = 0.f;
        for (int v = 0; v < 8; v++) t += mg[s][v]*mc[s][v];
        loss += logf(t);
    }
    for (int v = 0; v < 8; v++) {
        float t = 0.f;
        for (int s = 0; s < 8; s++) t += mgT[v][s]*mc[v][s];
        loss += logf(t);
    }
    out[0] = -loss/(float)ND;
}

// ---------------- host ----------------
extern "C" void kernel_launch(void* const* d_in, const int* in_sizes, int n_in,
                              void* d_out, int out_size)
{
    const float* doc  = (const float*)d_in[0];
    const float* img  = (const float*)d_in[1];
    const float* tm   = (const float*)d_in[2];
    const float* im   = (const float*)d_in[3];
    const float* se   = (const float*)d_in[4];
    const float* cont = (const float*)d_in[5];
    const int*   width= (const int*)  d_in[6];
    const float* m1   = (const float*)d_in[7];
    const float* aw1  = (const float*)d_in[8];
    const float* ab1  = (const float*)d_in[9];
    const float* aw2  = (const float*)d_in[10];
    const float* ab2  = (const float*)d_in[11];
    const float* wemb = (const float*)d_in[12];
    const float* pw1  = (const float*)d_in[13];
    const float* pb1  = (const float*)d_in[14];
    const float* pw2  = (const float*)d_in[15];
    const float* pb2  = (const float*)d_in[16];
    const float* pw3  = (const float*)d_in[17];
    const float* pb3  = (const float*)d_in[18];

    // (1) split W1c/W2 into bf16 hi/lo; g_ts = pb3
    int prep_total = PREP_G1 + PREP_G2 + NPAIR;
    prep_kernel<<<(prep_total + 255)/256, 256>>>(pw1, pw2, pb3);
    // (2) span attention hidden (also zeroes g_a/g_b)
    span_gemm_kernel<<<dim3(HH/BN, 1280/BM), 256>>>(cont, aw1, ab1);
    // (3) span scores
    matvec_scores<<<(1280*32+255)/256, 256>>>(aw2, ab2);
    // (4) assemble spans
    assemble_kernel<<<NSPAN, 256>>>(se, cont, width, wemb);
    // (5) a,b = spans @ w1 halves (split-K)
    gemm_ab_kernel<<<dim3(2048/BN, KS), 256>>>(pw1);
    // (6) h1 = relu(prod @ W1c + a + b + b1)  [HMMA bf16x3, reg-prefetch pipelined]
    h1_mma_kernel<<<dim3(8, 128), 256>>>(pb1);
    // (7) ts += relu(h1 @ W2 + b2) @ w3  [HMMA bf16x3, fused, pipelined]
    h2_mma_kernel<<<dim3(8, 128), 256>>>(pb2, pw3);

    // grounding (independent)
    att_kernel<<<64, 256>>>(doc, img);
    ground_reduce<<<64, 64>>>(tm, im);

    // adaptive S_c + final loss
    sc_kernel<<<64, 32>>>(m1);
    loss_kernel<<<1, 32>>>((float*)d_out);
}

// round 10
// speedup vs baseline: 1.0596x; 1.0596x over previous
#include <cuda_runtime.h>
#include <cuda_bf16.h>
#include <math.h>
#include <stdint.h>

// ---------------- problem constants ----------------
#define ND   8
#define FF   64
#define RR   36
#define DD   1024
#define MS   16
#define WW   10
#define BH   768
#define HH   1024
#define ED   20
#define SD   2324
#define NSPAN (ND*MS)          // 128
#define NPAIR (NSPAN*NSPAN)    // 16384
#define NEGV (-1e10f)

#define KPAD1 2368             // 74 * 32
#define KPAD2 1024             // 32 * 32
#define NT1   (KPAD1/32)
#define NT2   (KPAD2/32)

// ---------------- scratch ----------------
__device__ __align__(16) float g_hspan[1280*HH];
__device__ __align__(16) float g_scores[1280];
__device__ __align__(16) float g_spans[NSPAN*SD + 64];   // +pad for over-read
__device__ __align__(16) float g_a[NSPAN*HH];
__device__ __align__(16) float g_b[NSPAN*HH];
__device__ __align__(16) __nv_bfloat16 g_B1hi[HH*KPAD1]; // [n][k] = pw1[2SD+k][n]
__device__ __align__(16) __nv_bfloat16 g_B1lo[HH*KPAD1];
__device__ __align__(16) __nv_bfloat16 g_W2hi[HH*KPAD2]; // [n][k] = pw2[k][n]
__device__ __align__(16) __nv_bfloat16 g_W2lo[HH*KPAD2];
__device__ __align__(16) __nv_bfloat16 g_h1hi[(long)NPAIR*HH];
__device__ __align__(16) __nv_bfloat16 g_h1lo[(long)NPAIR*HH];
__device__ __align__(16) float g_ts[NPAIR];
__device__ __align__(16) float g_att[64*FF*RR];
__device__ float g_Sg[64];
__device__ float g_Sc[64];

#define FMA2(d,a,b) asm("fma.rn.f32x2 %0, %1, %2, %0;" : "+l"(d) : "l"(a), "l"(b))

// ---------------- warp MMA helpers (generic sm_80+ path; no tcgen05) ----------------
__device__ __forceinline__ unsigned smem_u32(const void* p) {
    unsigned a;
    asm("{ .reg .u64 t; cvta.to.shared.u64 t, %1; cvt.u32.u64 %0, t; }" : "=r"(a) : "l"(p));
    return a;
}
__device__ __forceinline__ void ldsm_x4(unsigned& r0, unsigned& r1, unsigned& r2, unsigned& r3,
                                        unsigned addr) {
    asm volatile("ldmatrix.sync.aligned.m8n8.x4.shared.b16 {%0,%1,%2,%3}, [%4];"
                 : "=r"(r0), "=r"(r1), "=r"(r2), "=r"(r3) : "r"(addr));
}
__device__ __forceinline__ void mma_bf16(float (&c)[4], const unsigned (&a)[4],
                                         unsigned b0, unsigned b1) {
    asm volatile(
        "mma.sync.aligned.m16n8k16.row.col.f32.bf16.bf16.f32 "
        "{%0,%1,%2,%3}, {%4,%5,%6,%7}, {%8,%9}, {%0,%1,%2,%3};"
        : "+f"(c[0]), "+f"(c[1]), "+f"(c[2]), "+f"(c[3])
        : "r"(a[0]), "r"(a[1]), "r"(a[2]), "r"(a[3]), "r"(b0), "r"(b1));
}
__device__ __forceinline__ void bf16_split(float v, unsigned short& h, unsigned short& l) {
    __nv_bfloat16 hb = __float2bfloat16(v);
    __nv_bfloat16 lb = __float2bfloat16(v - __bfloat162float(hb));
    h = __bfloat16_as_ushort(hb);
    l = __bfloat16_as_ushort(lb);
}
#define CP_ASYNC16(saddr, gptr) \
    asm volatile("cp.async.cg.shared.global [%0], [%1], 16;" :: "r"(saddr), "l"(gptr) : "memory")
#define CP_COMMIT() asm volatile("cp.async.commit_group;" ::: "memory")
#define CP_WAIT0()  asm volatile("cp.async.wait_group 0;" ::: "memory")

// smem tile: [128 rows][40 bf16]  (80B stride -> conflict-free ldmatrix; 80 % 16 == 0)
#define TROW 40
#define MATB 10240                  // bytes per matrix per stage (128*40*2)
#define MATE (128*TROW)             // elements per matrix per stage
#define DSMEM_MMA (8*MATB)          // 81920: {Ahi0,Ahi1,Alo0,Alo1,Bhi0,Bhi1,Blo0,Blo1}

// ---------------- prep: split W1c/W2 into bf16 hi/lo [n][k]; init g_ts=pb3 ----------------
#define PREP_G1 (HH*(KPAD1/8))
#define PREP_G2 (HH*(KPAD2/8))
__global__ void prep_kernel(const float* __restrict__ pw1, const float* __restrict__ pw2,
                            const float* __restrict__ pb3)
{
    int gid = blockIdx.x*256 + threadIdx.x;
    if (gid < PREP_G1) {
        int n = gid % HH, kg = gid / HH;
        union { uint4 q; unsigned short us[8]; } H, L;
        #pragma unroll
        for (int e = 0; e < 8; e++) {
            int k = kg*8 + e;
            float v = (k < SD) ? pw1[((long)(2*SD + k))*HH + n] : 0.f;
            bf16_split(v, H.us[e], L.us[e]);
        }
        *(uint4*)(g_B1hi + (long)n*KPAD1 + kg*8) = H.q;
        *(uint4*)(g_B1lo + (long)n*KPAD1 + kg*8) = L.q;
    } else if (gid < PREP_G1 + PREP_G2) {
        int j = gid - PREP_G1;
        int n = j % HH, kg = j / HH;
        union { uint4 q; unsigned short us[8]; } H, L;
        #pragma unroll
        for (int e = 0; e < 8; e++) {
            int k = kg*8 + e;
            float v = pw2[(long)k*HH + n];
            bf16_split(v, H.us[e], L.us[e]);
        }
        *(uint4*)(g_W2hi + (long)n*KPAD2 + kg*8) = H.q;
        *(uint4*)(g_W2lo + (long)n*KPAD2 + kg*8) = L.q;
    } else {
        int i = gid - PREP_G1 - PREP_G2;
        if (i < NPAIR) g_ts[i] = pb3[0];
    }
}

// ---------------- h1 HMMA kernel (double-buffered, cp.async B) ----------------
__global__ void __launch_bounds__(256)
h1_mma_kernel(const float* __restrict__ pb1)
{
    extern __shared__ __align__(16) char dsm8[];
    __nv_bfloat16* dsm = (__nv_bfloat16*)dsm8;
    unsigned sb = smem_u32(dsm8);

    int tid = threadIdx.x, lane = tid & 31, wid = tid >> 5;
    int wy = wid & 3, wx = wid >> 2;
    int m0 = blockIdx.y*128, n0 = blockIdx.x*128;

    int lrow = tid >> 1, lks = (tid & 1)*16;
    int lgrow = m0 + lrow;
    int lii = (lgrow >> 4) & 15, ljj = lgrow & 15, lsv = lgrow >> 8;
    const float* pa  = g_spans + (long)((lsv >> 3)*MS + lii)*SD;
    const float* pbs = g_spans + (long)((lsv & 7)*MS + ljj)*SD;
    const __nv_bfloat16* bhsrc = g_B1hi + (long)(n0 + lrow)*KPAD1;
    const __nv_bfloat16* blsrc = g_B1lo + (long)(n0 + lrow)*KPAD1;

    unsigned srow = (unsigned)(lrow*TROW + lks)*2;   // byte offset within a matrix

    float c[2][8][4];
    #pragma unroll
    for (int i = 0; i < 2; i++)
        #pragma unroll
        for (int j = 0; j < 8; j++)
            #pragma unroll
            for (int e = 0; e < 4; e++) c[i][j][e] = 0.f;

    // ---- prologue: fill stage 0 ----
    {
        CP_ASYNC16(sb + 4*MATB + srow,      bhsrc + lks);
        CP_ASYNC16(sb + 4*MATB + srow + 16, bhsrc + lks + 8);
        CP_ASYNC16(sb + 6*MATB + srow,      blsrc + lks);
        CP_ASYNC16(sb + 6*MATB + srow + 16, blsrc + lks + 8);
        CP_COMMIT();
        float p[16];
        #pragma unroll
        for (int q = 0; q < 4; q++) {
            float4 x = *(const float4*)(pa  + lks + q*4);
            float4 y = *(const float4*)(pbs + lks + q*4);
            p[q*4+0] = x.x*y.x; p[q*4+1] = x.y*y.y;
            p[q*4+2] = x.z*y.z; p[q*4+3] = x.w*y.w;
        }
        union { uint4 q[2]; unsigned short us[16]; } H, L;
        #pragma unroll
        for (int e = 0; e < 16; e++) bf16_split(p[e], H.us[e], L.us[e]);
        *(uint4*)&dsm[0*MATE + lrow*TROW + lks]     = H.q[0];
        *(uint4*)&dsm[0*MATE + lrow*TROW + lks + 8] = H.q[1];
        *(uint4*)&dsm[2*MATE + lrow*TROW + lks]     = L.q[0];
        *(uint4*)&dsm[2*MATE + lrow*TROW + lks + 8] = L.q[1];
        CP_WAIT0();
    }
    __syncthreads();

    for (int t = 0; t < NT1; t++) {
        int cur = t & 1, nxt = cur ^ 1;
        bool more = (t + 1 < NT1);

        // issue B cp.async for t+1 into next stage BEFORE the MMA phase
        if (more) {
            int kk = (t+1)*32 + lks;
            CP_ASYNC16(sb + (4+nxt)*MATB + srow,      bhsrc + kk);
            CP_ASYNC16(sb + (4+nxt)*MATB + srow + 16, bhsrc + kk + 8);
            CP_ASYNC16(sb + (6+nxt)*MATB + srow,      blsrc + kk);
            CP_ASYNC16(sb + (6+nxt)*MATB + srow + 16, blsrc + kk + 8);
            CP_COMMIT();
        }

        // MMA phase on current stage
        unsigned sbAhi = sb + cur*MATB,       sbAlo = sb + (2+cur)*MATB;
        unsigned sbBhi = sb + (4+cur)*MATB,   sbBlo = sb + (6+cur)*MATB;
        #pragma unroll
        for (int kt = 0; kt < 2; kt++) {
            unsigned ah[2][4], al[2][4], bh[4][4], bl[4][4];
            int arow = lane & 15, acol = (lane >> 4)*8;
            #pragma unroll
            for (int mt = 0; mt < 2; mt++) {
                unsigned off = (unsigned)(((wy*32 + mt*16 + arow)*TROW + kt*16 + acol)*2);
                ldsm_x4(ah[mt][0], ah[mt][1], ah[mt][2], ah[mt][3], sbAhi + off);
                ldsm_x4(al[mt][0], al[mt][1], al[mt][2], al[mt][3], sbAlo + off);
            }
            int nrow = (lane & 7) + ((lane >> 4) << 3), kc = lane & 8;
            #pragma unroll
            for (int np = 0; np < 4; np++) {
                unsigned off = (unsigned)(((wx*64 + np*16 + nrow)*TROW + kt*16 + kc)*2);
                ldsm_x4(bh[np][0], bh[np][1], bh[np][2], bh[np][3], sbBhi + off);
                ldsm_x4(bl[np][0], bl[np][1], bl[np][2], bl[np][3], sbBlo + off);
            }
            #pragma unroll
            for (int mt = 0; mt < 2; mt++)
                #pragma unroll
                for (int nt = 0; nt < 8; nt++) {
                    int np = nt >> 1, h = (nt & 1)*2;
                    mma_bf16(c[mt][nt], ah[mt], bh[np][h], bh[np][h+1]);
                    mma_bf16(c[mt][nt], ah[mt], bl[np][h], bl[np][h+1]);
                    mma_bf16(c[mt][nt], al[mt], bh[np][h], bh[np][h+1]);
                }
        }

        // A tile for t+1 (compute+split) into next stage; overlaps other warps' MMAs
        if (more) {
            int kk = (t+1)*32 + lks;
            float p[16];
            #pragma unroll
            for (int q = 0; q < 4; q++) {
                float4 x = *(const float4*)(pa  + kk + q*4);
                float4 y = *(const float4*)(pbs + kk + q*4);
                p[q*4+0] = x.x*y.x; p[q*4+1] = x.y*y.y;
                p[q*4+2] = x.z*y.z; p[q*4+3] = x.w*y.w;
            }
            if (kk + 16 > SD) {
                #pragma unroll
                for (int e = 0; e < 16; e++) if (kk + e >= SD) p[e] = 0.f;
            }
            union { uint4 q[2]; unsigned short us[16]; } H, L;
            #pragma unroll
            for (int e = 0; e < 16; e++) bf16_split(p[e], H.us[e], L.us[e]);
            *(uint4*)&dsm[(0+nxt)*MATE + lrow*TROW + lks]     = H.q[0];
            *(uint4*)&dsm[(0+nxt)*MATE + lrow*TROW + lks + 8] = H.q[1];
            *(uint4*)&dsm[(2+nxt)*MATE + lrow*TROW + lks]     = L.q[0];
            *(uint4*)&dsm[(2+nxt)*MATE + lrow*TROW + lks + 8] = L.q[1];
        }
        CP_WAIT0();
        __syncthreads();
    }

    // epilogue: +bias +a +b, relu, split, store bf16 hi/lo
    int g = lane >> 2, t4 = lane & 3;
    #pragma unroll
    for (int mt = 0; mt < 2; mt++) {
        #pragma unroll
        for (int rr = 0; rr < 2; rr++) {
            int grow = m0 + wy*32 + mt*16 + rr*8 + g;
            int ii = (grow >> 4) & 15, jj = grow & 15, sv = grow >> 8;
            int rA = (sv >> 3)*MS + ii, rB = (sv & 7)*MS + jj;
            #pragma unroll
            for (int nt = 0; nt < 8; nt++) {
                int col = n0 + wx*64 + nt*8 + 2*t4;
                float v0 = c[mt][nt][rr*2+0] + pb1[col]
                         + g_a[rA*HH + col] + g_b[rB*HH + col];
                float v1 = c[mt][nt][rr*2+1] + pb1[col+1]
                         + g_a[rA*HH + col+1] + g_b[rB*HH + col+1];
                v0 = fmaxf(v0, 0.f); v1 = fmaxf(v1, 0.f);
                unsigned short h0, l0, h1, l1;
                bf16_split(v0, h0, l0); bf16_split(v1, h1, l1);
                *(unsigned*)&g_h1hi[(long)grow*HH + col] = (unsigned)h0 | ((unsigned)h1 << 16);
                *(unsigned*)&g_h1lo[(long)grow*HH + col] = (unsigned)l0 | ((unsigned)l1 << 16);
            }
        }
    }
}

// ---------------- h2 HMMA kernel (double-buffered, all-cp.async; fused ts matvec) ----------------
__global__ void __launch_bounds__(256)
h2_mma_kernel(const float* __restrict__ pb2, const float* __restrict__ pw3)
{
    extern __shared__ __align__(16) char dsm8[];
    unsigned sb = smem_u32(dsm8);
    __shared__ float w3s[128], pb2s[128];

    int tid = threadIdx.x, lane = tid & 31, wid = tid >> 5;
    int wy = wid & 3, wx = wid >> 2;
    int m0 = blockIdx.y*128, n0 = blockIdx.x*128;

    if (tid < 128) { w3s[tid] = pw3[n0 + tid]; pb2s[tid] = pb2[n0 + tid]; }

    int lrow = tid >> 1, lks = (tid & 1)*16;
    const __nv_bfloat16* ahsrc = g_h1hi + (long)(m0 + lrow)*HH;
    const __nv_bfloat16* alsrc = g_h1lo + (long)(m0 + lrow)*HH;
    const __nv_bfloat16* bhsrc = g_W2hi + (long)(n0 + lrow)*KPAD2;
    const __nv_bfloat16* blsrc = g_W2lo + (long)(n0 + lrow)*KPAD2;
    unsigned srow = (unsigned)(lrow*TROW + lks)*2;

    float c[2][8][4];
    #pragma unroll
    for (int i = 0; i < 2; i++)
        #pragma unroll
        for (int j = 0; j < 8; j++)
            #pragma unroll
            for (int e = 0; e < 4; e++) c[i][j][e] = 0.f;

    // prologue: stage 0
    {
        CP_ASYNC16(sb + 0*MATB + srow,      ahsrc + lks);
        CP_ASYNC16(sb + 0*MATB + srow + 16, ahsrc + lks + 8);
        CP_ASYNC16(sb + 2*MATB + srow,      alsrc + lks);
        CP_ASYNC16(sb + 2*MATB + srow + 16, alsrc + lks + 8);
        CP_ASYNC16(sb + 4*MATB + srow,      bhsrc + lks);
        CP_ASYNC16(sb + 4*MATB + srow + 16, bhsrc + lks + 8);
        CP_ASYNC16(sb + 6*MATB + srow,      blsrc + lks);
        CP_ASYNC16(sb + 6*MATB + srow + 16, blsrc + lks + 8);
        CP_COMMIT(); CP_WAIT0();
    }
    __syncthreads();

    for (int t = 0; t < NT2; t++) {
        int cur = t & 1, nxt = cur ^ 1;
        bool more = (t + 1 < NT2);

        if (more) {
            int kk = (t+1)*32 + lks;
            CP_ASYNC16(sb + (0+nxt)*MATB + srow,      ahsrc + kk);
            CP_ASYNC16(sb + (0+nxt)*MATB + srow + 16, ahsrc + kk + 8);
            CP_ASYNC16(sb + (2+nxt)*MATB + srow,      alsrc + kk);
            CP_ASYNC16(sb + (2+nxt)*MATB + srow + 16, alsrc + kk + 8);
            CP_ASYNC16(sb + (4+nxt)*MATB + srow,      bhsrc + kk);
            CP_ASYNC16(sb + (4+nxt)*MATB + srow + 16, bhsrc + kk + 8);
            CP_ASYNC16(sb + (6+nxt)*MATB + srow,      blsrc + kk);
            CP_ASYNC16(sb + (6+nxt)*MATB + srow + 16, blsrc + kk + 8);
            CP_COMMIT();
        }

        unsigned sbAhi = sb + cur*MATB,     sbAlo = sb + (2+cur)*MATB;
        unsigned sbBhi = sb + (4+cur)*MATB, sbBlo = sb + (6+cur)*MATB;
        #pragma unroll
        for (int kt = 0; kt < 2; kt++) {
            unsigned ah[2][4], al[2][4], bh[4][4], bl[4][4];
            int arow = lane & 15, acol = (lane >> 4)*8;
            #pragma unroll
            for (int mt = 0; mt < 2; mt++) {
                unsigned off = (unsigned)(((wy*32 + mt*16 + arow)*TROW + kt*16 + acol)*2);
                ldsm_x4(ah[mt][0], ah[mt][1], ah[mt][2], ah[mt][3], sbAhi + off);
                ldsm_x4(al[mt][0], al[mt][1], al[mt][2], al[mt][3], sbAlo + off);
            }
            int nrow = (lane & 7) + ((lane >> 4) << 3), kc = lane & 8;
            #pragma unroll
            for (int np = 0; np < 4; np++) {
                unsigned off = (unsigned)(((wx*64 + np*16 + nrow)*TROW + kt*16 + kc)*2);
                ldsm_x4(bh[np][0], bh[np][1], bh[np][2], bh[np][3], sbBhi + off);
                ldsm_x4(bl[np][0], bl[np][1], bl[np][2], bl[np][3], sbBlo + off);
            }
            #pragma unroll
            for (int mt = 0; mt < 2; mt++)
                #pragma unroll
                for (int nt = 0; nt < 8; nt++) {
                    int np = nt >> 1, h = (nt & 1)*2;
                    mma_bf16(c[mt][nt], ah[mt], bh[np][h], bh[np][h+1]);
                    mma_bf16(c[mt][nt], ah[mt], bl[np][h], bl[np][h+1]);
                    mma_bf16(c[mt][nt], al[mt], bh[np][h], bh[np][h+1]);
                }
        }
        CP_WAIT0();
        __syncthreads();
    }

    // epilogue: relu(+b2) dot w3; quad reduce; atomicAdd into g_ts
    int g = lane >> 2, t4 = lane & 3;
    #pragma unroll
    for (int mt = 0; mt < 2; mt++) {
        float p0 = 0.f, p1 = 0.f;
        #pragma unroll
        for (int nt = 0; nt < 8; nt++) {
            int lc = wx*64 + nt*8 + 2*t4;
            p0 += fmaxf(c[mt][nt][0] + pb2s[lc],   0.f)*w3s[lc]
                + fmaxf(c[mt][nt][1] + pb2s[lc+1], 0.f)*w3s[lc+1];
            p1 += fmaxf(c[mt][nt][2] + pb2s[lc],   0.f)*w3s[lc]
                + fmaxf(c[mt][nt][3] + pb2s[lc+1], 0.f)*w3s[lc+1];
        }
        p0 += __shfl_xor_sync(0xffffffffu, p0, 1);
        p0 += __shfl_xor_sync(0xffffffffu, p0, 2);
        p1 += __shfl_xor_sync(0xffffffffu, p1, 1);
        p1 += __shfl_xor_sync(0xffffffffu, p1, 2);
        if (t4 == 0) {
            atomicAdd(&g_ts[m0 + wy*32 + mt*16 + g],     p0);
            atomicAdd(&g_ts[m0 + wy*32 + mt*16 + 8 + g], p1);
        }
    }
}

// ---------------- SIMT span GEMM (1280x1024x768, bias+relu; also zeroes g_a/g_b) ----------------
#define BM 128
#define BN 128
#define BK 16
#define TM 8
#define TN 8

__global__ __launch_bounds__(256, 2)
void span_gemm_kernel(const float* __restrict__ A, const float* __restrict__ B,
                      const float* __restrict__ bias)
{
    const int N = HH, K = BH;
    float* C = g_hspan;

    __shared__ __align__(16) float2 As2[2][BK][BM];
    __shared__ __align__(16) float  Bs[2][BK][BN];

    int tid = threadIdx.x;
    {   // zero g_a/g_b for split-K atomics
        float4 z = make_float4(0.f,0.f,0.f,0.f);
        int gt = (blockIdx.y*gridDim.x + blockIdx.x)*256 + tid;
        int nb = gridDim.x*gridDim.y*256;
        for (int i = gt; i < NSPAN*HH/4; i += nb) {
            ((float4*)g_a)[i] = z;
            ((float4*)g_b)[i] = z;
        }
    }
    int m0 = blockIdx.y * BM;
    int n0 = blockIdx.x * BN;

    int la_row = tid >> 1, la_cb = (tid & 1) * 8;
    int lb_row = tid >> 4, lb_col = (tid & 15) * 8;

    unsigned long long acc2[TM][TN/2];
    #pragma unroll
    for (int i = 0; i < TM; i++)
        #pragma unroll
        for (int j = 0; j < TN/2; j++) acc2[i][j] = 0ull;

    int tx = tid & 15, ty = tid >> 4;
    int ntiles = K / BK;

    float4 aR[2], bR[2];
    #pragma unroll
    for (int c = 0; c < 2; c++) {
        aR[c] = *(const float4*)(A + (long)(m0+la_row)*K + la_cb + c*4);
        bR[c] = *(const float4*)(B + (long)lb_row*N + n0 + lb_col + c*4);
    }
    #pragma unroll
    for (int c = 0; c < 2; c++) {
        int kc = la_cb + c*4;
        As2[0][kc+0][la_row] = make_float2(aR[c].x, aR[c].x);
        As2[0][kc+1][la_row] = make_float2(aR[c].y, aR[c].y);
        As2[0][kc+2][la_row] = make_float2(aR[c].z, aR[c].z);
        As2[0][kc+3][la_row] = make_float2(aR[c].w, aR[c].w);
        *(float4*)&Bs[0][lb_row][lb_col + c*4] = bR[c];
    }
    __syncthreads();

    for (int t = 0; t < ntiles; t++) {
        int cur = t & 1, nxt = cur ^ 1;
        bool more = (t + 1 < ntiles);
        if (more) {
            int k0 = (t + 1) * BK;
            #pragma unroll
            for (int c = 0; c < 2; c++) {
                aR[c] = *(const float4*)(A + (long)(m0+la_row)*K + k0 + la_cb + c*4);
                bR[c] = *(const float4*)(B + (long)(k0+lb_row)*N + n0 + lb_col + c*4);
            }
        }
        #pragma unroll
        for (int kk = 0; kk < BK; kk++) {
            unsigned long long rm2[TM], rb2[TN/2];
            #pragma unroll
            for (int i = 0; i < TM; i += 2) {
                ulonglong2 v = *(const ulonglong2*)&As2[cur][kk][ty*TM + i];
                rm2[i] = v.x; rm2[i+1] = v.y;
            }
            #pragma unroll
            for (int j = 0; j < TN/2; j += 2) {
                ulonglong2 v = *(const ulonglong2*)&Bs[cur][kk][tx*TN + 2*j];
                rb2[j] = v.x; rb2[j+1] = v.y;
            }
            #pragma unroll
            for (int i = 0; i < TM; i++)
                #pragma unroll
                for (int j = 0; j < TN/2; j++)
                    FMA2(acc2[i][j], rm2[i], rb2[j]);
        }
        if (more) {
            #pragma unroll
            for (int c = 0; c < 2; c++) {
                int kc = la_cb + c*4;
                As2[nxt][kc+0][la_row] = make_float2(aR[c].x, aR[c].x);
                As2[nxt][kc+1][la_row] = make_float2(aR[c].y, aR[c].y);
                As2[nxt][kc+2][la_row] = make_float2(aR[c].z, aR[c].z);
                As2[nxt][kc+3][la_row] = make_float2(aR[c].w, aR[c].w);
                *(float4*)&Bs[nxt][lb_row][lb_col + c*4] = bR[c];
            }
        }
        __syncthreads();
    }

    #pragma unroll
    for (int i = 0; i < TM; i++) {
        int row = m0 + ty*TM + i;
        #pragma unroll
        for (int q = 0; q < 2; q++) {
            int col = n0 + tx*TN + q*4;
            float v0 = __uint_as_float((unsigned)(acc2[i][2*q]   & 0xffffffffull));
            float v1 = __uint_as_float((unsigned)(acc2[i][2*q]   >> 32));
            float v2 = __uint_as_float((unsigned)(acc2[i][2*q+1] & 0xffffffffull));
            float v3 = __uint_as_float((unsigned)(acc2[i][2*q+1] >> 32));
            float4 bv = *(const float4*)(bias + col);
            v0 = fmaxf(v0 + bv.x, 0.f); v1 = fmaxf(v1 + bv.y, 0.f);
            v2 = fmaxf(v2 + bv.z, 0.f); v3 = fmaxf(v3 + bv.w, 0.f);
            *(float4*)(C + (long)row*N + col) = make_float4(v0, v1, v2, v3);
        }
    }
}

// ---------------- split-K GEMM computing g_a and g_b together ----------------
#define KS 8
#define KSLC 292   // multiple of 4 (float4 alignment); 8*292 >= 2324

__global__ __launch_bounds__(256, 2)
void gemm_ab_kernel(const float* __restrict__ pw1)
{
    __shared__ __align__(16) float2 As2[BK][BM];
    __shared__ __align__(16) float  Bs[BK][BN];

    int tid = threadIdx.x;
    int n0 = blockIdx.x * BN;
    int kstart = blockIdx.y * KSLC;
    int kend = min(kstart + KSLC, SD);

    const float* Bsel = (n0 < HH) ? pw1 + n0 : pw1 + (long)SD*HH + (n0 - HH);
    float* Cout = (n0 < HH) ? g_a + n0 : g_b + (n0 - HH);

    int la_row = tid >> 1, la_cb = (tid & 1) * 8;
    int lb_row = tid >> 4, lb_col = (tid & 15) * 8;

    unsigned long long acc2[TM][TN/2];
    #pragma unroll
    for (int i = 0; i < TM; i++)
        #pragma unroll
        for (int j = 0; j < TN/2; j++) acc2[i][j] = 0ull;

    int tx = tid & 15, ty = tid >> 4;

    for (int k0 = kstart; k0 < kend; k0 += BK) {
        #pragma unroll
        for (int c = 0; c < 2; c++) {
            int k = k0 + la_cb + c*4;
            float4 v = make_float4(0.f,0.f,0.f,0.f);
            if (k < kend) v = *(const float4*)(g_spans + (long)la_row*SD + k);
            int kc = la_cb + c*4;
            As2[kc+0][la_row] = make_float2(v.x, v.x);
            As2[kc+1][la_row] = make_float2(v.y, v.y);
            As2[kc+2][la_row] = make_float2(v.z, v.z);
            As2[kc+3][la_row] = make_float2(v.w, v.w);
            int kb = k0 + lb_row;
            float4 w = make_float4(0.f,0.f,0.f,0.f);
            if (kb < kend) w = *(const float4*)(Bsel + (long)kb*HH + lb_col + c*4);
            *(float4*)&Bs[lb_row][lb_col + c*4] = w;
        }
        __syncthreads();
        #pragma unroll
        for (int kk = 0; kk < BK; kk++) {
            unsigned long long rm2[TM], rb2[TN/2];
            #pragma unroll
            for (int i = 0; i < TM; i += 2) {
                ulonglong2 v = *(const ulonglong2*)&As2[kk][ty*TM + i];
                rm2[i] = v.x; rm2[i+1] = v.y;
            }
            #pragma unroll
            for (int j = 0; j < TN/2; j += 2) {
                ulonglong2 v = *(const ulonglong2*)&Bs[kk][tx*TN + 2*j];
                rb2[j] = v.x; rb2[j+1] = v.y;
            }
            #pragma unroll
            for (int i = 0; i < TM; i++)
                #pragma unroll
                for (int j = 0; j < TN/2; j++)
                    FMA2(acc2[i][j], rm2[i], rb2[j]);
        }
        __syncthreads();
    }

    #pragma unroll
    for (int i = 0; i < TM; i++) {
        int row = ty*TM + i;
        #pragma unroll
        for (int j = 0; j < TN/2; j++) {
            int col = tx*TN + 2*j;
            float v0 = __uint_as_float((unsigned)(acc2[i][j] & 0xffffffffull));
            float v1 = __uint_as_float((unsigned)(acc2[i][j] >> 32));
            atomicAdd(Cout + (long)row*HH + col,     v0);
            atomicAdd(Cout + (long)row*HH + col + 1, v1);
        }
    }
}

// ---------------- matvec for span scores ----------------
__global__ void matvec_scores(const float* __restrict__ w, const float* __restrict__ bias)
{
    int warp = (blockIdx.x*blockDim.x + threadIdx.x) >> 5;
    int lane = threadIdx.x & 31;
    if (warp >= 1280) return;
    const float4* a4 = (const float4*)(g_hspan + (long)warp*1024);
    const float4* w4 = (const float4*)w;
    float s = 0.f;
    #pragma unroll 4
    for (int c = lane; c < 256; c += 32) {
        float4 x = a4[c], y = w4[c];
        s += x.x*y.x + x.y*y.y + x.z*y.z + x.w*y.w;
    }
    #pragma unroll
    for (int o = 16; o > 0; o >>= 1) s += __shfl_xor_sync(0xffffffffu, s, o);
    if (lane == 0) g_scores[warp] = s + bias[0];
}

// ---------------- span softmax + assemble spans ----------------
__global__ void assemble_kernel(const float* __restrict__ se, const float* __restrict__ cont,
                                const int* __restrict__ width, const float* __restrict__ wemb)
{
    int b = blockIdx.x;
    int tid = threadIdx.x;
    __shared__ float attn[WW];
    int w = width[b];
    if (tid == 0) {
        float sc[WW]; float mx = -INFINITY;
        for (int t = 0; t < WW; t++) {
            sc[t] = (t < w) ? g_scores[b*WW + t] : NEGV;
            mx = fmaxf(mx, sc[t]);
        }
        float sum = 0.f;
        for (int t = 0; t < WW; t++) { sc[t] = expf(sc[t] - mx); sum += sc[t]; }
        for (int t = 0; t < WW; t++) attn[t] = sc[t]/sum;
    }
    __syncthreads();
    float* row = g_spans + (long)b*SD;
    for (int k = tid; k < 2*BH; k += 256) row[k] = se[(long)b*2*BH + k];
    for (int d = tid; d < BH; d += 256) {
        float acc = 0.f;
        #pragma unroll
        for (int t = 0; t < WW; t++) acc += attn[t]*cont[((long)b*WW + t)*BH + d];
        row[2*BH + d] = acc;
    }
    if (tid < ED) row[2*BH + BH + tid] = wemb[min(w,4)*ED + tid];
}

// ---------------- grounding: att[s,v,i,j] = doc[s,i,:]·img[v,j,:] ----------------
__global__ void att_kernel(const float* __restrict__ doc, const float* __restrict__ img)
{
    int b = blockIdx.x, s = b >> 3, v = b & 7;
    for (int idx = threadIdx.x; idx < FF*RR; idx += blockDim.x) {
        int i = idx / RR, j = idx % RR;
        const float4* dr = (const float4*)(doc + (long)(s*FF + i)*DD);
        const float4* ir = (const float4*)(img + (long)(v*RR + j)*DD);
        float acc = 0.f;
        #pragma unroll 8
        for (int c = 0; c < DD/4; c++) {
            float4 x = dr[c], y = ir[c];
            acc += x.x*y.x + x.y*y.y + x.z*y.z + x.w*y.w;
        }
        g_att[((long)b*FF + i)*RR + j] = acc;
    }
}

// ---------------- grounding reduce -> S_g ----------------
__global__ void ground_reduce(const float* __restrict__ tm, const float* __restrict__ im)
{
    __shared__ float sh[FF][RR+1];
    __shared__ float stm[FF], sim[RR];
    __shared__ float red[FF];
    int b = blockIdx.x, s = b >> 3, v = b & 7;
    int tid = threadIdx.x; // 64
    if (tid < FF) stm[tid] = tm[s*FF + tid];
    if (tid < RR) sim[tid] = im[v*RR + tid];
    __syncthreads();
    for (int idx = tid; idx < FF*RR; idx += 64) {
        int i = idx / RR, j = idx % RR;
        float a = g_att[((long)b*FF + i)*RR + j];
        float m = stm[i]*sim[j];
        a *= m;
        if (a == 0.f) a = NEGV;
        sh[i][j] = a;
    }
    __syncthreads();
    float part = 0.f;
    {
        int i = tid;
        float mx = -INFINITY;
        for (int j = 0; j < RR; j++) mx = fmaxf(mx, sh[i][j]*sim[j]);
        float ssum = 0.f;
        for (int j = 0; j < RR; j++) ssum += expf(sh[i][j]*sim[j] - mx);
        for (int j = 0; j < RR; j++) {
            float aw = expf(sh[i][j]*sim[j] - mx)/ssum * stm[i]*sim[j];
            part += aw * sh[i][j];
        }
    }
    if (tid < RR) {
        int j = tid;
        float mx = -INFINITY;
        for (int i = 0; i < FF; i++) mx = fmaxf(mx, sh[i][j]);
        float ssum = 0.f;
        for (int i = 0; i < FF; i++) ssum += expf(sh[i][j] - mx);
        for (int i = 0; i < FF; i++) {
            float aw = expf(sh[i][j] - mx)/ssum * stm[i]*sim[j];
            part += aw * sh[i][j];
        }
    }
    red[tid] = part;
    __syncthreads();
    for (int o = 32; o > 0; o >>= 1) {
        if (tid < o) red[tid] += red[tid+o];
        __syncthreads();
    }
    if (tid == 0) g_Sg[b] = red[0];
}

// ---------------- adaptive S_c ----------------
__global__ void sc_kernel(const float* __restrict__ m1)
{
    int b = blockIdx.x, s = b >> 3, v = b & 7;
    const float* T = g_ts + (long)b*MS*MS;
    int lane = threadIdx.x;
    float cs = 0.f, cv = 0.f;
    for (int k = 0; k < MS; k++) { cs += m1[s*MS+k]; cv += m1[v*MS+k]; }
    float max1 = -INFINITY, max2 = -INFINITY;
    if (lane < MS) {
        float rm = 0.f;
        for (int j = 0; j < MS; j++) rm += T[lane*MS+j]*m1[v*MS+j];
        rm /= cv;
        if (m1[s*MS+lane] > 0.f) max1 = rm;
        float cm = 0.f;
        for (int i = 0; i < MS; i++) cm += T[i*MS+lane]*m1[s*MS+i];
        cm /= cs;
        if (m1[v*MS+lane] > 0.f) max2 = cm;
    }
    for (int o = 16; o > 0; o >>= 1) {
        max1 = fmaxf(max1, __shfl_xor_sync(0xffffffffu, max1, o));
        max2 = fmaxf(max2, __shfl_xor_sync(0xffffffffu, max2, o));
    }
    if (lane == 0) g_Sc[b] = 0.5f*(max1 + max2);
}

// ---------------- final loss ----------------
__global__ void loss_kernel(float* __restrict__ out)
{
    if (threadIdx.x != 0) return;
    float mg[8][8], mgT[8][8], mc[8][8];
    for (int s = 0; s < 8; s++) {
        float mx = -INFINITY;
        for (int v = 0; v < 8; v++) mx = fmaxf(mx, g_Sg[s*8+v]);
        float sum = 0.f;
        for (int v = 0; v < 8; v++) { mg[s][v] = expf(g_Sg[s*8+v]-mx); sum += mg[s][v]; }
        for (int v = 0; v < 8; v++) mg[s][v] /= sum;
    }
    for (int v = 0; v < 8; v++) {
        float mx = -INFINITY;
        for (int s = 0; s < 8; s++) mx = fmaxf(mx, g_Sg[s*8+v]);
        float sum = 0.f;
        for (int s = 0; s < 8; s++) { mgT[v][s] = expf(g_Sg[s*8+v]-mx); sum += mgT[v][s]; }
        for (int s = 0; s < 8; s++) mgT[v][s] /= sum;
    }
    for (int s = 0; s < 8; s++) {
        float mx = -INFINITY;
        for (int v = 0; v < 8; v++) mx = fmaxf(mx, g_Sc[s*8+v]);
        float sum = 0.f;
        for (int v = 0; v < 8; v++) { mc[s][v] = expf(g_Sc[s*8+v]-mx); sum += mc[s][v]; }
        for (int v = 0; v < 8; v++) mc[s][v] /= sum;
    }
    float loss = 0.f;
    for (int s = 0; s < 8; s++) {
        float t = 0.f;
        for (int v = 0; v < 8; v++) t += mg[s][v]*mc[s][v];
        loss += logf(t);
    }
    for (int v = 0; v < 8; v++) {
        float t = 0.f;
        for (int s = 0; s < 8; s++) t += mgT[v][s]*mc[v][s];
        loss += logf(t);
    }
    out[0] = -loss/(float)ND;
}

// ---------------- host ----------------
extern "C" void kernel_launch(void* const* d_in, const int* in_sizes, int n_in,
                              void* d_out, int out_size)
{
    const float* doc  = (const float*)d_in[0];
    const float* img  = (const float*)d_in[1];
    const float* tm   = (const float*)d_in[2];
    const float* im   = (const float*)d_in[3];
    const float* se   = (const float*)d_in[4];
    const float* cont = (const float*)d_in[5];
    const int*   width= (const int*)  d_in[6];
    const float* m1   = (const float*)d_in[7];
    const float* aw1  = (const float*)d_in[8];
    const float* ab1  = (const float*)d_in[9];
    const float* aw2  = (const float*)d_in[10];
    const float* ab2  = (const float*)d_in[11];
    const float* wemb = (const float*)d_in[12];
    const float* pw1  = (const float*)d_in[13];
    const float* pb1  = (const float*)d_in[14];
    const float* pw2  = (const float*)d_in[15];
    const float* pb2  = (const float*)d_in[16];
    const float* pw3  = (const float*)d_in[17];
    const float* pb3  = (const float*)d_in[18];

    cudaFuncSetAttribute(h1_mma_kernel, cudaFuncAttributeMaxDynamicSharedMemorySize, DSMEM_MMA);
    cudaFuncSetAttribute(h2_mma_kernel, cudaFuncAttributeMaxDynamicSharedMemorySize, DSMEM_MMA);

    // (1) split W1c/W2 into bf16 hi/lo; g_ts = pb3
    int prep_total = PREP_G1 + PREP_G2 + NPAIR;
    prep_kernel<<<(prep_total + 255)/256, 256>>>(pw1, pw2, pb3);
    // (2) span attention hidden (also zeroes g_a/g_b)
    span_gemm_kernel<<<dim3(HH/BN, 1280/BM), 256>>>(cont, aw1, ab1);
    // (3) span scores
    matvec_scores<<<(1280*32+255)/256, 256>>>(aw2, ab2);
    // (4) assemble spans
    assemble_kernel<<<NSPAN, 256>>>(se, cont, width, wemb);
    // (5) a,b = spans @ w1 halves (split-K)
    gemm_ab_kernel<<<dim3(2048/BN, KS), 256>>>(pw1);
    // (6) h1 = relu(prod @ W1c + a + b + b1)  [HMMA bf16x3, double-buffered + cp.async]
    h1_mma_kernel<<<dim3(8, 128), 256, DSMEM_MMA>>>(pb1);
    // (7) ts += relu(h1 @ W2 + b2) @ w3  [HMMA bf16x3, fused, all-cp.async]
    h2_mma_kernel<<<dim3(8, 128), 256, DSMEM_MMA>>>(pb2, pw3);

    // grounding (independent)
    att_kernel<<<64, 256>>>(doc, img);
    ground_reduce<<<64, 64>>>(tm, im);

    // adaptive S_c + final loss
    sc_kernel<<<64, 32>>>(m1);
    loss_kernel<<<1, 32>>>((float*)d_out);
}

// round 11
// speedup vs baseline: 1.3930x; 1.3145x over previous
#include <cuda_runtime.h>
#include <cuda_bf16.h>
#include <cuda_fp16.h>
#include <math.h>
#include <stdint.h>

// ---------------- problem constants ----------------
#define ND   8
#define FF   64
#define RR   36
#define DD   1024
#define MS   16
#define WW   10
#define BH   768
#define HH   1024
#define ED   20
#define SD   2324
#define NSPAN (ND*MS)          // 128
#define NPAIR (NSPAN*NSPAN)    // 16384
#define NEGV (-1e10f)

#define KPAD1 2368             // 74 * 32
#define KPAD2 1024             // 32 * 32
#define NT1   (KPAD1/32)
#define NT2   (KPAD2/32)

// ---------------- scratch ----------------
__device__ __align__(16) float g_hspan[1280*HH];
__device__ __align__(16) float g_scores[1280];
__device__ __align__(16) float g_spans[NSPAN*SD + 64];   // +pad for over-read
__device__ __align__(16) float g_a[NSPAN*HH];
__device__ __align__(16) float g_b[NSPAN*HH];
__device__ __align__(16) __half g_B1[HH*KPAD1];          // [n][k] = fp16(pw1[2SD+k][n])
__device__ __align__(16) __half g_W2[HH*KPAD2];          // [n][k] = fp16(pw2[k][n])
__device__ __align__(16) __half g_h1hi[(long)NPAIR*HH];
__device__ __align__(16) __half g_h1lo[(long)NPAIR*HH];
__device__ __align__(16) float g_ts[NPAIR];
__device__ __align__(16) float g_att[64*FF*RR];
__device__ float g_Sg[64];
__device__ float g_Sc[64];

#define FMA2(d,a,b) asm("fma.rn.f32x2 %0, %1, %2, %0;" : "+l"(d) : "l"(a), "l"(b))

// ---------------- warp MMA helpers (generic sm_80+ path) ----------------
__device__ __forceinline__ unsigned smem_u32(const void* p) {
    unsigned a;
    asm("{ .reg .u64 t; cvta.to.shared.u64 t, %1; cvt.u32.u64 %0, t; }" : "=r"(a) : "l"(p));
    return a;
}
__device__ __forceinline__ void ldsm_x4(unsigned& r0, unsigned& r1, unsigned& r2, unsigned& r3,
                                        unsigned addr) {
    asm volatile("ldmatrix.sync.aligned.m8n8.x4.shared.b16 {%0,%1,%2,%3}, [%4];"
                 : "=r"(r0), "=r"(r1), "=r"(r2), "=r"(r3) : "r"(addr));
}
__device__ __forceinline__ void mma_f16(float (&c)[4], const unsigned (&a)[4],
                                        unsigned b0, unsigned b1) {
    asm volatile(
        "mma.sync.aligned.m16n8k16.row.col.f32.f16.f16.f32 "
        "{%0,%1,%2,%3}, {%4,%5,%6,%7}, {%8,%9}, {%0,%1,%2,%3};"
        : "+f"(c[0]), "+f"(c[1]), "+f"(c[2]), "+f"(c[3])
        : "r"(a[0]), "r"(a[1]), "r"(a[2]), "r"(a[3]), "r"(b0), "r"(b1));
}
__device__ __forceinline__ void f16_split(float v, unsigned short& h, unsigned short& l) {
    __half hb = __float2half_rn(v);
    __half lb = __float2half_rn(v - __half2float(hb));
    h = __half_as_ushort(hb);
    l = __half_as_ushort(lb);
}
#define CP_ASYNC16(saddr, gptr) \
    asm volatile("cp.async.cg.shared.global [%0], [%1], 16;" :: "r"(saddr), "l"(gptr) : "memory")
#define CP_COMMIT() asm volatile("cp.async.commit_group;" ::: "memory")
#define CP_WAIT0()  asm volatile("cp.async.wait_group 0;" ::: "memory")

// smem tile: [128 rows][40 fp16]  (80B stride -> conflict-free ldmatrix; 80 % 16 == 0)
#define TROW 40
#define MATB 10240                  // bytes per matrix per stage (128*40*2)
#define MATE (128*TROW)             // elements per matrix per stage
// stages: {Ahi0,Ahi1,Alo0,Alo1,B0,B1}
#define DSMEM_MMA (6*MATB)          // 61440

// ---------------- prep: W1c/W2 -> fp16 [n][k]; init g_ts=pb3 ----------------
#define PREP_G1 (HH*(KPAD1/8))
#define PREP_G2 (HH*(KPAD2/8))
__global__ void prep_kernel(const float* __restrict__ pw1, const float* __restrict__ pw2,
                            const float* __restrict__ pb3)
{
    int gid = blockIdx.x*256 + threadIdx.x;
    if (gid < PREP_G1) {
        int n = gid % HH, kg = gid / HH;
        union { uint4 q; unsigned short us[8]; } H;
        #pragma unroll
        for (int e = 0; e < 8; e++) {
            int k = kg*8 + e;
            float v = (k < SD) ? pw1[((long)(2*SD + k))*HH + n] : 0.f;
            H.us[e] = __half_as_ushort(__float2half_rn(v));
        }
        *(uint4*)(g_B1 + (long)n*KPAD1 + kg*8) = H.q;
    } else if (gid < PREP_G1 + PREP_G2) {
        int j = gid - PREP_G1;
        int n = j % HH, kg = j / HH;
        union { uint4 q; unsigned short us[8]; } H;
        #pragma unroll
        for (int e = 0; e < 8; e++) {
            int k = kg*8 + e;
            H.us[e] = __half_as_ushort(__float2half_rn(pw2[(long)k*HH + n]));
        }
        *(uint4*)(g_W2 + (long)n*KPAD2 + kg*8) = H.q;
    } else {
        int i = gid - PREP_G1 - PREP_G2;
        if (i < NPAIR) g_ts[i] = pb3[0];
    }
}

// ---------------- h1 HMMA kernel (fp16 2-term, double-buffered, cp.async B) ----------------
__global__ void __launch_bounds__(256)
h1_mma_kernel(const float* __restrict__ pb1)
{
    extern __shared__ __align__(16) char dsm8[];
    __half* dsm = (__half*)dsm8;
    unsigned sb = smem_u32(dsm8);

    int tid = threadIdx.x, lane = tid & 31, wid = tid >> 5;
    int wy = wid & 3, wx = wid >> 2;
    int m0 = blockIdx.y*128, n0 = blockIdx.x*128;

    int lrow = tid >> 1, lks = (tid & 1)*16;
    int lgrow = m0 + lrow;
    int lii = (lgrow >> 4) & 15, ljj = lgrow & 15, lsv = lgrow >> 8;
    const float* pa  = g_spans + (long)((lsv >> 3)*MS + lii)*SD;
    const float* pbs = g_spans + (long)((lsv & 7)*MS + ljj)*SD;
    const __half* bsrc = g_B1 + (long)(n0 + lrow)*KPAD1;

    unsigned srow = (unsigned)(lrow*TROW + lks)*2;   // byte offset within a matrix

    float c[2][8][4];
    #pragma unroll
    for (int i = 0; i < 2; i++)
        #pragma unroll
        for (int j = 0; j < 8; j++)
            #pragma unroll
            for (int e = 0; e < 4; e++) c[i][j][e] = 0.f;

    // ---- prologue: fill stage 0 ----
    {
        CP_ASYNC16(sb + 4*MATB + srow,      bsrc + lks);
        CP_ASYNC16(sb + 4*MATB + srow + 16, bsrc + lks + 8);
        CP_COMMIT();
        float p[16];
        #pragma unroll
        for (int q = 0; q < 4; q++) {
            float4 x = *(const float4*)(pa  + lks + q*4);
            float4 y = *(const float4*)(pbs + lks + q*4);
            p[q*4+0] = x.x*y.x; p[q*4+1] = x.y*y.y;
            p[q*4+2] = x.z*y.z; p[q*4+3] = x.w*y.w;
        }
        union { uint4 q[2]; unsigned short us[16]; } H, L;
        #pragma unroll
        for (int e = 0; e < 16; e++) f16_split(p[e], H.us[e], L.us[e]);
        *(uint4*)&dsm[0*MATE + lrow*TROW + lks]     = H.q[0];
        *(uint4*)&dsm[0*MATE + lrow*TROW + lks + 8] = H.q[1];
        *(uint4*)&dsm[2*MATE + lrow*TROW + lks]     = L.q[0];
        *(uint4*)&dsm[2*MATE + lrow*TROW + lks + 8] = L.q[1];
        CP_WAIT0();
    }
    __syncthreads();

    for (int t = 0; t < NT1; t++) {
        int cur = t & 1, nxt = cur ^ 1;
        bool more = (t + 1 < NT1);

        if (more) {
            int kk = (t+1)*32 + lks;
            CP_ASYNC16(sb + (4+nxt)*MATB + srow,      bsrc + kk);
            CP_ASYNC16(sb + (4+nxt)*MATB + srow + 16, bsrc + kk + 8);
            CP_COMMIT();
        }

        unsigned sbAhi = sb + cur*MATB, sbAlo = sb + (2+cur)*MATB, sbB = sb + (4+cur)*MATB;
        #pragma unroll
        for (int kt = 0; kt < 2; kt++) {
            unsigned ah[2][4], al[2][4], b[4][4];
            int arow = lane & 15, acol = (lane >> 4)*8;
            #pragma unroll
            for (int mt = 0; mt < 2; mt++) {
                unsigned off = (unsigned)(((wy*32 + mt*16 + arow)*TROW + kt*16 + acol)*2);
                ldsm_x4(ah[mt][0], ah[mt][1], ah[mt][2], ah[mt][3], sbAhi + off);
                ldsm_x4(al[mt][0], al[mt][1], al[mt][2], al[mt][3], sbAlo + off);
            }
            int nrow = (lane & 7) + ((lane >> 4) << 3), kc = lane & 8;
            #pragma unroll
            for (int np = 0; np < 4; np++) {
                unsigned off = (unsigned)(((wx*64 + np*16 + nrow)*TROW + kt*16 + kc)*2);
                ldsm_x4(b[np][0], b[np][1], b[np][2], b[np][3], sbB + off);
            }
            #pragma unroll
            for (int mt = 0; mt < 2; mt++)
                #pragma unroll
                for (int nt = 0; nt < 8; nt++) {
                    int np = nt >> 1, h = (nt & 1)*2;
                    mma_f16(c[mt][nt], ah[mt], b[np][h], b[np][h+1]);
                    mma_f16(c[mt][nt], al[mt], b[np][h], b[np][h+1]);
                }
        }

        // A tile for t+1 (compute+split) into next stage; overlaps other warps' MMAs
        if (more) {
            int kk = (t+1)*32 + lks;
            float p[16];
            #pragma unroll
            for (int q = 0; q < 4; q++) {
                float4 x = *(const float4*)(pa  + kk + q*4);
                float4 y = *(const float4*)(pbs + kk + q*4);
                p[q*4+0] = x.x*y.x; p[q*4+1] = x.y*y.y;
                p[q*4+2] = x.z*y.z; p[q*4+3] = x.w*y.w;
            }
            if (kk + 16 > SD) {
                #pragma unroll
                for (int e = 0; e < 16; e++) if (kk + e >= SD) p[e] = 0.f;
            }
            union { uint4 q[2]; unsigned short us[16]; } H, L;
            #pragma unroll
            for (int e = 0; e < 16; e++) f16_split(p[e], H.us[e], L.us[e]);
            *(uint4*)&dsm[(0+nxt)*MATE + lrow*TROW + lks]     = H.q[0];
            *(uint4*)&dsm[(0+nxt)*MATE + lrow*TROW + lks + 8] = H.q[1];
            *(uint4*)&dsm[(2+nxt)*MATE + lrow*TROW + lks]     = L.q[0];
            *(uint4*)&dsm[(2+nxt)*MATE + lrow*TROW + lks + 8] = L.q[1];
        }
        CP_WAIT0();
        __syncthreads();
    }

    // epilogue: +bias +a +b, relu, split, store fp16 hi/lo
    int g = lane >> 2, t4 = lane & 3;
    #pragma unroll
    for (int mt = 0; mt < 2; mt++) {
        #pragma unroll
        for (int rr = 0; rr < 2; rr++) {
            int grow = m0 + wy*32 + mt*16 + rr*8 + g;
            int ii = (grow >> 4) & 15, jj = grow & 15, sv = grow >> 8;
            int rA = (sv >> 3)*MS + ii, rB = (sv & 7)*MS + jj;
            #pragma unroll
            for (int nt = 0; nt < 8; nt++) {
                int col = n0 + wx*64 + nt*8 + 2*t4;
                float v0 = c[mt][nt][rr*2+0] + pb1[col]
                         + g_a[rA*HH + col] + g_b[rB*HH + col];
                float v1 = c[mt][nt][rr*2+1] + pb1[col+1]
                         + g_a[rA*HH + col+1] + g_b[rB*HH + col+1];
                v0 = fmaxf(v0, 0.f); v1 = fmaxf(v1, 0.f);
                unsigned short h0, l0, h1, l1;
                f16_split(v0, h0, l0); f16_split(v1, h1, l1);
                *(unsigned*)&g_h1hi[(long)grow*HH + col] = (unsigned)h0 | ((unsigned)h1 << 16);
                *(unsigned*)&g_h1lo[(long)grow*HH + col] = (unsigned)l0 | ((unsigned)l1 << 16);
            }
        }
    }
}

// ---------------- h2 HMMA kernel (fp16 2-term, all-cp.async; fused ts matvec) ----------------
__global__ void __launch_bounds__(256)
h2_mma_kernel(const float* __restrict__ pb2, const float* __restrict__ pw3)
{
    extern __shared__ __align__(16) char dsm8[];
    unsigned sb = smem_u32(dsm8);
    __shared__ float w3s[128], pb2s[128];

    int tid = threadIdx.x, lane = tid & 31, wid = tid >> 5;
    int wy = wid & 3, wx = wid >> 2;
    int m0 = blockIdx.y*128, n0 = blockIdx.x*128;

    if (tid < 128) { w3s[tid] = pw3[n0 + tid]; pb2s[tid] = pb2[n0 + tid]; }

    int lrow = tid >> 1, lks = (tid & 1)*16;
    const __half* ahsrc = g_h1hi + (long)(m0 + lrow)*HH;
    const __half* alsrc = g_h1lo + (long)(m0 + lrow)*HH;
    const __half* bsrc  = g_W2 + (long)(n0 + lrow)*KPAD2;
    unsigned srow = (unsigned)(lrow*TROW + lks)*2;

    float c[2][8][4];
    #pragma unroll
    for (int i = 0; i < 2; i++)
        #pragma unroll
        for (int j = 0; j < 8; j++)
            #pragma unroll
            for (int e = 0; e < 4; e++) c[i][j][e] = 0.f;

    // prologue: stage 0
    {
        CP_ASYNC16(sb + 0*MATB + srow,      ahsrc + lks);
        CP_ASYNC16(sb + 0*MATB + srow + 16, ahsrc + lks + 8);
        CP_ASYNC16(sb + 2*MATB + srow,      alsrc + lks);
        CP_ASYNC16(sb + 2*MATB + srow + 16, alsrc + lks + 8);
        CP_ASYNC16(sb + 4*MATB + srow,      bsrc + lks);
        CP_ASYNC16(sb + 4*MATB + srow + 16, bsrc + lks + 8);
        CP_COMMIT(); CP_WAIT0();
    }
    __syncthreads();

    for (int t = 0; t < NT2; t++) {
        int cur = t & 1, nxt = cur ^ 1;
        bool more = (t + 1 < NT2);

        if (more) {
            int kk = (t+1)*32 + lks;
            CP_ASYNC16(sb + (0+nxt)*MATB + srow,      ahsrc + kk);
            CP_ASYNC16(sb + (0+nxt)*MATB + srow + 16, ahsrc + kk + 8);
            CP_ASYNC16(sb + (2+nxt)*MATB + srow,      alsrc + kk);
            CP_ASYNC16(sb + (2+nxt)*MATB + srow + 16, alsrc + kk + 8);
            CP_ASYNC16(sb + (4+nxt)*MATB + srow,      bsrc + kk);
            CP_ASYNC16(sb + (4+nxt)*MATB + srow + 16, bsrc + kk + 8);
            CP_COMMIT();
        }

        unsigned sbAhi = sb + cur*MATB, sbAlo = sb + (2+cur)*MATB, sbB = sb + (4+cur)*MATB;
        #pragma unroll
        for (int kt = 0; kt < 2; kt++) {
            unsigned ah[2][4], al[2][4], b[4][4];
            int arow = lane & 15, acol = (lane >> 4)*8;
            #pragma unroll
            for (int mt = 0; mt < 2; mt++) {
                unsigned off = (unsigned)(((wy*32 + mt*16 + arow)*TROW + kt*16 + acol)*2);
                ldsm_x4(ah[mt][0], ah[mt][1], ah[mt][2], ah[mt][3], sbAhi + off);
                ldsm_x4(al[mt][0], al[mt][1], al[mt][2], al[mt][3], sbAlo + off);
            }
            int nrow = (lane & 7) + ((lane >> 4) << 3), kc = lane & 8;
            #pragma unroll
            for (int np = 0; np < 4; np++) {
                unsigned off = (unsigned)(((wx*64 + np*16 + nrow)*TROW + kt*16 + kc)*2);
                ldsm_x4(b[np][0], b[np][1], b[np][2], b[np][3], sbB + off);
            }
            #pragma unroll
            for (int mt = 0; mt < 2; mt++)
                #pragma unroll
                for (int nt = 0; nt < 8; nt++) {
                    int np = nt >> 1, h = (nt & 1)*2;
                    mma_f16(c[mt][nt], ah[mt], b[np][h], b[np][h+1]);
                    mma_f16(c[mt][nt], al[mt], b[np][h], b[np][h+1]);
                }
        }
        CP_WAIT0();
        __syncthreads();
    }

    // epilogue: relu(+b2) dot w3; quad reduce; atomicAdd into g_ts
    int g = lane >> 2, t4 = lane & 3;
    #pragma unroll
    for (int mt = 0; mt < 2; mt++) {
        float p0 = 0.f, p1 = 0.f;
        #pragma unroll
        for (int nt = 0; nt < 8; nt++) {
            int lc = wx*64 + nt*8 + 2*t4;
            p0 += fmaxf(c[mt][nt][0] + pb2s[lc],   0.f)*w3s[lc]
                + fmaxf(c[mt][nt][1] + pb2s[lc+1], 0.f)*w3s[lc+1];
            p1 += fmaxf(c[mt][nt][2] + pb2s[lc],   0.f)*w3s[lc]
                + fmaxf(c[mt][nt][3] + pb2s[lc+1], 0.f)*w3s[lc+1];
        }
        p0 += __shfl_xor_sync(0xffffffffu, p0, 1);
        p0 += __shfl_xor_sync(0xffffffffu, p0, 2);
        p1 += __shfl_xor_sync(0xffffffffu, p1, 1);
        p1 += __shfl_xor_sync(0xffffffffu, p1, 2);
        if (t4 == 0) {
            atomicAdd(&g_ts[m0 + wy*32 + mt*16 + g],     p0);
            atomicAdd(&g_ts[m0 + wy*32 + mt*16 + 8 + g], p1);
        }
    }
}

// ---------------- SIMT span GEMM (1280x1024x768, bias+relu; also zeroes g_a/g_b) ----------------
#define BM 128
#define BN 128
#define BK 16
#define TM 8
#define TN 8

__global__ __launch_bounds__(256, 2)
void span_gemm_kernel(const float* __restrict__ A, const float* __restrict__ B,
                      const float* __restrict__ bias)
{
    const int N = HH, K = BH;
    float* C = g_hspan;

    __shared__ __align__(16) float2 As2[2][BK][BM];
    __shared__ __align__(16) float  Bs[2][BK][BN];

    int tid = threadIdx.x;
    {   // zero g_a/g_b for split-K atomics
        float4 z = make_float4(0.f,0.f,0.f,0.f);
        int gt = (blockIdx.y*gridDim.x + blockIdx.x)*256 + tid;
        int nb = gridDim.x*gridDim.y*256;
        for (int i = gt; i < NSPAN*HH/4; i += nb) {
            ((float4*)g_a)[i] = z;
            ((float4*)g_b)[i] = z;
        }
    }
    int m0 = blockIdx.y * BM;
    int n0 = blockIdx.x * BN;

    int la_row = tid >> 1, la_cb = (tid & 1) * 8;
    int lb_row = tid >> 4, lb_col = (tid & 15) * 8;

    unsigned long long acc2[TM][TN/2];
    #pragma unroll
    for (int i = 0; i < TM; i++)
        #pragma unroll
        for (int j = 0; j < TN/2; j++) acc2[i][j] = 0ull;

    int tx = tid & 15, ty = tid >> 4;
    int ntiles = K / BK;

    float4 aR[2], bR[2];
    #pragma unroll
    for (int c = 0; c < 2; c++) {
        aR[c] = *(const float4*)(A + (long)(m0+la_row)*K + la_cb + c*4);
        bR[c] = *(const float4*)(B + (long)lb_row*N + n0 + lb_col + c*4);
    }
    #pragma unroll
    for (int c = 0; c < 2; c++) {
        int kc = la_cb + c*4;
        As2[0][kc+0][la_row] = make_float2(aR[c].x, aR[c].x);
        As2[0][kc+1][la_row] = make_float2(aR[c].y, aR[c].y);
        As2[0][kc+2][la_row] = make_float2(aR[c].z, aR[c].z);
        As2[0][kc+3][la_row] = make_float2(aR[c].w, aR[c].w);
        *(float4*)&Bs[0][lb_row][lb_col + c*4] = bR[c];
    }
    __syncthreads();

    for (int t = 0; t < ntiles; t++) {
        int cur = t & 1, nxt = cur ^ 1;
        bool more = (t + 1 < ntiles);
        if (more) {
            int k0 = (t + 1) * BK;
            #pragma unroll
            for (int c = 0; c < 2; c++) {
                aR[c] = *(const float4*)(A + (long)(m0+la_row)*K + k0 + la_cb + c*4);
                bR[c] = *(const float4*)(B + (long)(k0+lb_row)*N + n0 + lb_col + c*4);
            }
        }
        #pragma unroll
        for (int kk = 0; kk < BK; kk++) {
            unsigned long long rm2[TM], rb2[TN/2];
            #pragma unroll
            for (int i = 0; i < TM; i += 2) {
                ulonglong2 v = *(const ulonglong2*)&As2[cur][kk][ty*TM + i];
                rm2[i] = v.x; rm2[i+1] = v.y;
            }
            #pragma unroll
            for (int j = 0; j < TN/2; j += 2) {
                ulonglong2 v = *(const ulonglong2*)&Bs[cur][kk][tx*TN + 2*j];
                rb2[j] = v.x; rb2[j+1] = v.y;
            }
            #pragma unroll
            for (int i = 0; i < TM; i++)
                #pragma unroll
                for (int j = 0; j < TN/2; j++)
                    FMA2(acc2[i][j], rm2[i], rb2[j]);
        }
        if (more) {
            #pragma unroll
            for (int c = 0; c < 2; c++) {
                int kc = la_cb + c*4;
                As2[nxt][kc+0][la_row] = make_float2(aR[c].x, aR[c].x);
                As2[nxt][kc+1][la_row] = make_float2(aR[c].y, aR[c].y);
                As2[nxt][kc+2][la_row] = make_float2(aR[c].z, aR[c].z);
                As2[nxt][kc+3][la_row] = make_float2(aR[c].w, aR[c].w);
                *(float4*)&Bs[nxt][lb_row][lb_col + c*4] = bR[c];
            }
        }
        __syncthreads();
    }

    #pragma unroll
    for (int i = 0; i < TM; i++) {
        int row = m0 + ty*TM + i;
        #pragma unroll
        for (int q = 0; q < 2; q++) {
            int col = n0 + tx*TN + q*4;
            float v0 = __uint_as_float((unsigned)(acc2[i][2*q]   & 0xffffffffull));
            float v1 = __uint_as_float((unsigned)(acc2[i][2*q]   >> 32));
            float v2 = __uint_as_float((unsigned)(acc2[i][2*q+1] & 0xffffffffull));
            float v3 = __uint_as_float((unsigned)(acc2[i][2*q+1] >> 32));
            float4 bv = *(const float4*)(bias + col);
            v0 = fmaxf(v0 + bv.x, 0.f); v1 = fmaxf(v1 + bv.y, 0.f);
            v2 = fmaxf(v2 + bv.z, 0.f); v3 = fmaxf(v3 + bv.w, 0.f);
            *(float4*)(C + (long)row*N + col) = make_float4(v0, v1, v2, v3);
        }
    }
}

// ---------------- split-K GEMM computing g_a and g_b together ----------------
#define KS 8
#define KSLC 292   // multiple of 4 (float4 alignment); 8*292 >= 2324

__global__ __launch_bounds__(256, 2)
void gemm_ab_kernel(const float* __restrict__ pw1)
{
    __shared__ __align__(16) float2 As2[BK][BM];
    __shared__ __align__(16) float  Bs[BK][BN];

    int tid = threadIdx.x;
    int n0 = blockIdx.x * BN;
    int kstart = blockIdx.y * KSLC;
    int kend = min(kstart + KSLC, SD);

    const float* Bsel = (n0 < HH) ? pw1 + n0 : pw1 + (long)SD*HH + (n0 - HH);
    float* Cout = (n0 < HH) ? g_a + n0 : g_b + (n0 - HH);

    int la_row = tid >> 1, la_cb = (tid & 1) * 8;
    int lb_row = tid >> 4, lb_col = (tid & 15) * 8;

    unsigned long long acc2[TM][TN/2];
    #pragma unroll
    for (int i = 0; i < TM; i++)
        #pragma unroll
        for (int j = 0; j < TN/2; j++) acc2[i][j] = 0ull;

    int tx = tid & 15, ty = tid >> 4;

    for (int k0 = kstart; k0 < kend; k0 += BK) {
        #pragma unroll
        for (int c = 0; c < 2; c++) {
            int k = k0 + la_cb + c*4;
            float4 v = make_float4(0.f,0.f,0.f,0.f);
            if (k < kend) v = *(const float4*)(g_spans + (long)la_row*SD + k);
            int kc = la_cb + c*4;
            As2[kc+0][la_row] = make_float2(v.x, v.x);
            As2[kc+1][la_row] = make_float2(v.y, v.y);
            As2[kc+2][la_row] = make_float2(v.z, v.z);
            As2[kc+3][la_row] = make_float2(v.w, v.w);
            int kb = k0 + lb_row;
            float4 w = make_float4(0.f,0.f,0.f,0.f);
            if (kb < kend) w = *(const float4*)(Bsel + (long)kb*HH + lb_col + c*4);
            *(float4*)&Bs[lb_row][lb_col + c*4] = w;
        }
        __syncthreads();
        #pragma unroll
        for (int kk = 0; kk < BK; kk++) {
            unsigned long long rm2[TM], rb2[TN/2];
            #pragma unroll
            for (int i = 0; i < TM; i += 2) {
                ulonglong2 v = *(const ulonglong2*)&As2[kk][ty*TM + i];
                rm2[i] = v.x; rm2[i+1] = v.y;
            }
            #pragma unroll
            for (int j = 0; j < TN/2; j += 2) {
                ulonglong2 v = *(const ulonglong2*)&Bs[kk][tx*TN + 2*j];
                rb2[j] = v.x; rb2[j+1] = v.y;
            }
            #pragma unroll
            for (int i = 0; i < TM; i++)
                #pragma unroll
                for (int j = 0; j < TN/2; j++)
                    FMA2(acc2[i][j], rm2[i], rb2[j]);
        }
        __syncthreads();
    }

    #pragma unroll
    for (int i = 0; i < TM; i++) {
        int row = ty*TM + i;
        #pragma unroll
        for (int j = 0; j < TN/2; j++) {
            int col = tx*TN + 2*j;
            float v0 = __uint_as_float((unsigned)(acc2[i][j] & 0xffffffffull));
            float v1 = __uint_as_float((unsigned)(acc2[i][j] >> 32));
            atomicAdd(Cout + (long)row*HH + col,     v0);
            atomicAdd(Cout + (long)row*HH + col + 1, v1);
        }
    }
}

// ---------------- matvec for span scores ----------------
__global__ void matvec_scores(const float* __restrict__ w, const float* __restrict__ bias)
{
    int warp = (blockIdx.x*blockDim.x + threadIdx.x) >> 5;
    int lane = threadIdx.x & 31;
    if (warp >= 1280) return;
    const float4* a4 = (const float4*)(g_hspan + (long)warp*1024);
    const float4* w4 = (const float4*)w;
    float s = 0.f;
    #pragma unroll 4
    for (int c = lane; c < 256; c += 32) {
        float4 x = a4[c], y = w4[c];
        s += x.x*y.x + x.y*y.y + x.z*y.z + x.w*y.w;
    }
    #pragma unroll
    for (int o = 16; o > 0; o >>= 1) s += __shfl_xor_sync(0xffffffffu, s, o);
    if (lane == 0) g_scores[warp] = s + bias[0];
}

// ---------------- span softmax + assemble spans ----------------
__global__ void assemble_kernel(const float* __restrict__ se, const float* __restrict__ cont,
                                const int* __restrict__ width, const float* __restrict__ wemb)
{
    int b = blockIdx.x;
    int tid = threadIdx.x;
    __shared__ float attn[WW];
    int w = width[b];
    if (tid == 0) {
        float sc[WW]; float mx = -INFINITY;
        for (int t = 0; t < WW; t++) {
            sc[t] = (t < w) ? g_scores[b*WW + t] : NEGV;
            mx = fmaxf(mx, sc[t]);
        }
        float sum = 0.f;
        for (int t = 0; t < WW; t++) { sc[t] = expf(sc[t] - mx); sum += sc[t]; }
        for (int t = 0; t < WW; t++) attn[t] = sc[t]/sum;
    }
    __syncthreads();
    float* row = g_spans + (long)b*SD;
    for (int k = tid; k < 2*BH; k += 256) row[k] = se[(long)b*2*BH + k];
    for (int d = tid; d < BH; d += 256) {
        float acc = 0.f;
        #pragma unroll
        for (int t = 0; t < WW; t++) acc += attn[t]*cont[((long)b*WW + t)*BH + d];
        row[2*BH + d] = acc;
    }
    if (tid < ED) row[2*BH + BH + tid] = wemb[min(w,4)*ED + tid];
}

// ---------------- grounding: att[s,v,i,j] = doc[s,i,:]·img[v,j,:] ----------------
__global__ void att_kernel(const float* __restrict__ doc, const float* __restrict__ img)
{
    int b = blockIdx.x, s = b >> 3, v = b & 7;
    for (int idx = threadIdx.x; idx < FF*RR; idx += blockDim.x) {
        int i = idx / RR, j = idx % RR;
        const float4* dr = (const float4*)(doc + (long)(s*FF + i)*DD);
        const float4* ir = (const float4*)(img + (long)(v*RR + j)*DD);
        float acc = 0.f;
        #pragma unroll 8
        for (int c = 0; c < DD/4; c++) {
            float4 x = dr[c], y = ir[c];
            acc += x.x*y.x + x.y*y.y + x.z*y.z + x.w*y.w;
        }
        g_att[((long)b*FF + i)*RR + j] = acc;
    }
}

// ---------------- grounding reduce -> S_g ----------------
__global__ void ground_reduce(const float* __restrict__ tm, const float* __restrict__ im)
{
    __shared__ float sh[FF][RR+1];
    __shared__ float stm[FF], sim[RR];
    __shared__ float red[FF];
    int b = blockIdx.x, s = b >> 3, v = b & 7;
    int tid = threadIdx.x; // 64
    if (tid < FF) stm[tid] = tm[s*FF + tid];
    if (tid < RR) sim[tid] = im[v*RR + tid];
    __syncthreads();
    for (int idx = tid; idx < FF*RR; idx += 64) {
        int i = idx / RR, j = idx % RR;
        float a = g_att[((long)b*FF + i)*RR + j];
        float m = stm[i]*sim[j];
        a *= m;
        if (a == 0.f) a = NEGV;
        sh[i][j] = a;
    }
    __syncthreads();
    float part = 0.f;
    {
        int i = tid;
        float mx = -INFINITY;
        for (int j = 0; j < RR; j++) mx = fmaxf(mx, sh[i][j]*sim[j]);
        float ssum = 0.f;
        for (int j = 0; j < RR; j++) ssum += expf(sh[i][j]*sim[j] - mx);
        for (int j = 0; j < RR; j++) {
            float aw = expf(sh[i][j]*sim[j] - mx)/ssum * stm[i]*sim[j];
            part += aw * sh[i][j];
        }
    }
    if (tid < RR) {
        int j = tid;
        float mx = -INFINITY;
        for (int i = 0; i < FF; i++) mx = fmaxf(mx, sh[i][j]);
        float ssum = 0.f;
        for (int i = 0; i < FF; i++) ssum += expf(sh[i][j] - mx);
        for (int i = 0; i < FF; i++) {
            float aw = expf(sh[i][j] - mx)/ssum * stm[i]*sim[j];
            part += aw * sh[i][j];
        }
    }
    red[tid] = part;
    __syncthreads();
    for (int o = 32; o > 0; o >>= 1) {
        if (tid < o) red[tid] += red[tid+o];
        __syncthreads();
    }
    if (tid == 0) g_Sg[b] = red[0];
}

// ---------------- adaptive S_c ----------------
__global__ void sc_kernel(const float* __restrict__ m1)
{
    int b = blockIdx.x, s = b >> 3, v = b & 7;
    const float* T = g_ts + (long)b*MS*MS;
    int lane = threadIdx.x;
    float cs = 0.f, cv = 0.f;
    for (int k = 0; k < MS; k++) { cs += m1[s*MS+k]; cv += m1[v*MS+k]; }
    float max1 = -INFINITY, max2 = -INFINITY;
    if (lane < MS) {
        float rm = 0.f;
        for (int j = 0; j < MS; j++) rm += T[lane*MS+j]*m1[v*MS+j];
        rm /= cv;
        if (m1[s*MS+lane] > 0.f) max1 = rm;
        float cm = 0.f;
        for (int i = 0; i < MS; i++) cm += T[i*MS+lane]*m1[s*MS+i];
        cm /= cs;
        if (m1[v*MS+lane] > 0.f) max2 = cm;
    }
    for (int o = 16; o > 0; o >>= 1) {
        max1 = fmaxf(max1, __shfl_xor_sync(0xffffffffu, max1, o));
        max2 = fmaxf(max2, __shfl_xor_sync(0xffffffffu, max2, o));
    }
    if (lane == 0) g_Sc[b] = 0.5f*(max1 + max2);
}

// ---------------- final loss ----------------
__global__ void loss_kernel(float* __restrict__ out)
{
    if (threadIdx.x != 0) return;
    float mg[8][8], mgT[8][8], mc[8][8];
    for (int s = 0; s < 8; s++) {
        float mx = -INFINITY;
        for (int v = 0; v < 8; v++) mx = fmaxf(mx, g_Sg[s*8+v]);
        float sum = 0.f;
        for (int v = 0; v < 8; v++) { mg[s][v] = expf(g_Sg[s*8+v]-mx); sum += mg[s][v]; }
        for (int v = 0; v < 8; v++) mg[s][v] /= sum;
    }
    for (int v = 0; v < 8; v++) {
        float mx = -INFINITY;
        for (int s = 0; s < 8; s++) mx = fmaxf(mx, g_Sg[s*8+v]);
        float sum = 0.f;
        for (int s = 0; s < 8; s++) { mgT[v][s] = expf(g_Sg[s*8+v]-mx); sum += mgT[v][s]; }
        for (int s = 0; s < 8; s++) mgT[v][s] /= sum;
    }
    for (int s = 0; s < 8; s++) {
        float mx = -INFINITY;
        for (int v = 0; v < 8; v++) mx = fmaxf(mx, g_Sc[s*8+v]);
        float sum = 0.f;
        for (int v = 0; v < 8; v++) { mc[s][v] = expf(g_Sc[s*8+v]-mx); sum += mc[s][v]; }
        for (int v = 0; v < 8; v++) mc[s][v] /= sum;
    }
    float loss = 0.f;
    for (int s = 0; s < 8; s++) {
        float t = 0.f;
        for (int v = 0; v < 8; v++) t += mg[s][v]*mc[s][v];
        loss += logf(t);
    }
    for (int v = 0; v < 8; v++) {
        float t = 0.f;
        for (int s = 0; s < 8; s++) t += mgT[v][s]*mc[v][s];
        loss += logf(t);
    }
    out[0] = -loss/(float)ND;
}

// ---------------- host ----------------
extern "C" void kernel_launch(void* const* d_in, const int* in_sizes, int n_in,
                              void* d_out, int out_size)
{
    const float* doc  = (const float*)d_in[0];
    const float* img  = (const float*)d_in[1];
    const float* tm   = (const float*)d_in[2];
    const float* im   = (const float*)d_in[3];
    const float* se   = (const float*)d_in[4];
    const float* cont = (const float*)d_in[5];
    const int*   width= (const int*)  d_in[6];
    const float* m1   = (const float*)d_in[7];
    const float* aw1  = (const float*)d_in[8];
    const float* ab1  = (const float*)d_in[9];
    const float* aw2  = (const float*)d_in[10];
    const float* ab2  = (const float*)d_in[11];
    const float* wemb = (const float*)d_in[12];
    const float* pw1  = (const float*)d_in[13];
    const float* pb1  = (const float*)d_in[14];
    const float* pw2  = (const float*)d_in[15];
    const float* pb2  = (const float*)d_in[16];
    const float* pw3  = (const float*)d_in[17];
    const float* pb3  = (const float*)d_in[18];

    cudaFuncSetAttribute(h1_mma_kernel, cudaFuncAttributeMaxDynamicSharedMemorySize, DSMEM_MMA);
    cudaFuncSetAttribute(h2_mma_kernel, cudaFuncAttributeMaxDynamicSharedMemorySize, DSMEM_MMA);

    // (1) W1c/W2 -> fp16 [n][k]; g_ts = pb3
    int prep_total = PREP_G1 + PREP_G2 + NPAIR;
    prep_kernel<<<(prep_total + 255)/256, 256>>>(pw1, pw2, pb3);
    // (2) span attention hidden (also zeroes g_a/g_b)
    span_gemm_kernel<<<dim3(HH/BN, 1280/BM), 256>>>(cont, aw1, ab1);
    // (3) span scores
    matvec_scores<<<(1280*32+255)/256, 256>>>(aw2, ab2);
    // (4) assemble spans
    assemble_kernel<<<NSPAN, 256>>>(se, cont, width, wemb);
    // (5) a,b = spans @ w1 halves (split-K)
    gemm_ab_kernel<<<dim3(2048/BN, KS), 256>>>(pw1);
    // (6) h1 = relu(prod @ W1c + a + b + b1)  [HMMA fp16 2-term]
    h1_mma_kernel<<<dim3(8, 128), 256, DSMEM_MMA>>>(pb1);
    // (7) ts += relu(h1 @ W2 + b2) @ w3  [HMMA fp16 2-term, fused]
    h2_mma_kernel<<<dim3(8, 128), 256, DSMEM_MMA>>>(pb2, pw3);

    // grounding (independent)
    att_kernel<<<64, 256>>>(doc, img);
    ground_reduce<<<64, 64>>>(tm, im);

    // adaptive S_c + final loss
    sc_kernel<<<64, 32>>>(m1);
    loss_kernel<<<1, 32>>>((float*)d_out);
}

// round 12
// speedup vs baseline: 1.6178x; 1.1614x over previous
#include <cuda_runtime.h>
#include <cuda_bf16.h>
#include <cuda_fp16.h>
#include <math.h>
#include <stdint.h>

// ---------------- problem constants ----------------
#define ND   8
#define FF   64
#define RR   36
#define DD   1024
#define MS   16
#define WW   10
#define BH   768
#define HH   1024
#define ED   20
#define SD   2324
#define NSPAN (ND*MS)          // 128
#define NPAIR (NSPAN*NSPAN)    // 16384
#define NEGV (-1e10f)

#define KPAD1 2368             // 74 * 32
#define KPAD2 1024             // 32 * 32
#define NT1   (KPAD1/32)
#define NT2   (KPAD2/32)

// ---------------- scratch ----------------
__device__ __align__(16) float g_hspan[1280*HH];
__device__ __align__(16) float g_scores[1280];
__device__ __align__(16) float g_spans[NSPAN*SD + 64];   // +pad for over-read
__device__ __align__(16) float g_a[NSPAN*HH];
__device__ __align__(16) float g_b[NSPAN*HH];
__device__ __align__(16) __half g_B1[HH*KPAD1];          // [n][k] = fp16(pw1[2SD+k][n])
__device__ __align__(16) __half g_W2[HH*KPAD2];          // [n][k] = fp16(pw2[k][n])
__device__ __align__(16) __half g_h1[(long)NPAIR*HH];
__device__ __align__(16) float g_ts[NPAIR];
__device__ __align__(16) float g_att[64*FF*RR];
__device__ float g_Sg[64];
__device__ float g_Sc[64];

#define FMA2(d,a,b) asm("fma.rn.f32x2 %0, %1, %2, %0;" : "+l"(d) : "l"(a), "l"(b))

// ---------------- warp MMA helpers (generic sm_80+ path) ----------------
__device__ __forceinline__ unsigned smem_u32(const void* p) {
    unsigned a;
    asm("{ .reg .u64 t; cvta.to.shared.u64 t, %1; cvt.u32.u64 %0, t; }" : "=r"(a) : "l"(p));
    return a;
}
__device__ __forceinline__ void ldsm_x4(unsigned& r0, unsigned& r1, unsigned& r2, unsigned& r3,
                                        unsigned addr) {
    asm volatile("ldmatrix.sync.aligned.m8n8.x4.shared.b16 {%0,%1,%2,%3}, [%4];"
                 : "=r"(r0), "=r"(r1), "=r"(r2), "=r"(r3) : "r"(addr));
}
__device__ __forceinline__ void mma_f16(float (&c)[4], const unsigned (&a)[4],
                                        unsigned b0, unsigned b1) {
    asm volatile(
        "mma.sync.aligned.m16n8k16.row.col.f32.f16.f16.f32 "
        "{%0,%1,%2,%3}, {%4,%5,%6,%7}, {%8,%9}, {%0,%1,%2,%3};"
        : "+f"(c[0]), "+f"(c[1]), "+f"(c[2]), "+f"(c[3])
        : "r"(a[0]), "r"(a[1]), "r"(a[2]), "r"(a[3]), "r"(b0), "r"(b1));
}
#define CP_ASYNC16(saddr, gptr) \
    asm volatile("cp.async.cg.shared.global [%0], [%1], 16;" :: "r"(saddr), "l"(gptr) : "memory")
#define CP_COMMIT() asm volatile("cp.async.commit_group;" ::: "memory")
#define CP_WAIT0()  asm volatile("cp.async.wait_group 0;" ::: "memory")

// smem tile: [128 rows][40 fp16]  (80B stride -> conflict-free ldmatrix; 80 % 16 == 0)
#define TROW 40
#define MATB 10240                  // bytes per matrix per stage (128*40*2)
#define MATE (128*TROW)             // elements per matrix per stage
// stages: {A0,A1,B0,B1}
#define DSMEM_MMA (4*MATB)          // 40960

// ---------------- prep: W1c/W2 -> fp16 [n][k]; init g_ts=pb3 ----------------
#define PREP_G1 (HH*(KPAD1/8))
#define PREP_G2 (HH*(KPAD2/8))
__global__ void prep_kernel(const float* __restrict__ pw1, const float* __restrict__ pw2,
                            const float* __restrict__ pb3)
{
    int gid = blockIdx.x*256 + threadIdx.x;
    if (gid < PREP_G1) {
        int n = gid % HH, kg = gid / HH;
        union { uint4 q; unsigned short us[8]; } H;
        #pragma unroll
        for (int e = 0; e < 8; e++) {
            int k = kg*8 + e;
            float v = (k < SD) ? pw1[((long)(2*SD + k))*HH + n] : 0.f;
            H.us[e] = __half_as_ushort(__float2half_rn(v));
        }
        *(uint4*)(g_B1 + (long)n*KPAD1 + kg*8) = H.q;
    } else if (gid < PREP_G1 + PREP_G2) {
        int j = gid - PREP_G1;
        int n = j % HH, kg = j / HH;
        union { uint4 q; unsigned short us[8]; } H;
        #pragma unroll
        for (int e = 0; e < 8; e++) {
            int k = kg*8 + e;
            H.us[e] = __half_as_ushort(__float2half_rn(pw2[(long)k*HH + n]));
        }
        *(uint4*)(g_W2 + (long)n*KPAD2 + kg*8) = H.q;
    } else {
        int i = gid - PREP_G1 - PREP_G2;
        if (i < NPAIR) g_ts[i] = pb3[0];
    }
}

// ---------------- h1 HMMA kernel (fp16 1-term, double-buffered, cp.async B) ----------------
__global__ void __launch_bounds__(256)
h1_mma_kernel(const float* __restrict__ pb1)
{
    extern __shared__ __align__(16) char dsm8[];
    __half* dsm = (__half*)dsm8;
    unsigned sb = smem_u32(dsm8);

    int tid = threadIdx.x, lane = tid & 31, wid = tid >> 5;
    int wy = wid & 3, wx = wid >> 2;
    int m0 = blockIdx.y*128, n0 = blockIdx.x*128;

    int lrow = tid >> 1, lks = (tid & 1)*16;
    int lgrow = m0 + lrow;
    int lii = (lgrow >> 4) & 15, ljj = lgrow & 15, lsv = lgrow >> 8;
    const float* pa  = g_spans + (long)((lsv >> 3)*MS + lii)*SD;
    const float* pbs = g_spans + (long)((lsv & 7)*MS + ljj)*SD;
    const __half* bsrc = g_B1 + (long)(n0 + lrow)*KPAD1;

    unsigned srow = (unsigned)(lrow*TROW + lks)*2;   // byte offset within a matrix

    float c[2][8][4];
    #pragma unroll
    for (int i = 0; i < 2; i++)
        #pragma unroll
        for (int j = 0; j < 8; j++)
            #pragma unroll
            for (int e = 0; e < 4; e++) c[i][j][e] = 0.f;

    // ---- prologue: fill stage 0 ----
    {
        CP_ASYNC16(sb + 2*MATB + srow,      bsrc + lks);
        CP_ASYNC16(sb + 2*MATB + srow + 16, bsrc + lks + 8);
        CP_COMMIT();
        union { uint4 q[2]; unsigned short us[16]; } H;
        #pragma unroll
        for (int q = 0; q < 4; q++) {
            float4 x = *(const float4*)(pa  + lks + q*4);
            float4 y = *(const float4*)(pbs + lks + q*4);
            H.us[q*4+0] = __half_as_ushort(__float2half_rn(x.x*y.x));
            H.us[q*4+1] = __half_as_ushort(__float2half_rn(x.y*y.y));
            H.us[q*4+2] = __half_as_ushort(__float2half_rn(x.z*y.z));
            H.us[q*4+3] = __half_as_ushort(__float2half_rn(x.w*y.w));
        }
        *(uint4*)&dsm[0*MATE + lrow*TROW + lks]     = H.q[0];
        *(uint4*)&dsm[0*MATE + lrow*TROW + lks + 8] = H.q[1];
        CP_WAIT0();
    }
    __syncthreads();

    for (int t = 0; t < NT1; t++) {
        int cur = t & 1, nxt = cur ^ 1;
        bool more = (t + 1 < NT1);

        if (more) {
            int kk = (t+1)*32 + lks;
            CP_ASYNC16(sb + (2+nxt)*MATB + srow,      bsrc + kk);
            CP_ASYNC16(sb + (2+nxt)*MATB + srow + 16, bsrc + kk + 8);
            CP_COMMIT();
        }

        unsigned sbA = sb + cur*MATB, sbB = sb + (2+cur)*MATB;
        #pragma unroll
        for (int kt = 0; kt < 2; kt++) {
            unsigned a[2][4], b[4][4];
            int arow = lane & 15, acol = (lane >> 4)*8;
            #pragma unroll
            for (int mt = 0; mt < 2; mt++) {
                unsigned off = (unsigned)(((wy*32 + mt*16 + arow)*TROW + kt*16 + acol)*2);
                ldsm_x4(a[mt][0], a[mt][1], a[mt][2], a[mt][3], sbA + off);
            }
            int nrow = (lane & 7) + ((lane >> 4) << 3), kc = lane & 8;
            #pragma unroll
            for (int np = 0; np < 4; np++) {
                unsigned off = (unsigned)(((wx*64 + np*16 + nrow)*TROW + kt*16 + kc)*2);
                ldsm_x4(b[np][0], b[np][1], b[np][2], b[np][3], sbB + off);
            }
            #pragma unroll
            for (int mt = 0; mt < 2; mt++)
                #pragma unroll
                for (int nt = 0; nt < 8; nt++) {
                    int np = nt >> 1, h = (nt & 1)*2;
                    mma_f16(c[mt][nt], a[mt], b[np][h], b[np][h+1]);
                }
        }

        // A tile for t+1 (compute+convert) into next stage; overlaps other warps' MMAs
        if (more) {
            int kk = (t+1)*32 + lks;
            float p[16];
            #pragma unroll
            for (int q = 0; q < 4; q++) {
                float4 x = *(const float4*)(pa  + kk + q*4);
                float4 y = *(const float4*)(pbs + kk + q*4);
                p[q*4+0] = x.x*y.x; p[q*4+1] = x.y*y.y;
                p[q*4+2] = x.z*y.z; p[q*4+3] = x.w*y.w;
            }
            if (kk + 16 > SD) {
                #pragma unroll
                for (int e = 0; e < 16; e++) if (kk + e >= SD) p[e] = 0.f;
            }
            union { uint4 q[2]; unsigned short us[16]; } H;
            #pragma unroll
            for (int e = 0; e < 16; e++) H.us[e] = __half_as_ushort(__float2half_rn(p[e]));
            *(uint4*)&dsm[nxt*MATE + lrow*TROW + lks]     = H.q[0];
            *(uint4*)&dsm[nxt*MATE + lrow*TROW + lks + 8] = H.q[1];
        }
        CP_WAIT0();
        __syncthreads();
    }

    // epilogue: +bias +a +b, relu, store fp16
    int g = lane >> 2, t4 = lane & 3;
    #pragma unroll
    for (int mt = 0; mt < 2; mt++) {
        #pragma unroll
        for (int rr = 0; rr < 2; rr++) {
            int grow = m0 + wy*32 + mt*16 + rr*8 + g;
            int ii = (grow >> 4) & 15, jj = grow & 15, sv = grow >> 8;
            int rA = (sv >> 3)*MS + ii, rB = (sv & 7)*MS + jj;
            #pragma unroll
            for (int nt = 0; nt < 8; nt++) {
                int col = n0 + wx*64 + nt*8 + 2*t4;
                float v0 = c[mt][nt][rr*2+0] + pb1[col]
                         + g_a[rA*HH + col] + g_b[rB*HH + col];
                float v1 = c[mt][nt][rr*2+1] + pb1[col+1]
                         + g_a[rA*HH + col+1] + g_b[rB*HH + col+1];
                v0 = fmaxf(v0, 0.f); v1 = fmaxf(v1, 0.f);
                unsigned short h0 = __half_as_ushort(__float2half_rn(v0));
                unsigned short h1 = __half_as_ushort(__float2half_rn(v1));
                *(unsigned*)&g_h1[(long)grow*HH + col] = (unsigned)h0 | ((unsigned)h1 << 16);
            }
        }
    }
}

// ---------------- h2 HMMA kernel (fp16 1-term, all-cp.async; fused ts matvec) ----------------
__global__ void __launch_bounds__(256)
h2_mma_kernel(const float* __restrict__ pb2, const float* __restrict__ pw3)
{
    extern __shared__ __align__(16) char dsm8[];
    unsigned sb = smem_u32(dsm8);
    __shared__ float w3s[128], pb2s[128];

    int tid = threadIdx.x, lane = tid & 31, wid = tid >> 5;
    int wy = wid & 3, wx = wid >> 2;
    int m0 = blockIdx.y*128, n0 = blockIdx.x*128;

    if (tid < 128) { w3s[tid] = pw3[n0 + tid]; pb2s[tid] = pb2[n0 + tid]; }

    int lrow = tid >> 1, lks = (tid & 1)*16;
    const __half* asrc = g_h1 + (long)(m0 + lrow)*HH;
    const __half* bsrc = g_W2 + (long)(n0 + lrow)*KPAD2;
    unsigned srow = (unsigned)(lrow*TROW + lks)*2;

    float c[2][8][4];
    #pragma unroll
    for (int i = 0; i < 2; i++)
        #pragma unroll
        for (int j = 0; j < 8; j++)
            #pragma unroll
            for (int e = 0; e < 4; e++) c[i][j][e] = 0.f;

    // prologue: stage 0
    {
        CP_ASYNC16(sb + 0*MATB + srow,      asrc + lks);
        CP_ASYNC16(sb + 0*MATB + srow + 16, asrc + lks + 8);
        CP_ASYNC16(sb + 2*MATB + srow,      bsrc + lks);
        CP_ASYNC16(sb + 2*MATB + srow + 16, bsrc + lks + 8);
        CP_COMMIT(); CP_WAIT0();
    }
    __syncthreads();

    for (int t = 0; t < NT2; t++) {
        int cur = t & 1, nxt = cur ^ 1;
        bool more = (t + 1 < NT2);

        if (more) {
            int kk = (t+1)*32 + lks;
            CP_ASYNC16(sb + nxt*MATB + srow,          asrc + kk);
            CP_ASYNC16(sb + nxt*MATB + srow + 16,     asrc + kk + 8);
            CP_ASYNC16(sb + (2+nxt)*MATB + srow,      bsrc + kk);
            CP_ASYNC16(sb + (2+nxt)*MATB + srow + 16, bsrc + kk + 8);
            CP_COMMIT();
        }

        unsigned sbA = sb + cur*MATB, sbB = sb + (2+cur)*MATB;
        #pragma unroll
        for (int kt = 0; kt < 2; kt++) {
            unsigned a[2][4], b[4][4];
            int arow = lane & 15, acol = (lane >> 4)*8;
            #pragma unroll
            for (int mt = 0; mt < 2; mt++) {
                unsigned off = (unsigned)(((wy*32 + mt*16 + arow)*TROW + kt*16 + acol)*2);
                ldsm_x4(a[mt][0], a[mt][1], a[mt][2], a[mt][3], sbA + off);
            }
            int nrow = (lane & 7) + ((lane >> 4) << 3), kc = lane & 8;
            #pragma unroll
            for (int np = 0; np < 4; np++) {
                unsigned off = (unsigned)(((wx*64 + np*16 + nrow)*TROW + kt*16 + kc)*2);
                ldsm_x4(b[np][0], b[np][1], b[np][2], b[np][3], sbB + off);
            }
            #pragma unroll
            for (int mt = 0; mt < 2; mt++)
                #pragma unroll
                for (int nt = 0; nt < 8; nt++) {
                    int np = nt >> 1, h = (nt & 1)*2;
                    mma_f16(c[mt][nt], a[mt], b[np][h], b[np][h+1]);
                }
        }
        CP_WAIT0();
        __syncthreads();
    }

    // epilogue: relu(+b2) dot w3; quad reduce; atomicAdd into g_ts
    int g = lane >> 2, t4 = lane & 3;
    #pragma unroll
    for (int mt = 0; mt < 2; mt++) {
        float p0 = 0.f, p1 = 0.f;
        #pragma unroll
        for (int nt = 0; nt < 8; nt++) {
            int lc = wx*64 + nt*8 + 2*t4;
            p0 += fmaxf(c[mt][nt][0] + pb2s[lc],   0.f)*w3s[lc]
                + fmaxf(c[mt][nt][1] + pb2s[lc+1], 0.f)*w3s[lc+1];
            p1 += fmaxf(c[mt][nt][2] + pb2s[lc],   0.f)*w3s[lc]
                + fmaxf(c[mt][nt][3] + pb2s[lc+1], 0.f)*w3s[lc+1];
        }
        p0 += __shfl_xor_sync(0xffffffffu, p0, 1);
        p0 += __shfl_xor_sync(0xffffffffu, p0, 2);
        p1 += __shfl_xor_sync(0xffffffffu, p1, 1);
        p1 += __shfl_xor_sync(0xffffffffu, p1, 2);
        if (t4 == 0) {
            atomicAdd(&g_ts[m0 + wy*32 + mt*16 + g],     p0);
            atomicAdd(&g_ts[m0 + wy*32 + mt*16 + 8 + g], p1);
        }
    }
}

// ---------------- SIMT span GEMM (1280x1024x768, bias+relu; also zeroes g_a/g_b) ----------------
#define BM 128
#define BN 128
#define BK 16
#define TM 8
#define TN 8

__global__ __launch_bounds__(256, 2)
void span_gemm_kernel(const float* __restrict__ A, const float* __restrict__ B,
                      const float* __restrict__ bias)
{
    const int N = HH, K = BH;
    float* C = g_hspan;

    __shared__ __align__(16) float2 As2[2][BK][BM];
    __shared__ __align__(16) float  Bs[2][BK][BN];

    int tid = threadIdx.x;
    {   // zero g_a/g_b for split-K atomics
        float4 z = make_float4(0.f,0.f,0.f,0.f);
        int gt = (blockIdx.y*gridDim.x + blockIdx.x)*256 + tid;
        int nb = gridDim.x*gridDim.y*256;
        for (int i = gt; i < NSPAN*HH/4; i += nb) {
            ((float4*)g_a)[i] = z;
            ((float4*)g_b)[i] = z;
        }
    }
    int m0 = blockIdx.y * BM;
    int n0 = blockIdx.x * BN;

    int la_row = tid >> 1, la_cb = (tid & 1) * 8;
    int lb_row = tid >> 4, lb_col = (tid & 15) * 8;

    unsigned long long acc2[TM][TN/2];
    #pragma unroll
    for (int i = 0; i < TM; i++)
        #pragma unroll
        for (int j = 0; j < TN/2; j++) acc2[i][j] = 0ull;

    int tx = tid & 15, ty = tid >> 4;
    int ntiles = K / BK;

    float4 aR[2], bR[2];
    #pragma unroll
    for (int c = 0; c < 2; c++) {
        aR[c] = *(const float4*)(A + (long)(m0+la_row)*K + la_cb + c*4);
        bR[c] = *(const float4*)(B + (long)lb_row*N + n0 + lb_col + c*4);
    }
    #pragma unroll
    for (int c = 0; c < 2; c++) {
        int kc = la_cb + c*4;
        As2[0][kc+0][la_row] = make_float2(aR[c].x, aR[c].x);
        As2[0][kc+1][la_row] = make_float2(aR[c].y, aR[c].y);
        As2[0][kc+2][la_row] = make_float2(aR[c].z, aR[c].z);
        As2[0][kc+3][la_row] = make_float2(aR[c].w, aR[c].w);
        *(float4*)&Bs[0][lb_row][lb_col + c*4] = bR[c];
    }
    __syncthreads();

    for (int t = 0; t < ntiles; t++) {
        int cur = t & 1, nxt = cur ^ 1;
        bool more = (t + 1 < ntiles);
        if (more) {
            int k0 = (t + 1) * BK;
            #pragma unroll
            for (int c = 0; c < 2; c++) {
                aR[c] = *(const float4*)(A + (long)(m0+la_row)*K + k0 + la_cb + c*4);
                bR[c] = *(const float4*)(B + (long)(k0+lb_row)*N + n0 + lb_col + c*4);
            }
        }
        #pragma unroll
        for (int kk = 0; kk < BK; kk++) {
            unsigned long long rm2[TM], rb2[TN/2];
            #pragma unroll
            for (int i = 0; i < TM; i += 2) {
                ulonglong2 v = *(const ulonglong2*)&As2[cur][kk][ty*TM + i];
                rm2[i] = v.x; rm2[i+1] = v.y;
            }
            #pragma unroll
            for (int j = 0; j < TN/2; j += 2) {
                ulonglong2 v = *(const ulonglong2*)&Bs[cur][kk][tx*TN + 2*j];
                rb2[j] = v.x; rb2[j+1] = v.y;
            }
            #pragma unroll
            for (int i = 0; i < TM; i++)
                #pragma unroll
                for (int j = 0; j < TN/2; j++)
                    FMA2(acc2[i][j], rm2[i], rb2[j]);
        }
        if (more) {
            #pragma unroll
            for (int c = 0; c < 2; c++) {
                int kc = la_cb + c*4;
                As2[nxt][kc+0][la_row] = make_float2(aR[c].x, aR[c].x);
                As2[nxt][kc+1][la_row] = make_float2(aR[c].y, aR[c].y);
                As2[nxt][kc+2][la_row] = make_float2(aR[c].z, aR[c].z);
                As2[nxt][kc+3][la_row] = make_float2(aR[c].w, aR[c].w);
                *(float4*)&Bs[nxt][lb_row][lb_col + c*4] = bR[c];
            }
        }
        __syncthreads();
    }

    #pragma unroll
    for (int i = 0; i < TM; i++) {
        int row = m0 + ty*TM + i;
        #pragma unroll
        for (int q = 0; q < 2; q++) {
            int col = n0 + tx*TN + q*4;
            float v0 = __uint_as_float((unsigned)(acc2[i][2*q]   & 0xffffffffull));
            float v1 = __uint_as_float((unsigned)(acc2[i][2*q]   >> 32));
            float v2 = __uint_as_float((unsigned)(acc2[i][2*q+1] & 0xffffffffull));
            float v3 = __uint_as_float((unsigned)(acc2[i][2*q+1] >> 32));
            float4 bv = *(const float4*)(bias + col);
            v0 = fmaxf(v0 + bv.x, 0.f); v1 = fmaxf(v1 + bv.y, 0.f);
            v2 = fmaxf(v2 + bv.z, 0.f); v3 = fmaxf(v3 + bv.w, 0.f);
            *(float4*)(C + (long)row*N + col) = make_float4(v0, v1, v2, v3);
        }
    }
}

// ---------------- split-K GEMM computing g_a and g_b together ----------------
#define KS 8
#define KSLC 292   // multiple of 4 (float4 alignment); 8*292 >= 2324

__global__ __launch_bounds__(256, 2)
void gemm_ab_kernel(const float* __restrict__ pw1)
{
    __shared__ __align__(16) float2 As2[BK][BM];
    __shared__ __align__(16) float  Bs[BK][BN];

    int tid = threadIdx.x;
    int n0 = blockIdx.x * BN;
    int kstart = blockIdx.y * KSLC;
    int kend = min(kstart + KSLC, SD);

    const float* Bsel = (n0 < HH) ? pw1 + n0 : pw1 + (long)SD*HH + (n0 - HH);
    float* Cout = (n0 < HH) ? g_a + n0 : g_b + (n0 - HH);

    int la_row = tid >> 1, la_cb = (tid & 1) * 8;
    int lb_row = tid >> 4, lb_col = (tid & 15) * 8;

    unsigned long long acc2[TM][TN/2];
    #pragma unroll
    for (int i = 0; i < TM; i++)
        #pragma unroll
        for (int j = 0; j < TN/2; j++) acc2[i][j] = 0ull;

    int tx = tid & 15, ty = tid >> 4;

    for (int k0 = kstart; k0 < kend; k0 += BK) {
        #pragma unroll
        for (int c = 0; c < 2; c++) {
            int k = k0 + la_cb + c*4;
            float4 v = make_float4(0.f,0.f,0.f,0.f);
            if (k < kend) v = *(const float4*)(g_spans + (long)la_row*SD + k);
            int kc = la_cb + c*4;
            As2[kc+0][la_row] = make_float2(v.x, v.x);
            As2[kc+1][la_row] = make_float2(v.y, v.y);
            As2[kc+2][la_row] = make_float2(v.z, v.z);
            As2[kc+3][la_row] = make_float2(v.w, v.w);
            int kb = k0 + lb_row;
            float4 w = make_float4(0.f,0.f,0.f,0.f);
            if (kb < kend) w = *(const float4*)(Bsel + (long)kb*HH + lb_col + c*4);
            *(float4*)&Bs[lb_row][lb_col + c*4] = w;
        }
        __syncthreads();
        #pragma unroll
        for (int kk = 0; kk < BK; kk++) {
            unsigned long long rm2[TM], rb2[TN/2];
            #pragma unroll
            for (int i = 0; i < TM; i += 2) {
                ulonglong2 v = *(const ulonglong2*)&As2[kk][ty*TM + i];
                rm2[i] = v.x; rm2[i+1] = v.y;
            }
            #pragma unroll
            for (int j = 0; j < TN/2; j += 2) {
                ulonglong2 v = *(const ulonglong2*)&Bs[kk][tx*TN + 2*j];
                rb2[j] = v.x; rb2[j+1] = v.y;
            }
            #pragma unroll
            for (int i = 0; i < TM; i++)
                #pragma unroll
                for (int j = 0; j < TN/2; j++)
                    FMA2(acc2[i][j], rm2[i], rb2[j]);
        }
        __syncthreads();
    }

    #pragma unroll
    for (int i = 0; i < TM; i++) {
        int row = ty*TM + i;
        #pragma unroll
        for (int j = 0; j < TN/2; j++) {
            int col = tx*TN + 2*j;
            float v0 = __uint_as_float((unsigned)(acc2[i][j] & 0xffffffffull));
            float v1 = __uint_as_float((unsigned)(acc2[i][j] >> 32));
            atomicAdd(Cout + (long)row*HH + col,     v0);
            atomicAdd(Cout + (long)row*HH + col + 1, v1);
        }
    }
}

// ---------------- matvec for span scores ----------------
__global__ void matvec_scores(const float* __restrict__ w, const float* __restrict__ bias)
{
    int warp = (blockIdx.x*blockDim.x + threadIdx.x) >> 5;
    int lane = threadIdx.x & 31;
    if (warp >= 1280) return;
    const float4* a4 = (const float4*)(g_hspan + (long)warp*1024);
    const float4* w4 = (const float4*)w;
    float s = 0.f;
    #pragma unroll 4
    for (int c = lane; c < 256; c += 32) {
        float4 x = a4[c], y = w4[c];
        s += x.x*y.x + x.y*y.y + x.z*y.z + x.w*y.w;
    }
    #pragma unroll
    for (int o = 16; o > 0; o >>= 1) s += __shfl_xor_sync(0xffffffffu, s, o);
    if (lane == 0) g_scores[warp] = s + bias[0];
}

// ---------------- span softmax + assemble spans ----------------
__global__ void assemble_kernel(const float* __restrict__ se, const float* __restrict__ cont,
                                const int* __restrict__ width, const float* __restrict__ wemb)
{
    int b = blockIdx.x;
    int tid = threadIdx.x;
    __shared__ float attn[WW];
    int w = width[b];
    if (tid == 0) {
        float sc[WW]; float mx = -INFINITY;
        for (int t = 0; t < WW; t++) {
            sc[t] = (t < w) ? g_scores[b*WW + t] : NEGV;
            mx = fmaxf(mx, sc[t]);
        }
        float sum = 0.f;
        for (int t = 0; t < WW; t++) { sc[t] = expf(sc[t] - mx); sum += sc[t]; }
        for (int t = 0; t < WW; t++) attn[t] = sc[t]/sum;
    }
    __syncthreads();
    float* row = g_spans + (long)b*SD;
    for (int k = tid; k < 2*BH; k += 256) row[k] = se[(long)b*2*BH + k];
    for (int d = tid; d < BH; d += 256) {
        float acc = 0.f;
        #pragma unroll
        for (int t = 0; t < WW; t++) acc += attn[t]*cont[((long)b*WW + t)*BH + d];
        row[2*BH + d] = acc;
    }
    if (tid < ED) row[2*BH + BH + tid] = wemb[min(w,4)*ED + tid];
}

// ---------------- grounding: att[s,v,i,j] = doc[s,i,:]·img[v,j,:] ----------------
__global__ void att_kernel(const float* __restrict__ doc, const float* __restrict__ img)
{
    int b = blockIdx.x, s = b >> 3, v = b & 7;
    for (int idx = threadIdx.x; idx < FF*RR; idx += blockDim.x) {
        int i = idx / RR, j = idx % RR;
        const float4* dr = (const float4*)(doc + (long)(s*FF + i)*DD);
        const float4* ir = (const float4*)(img + (long)(v*RR + j)*DD);
        float acc = 0.f;
        #pragma unroll 8
        for (int c = 0; c < DD/4; c++) {
            float4 x = dr[c], y = ir[c];
            acc += x.x*y.x + x.y*y.y + x.z*y.z + x.w*y.w;
        }
        g_att[((long)b*FF + i)*RR + j] = acc;
    }
}

// ---------------- grounding reduce -> S_g ----------------
__global__ void ground_reduce(const float* __restrict__ tm, const float* __restrict__ im)
{
    __shared__ float sh[FF][RR+1];
    __shared__ float stm[FF], sim[RR];
    __shared__ float red[FF];
    int b = blockIdx.x, s = b >> 3, v = b & 7;
    int tid = threadIdx.x; // 64
    if (tid < FF) stm[tid] = tm[s*FF + tid];
    if (tid < RR) sim[tid] = im[v*RR + tid];
    __syncthreads();
    for (int idx = tid; idx < FF*RR; idx += 64) {
        int i = idx / RR, j = idx % RR;
        float a = g_att[((long)b*FF + i)*RR + j];
        float m = stm[i]*sim[j];
        a *= m;
        if (a == 0.f) a = NEGV;
        sh[i][j] = a;
    }
    __syncthreads();
    float part = 0.f;
    {
        int i = tid;
        float mx = -INFINITY;
        for (int j = 0; j < RR; j++) mx = fmaxf(mx, sh[i][j]*sim[j]);
        float ssum = 0.f;
        for (int j = 0; j < RR; j++) ssum += expf(sh[i][j]*sim[j] - mx);
        for (int j = 0; j < RR; j++) {
            float aw = expf(sh[i][j]*sim[j] - mx)/ssum * stm[i]*sim[j];
            part += aw * sh[i][j];
        }
    }
    if (tid < RR) {
        int j = tid;
        float mx = -INFINITY;
        for (int i = 0; i < FF; i++) mx = fmaxf(mx, sh[i][j]);
        float ssum = 0.f;
        for (int i = 0; i < FF; i++) ssum += expf(sh[i][j] - mx);
        for (int i = 0; i < FF; i++) {
            float aw = expf(sh[i][j] - mx)/ssum * stm[i]*sim[j];
            part += aw * sh[i][j];
        }
    }
    red[tid] = part;
    __syncthreads();
    for (int o = 32; o > 0; o >>= 1) {
        if (tid < o) red[tid] += red[tid+o];
        __syncthreads();
    }
    if (tid == 0) g_Sg[b] = red[0];
}

// ---------------- adaptive S_c ----------------
__global__ void sc_kernel(const float* __restrict__ m1)
{
    int b = blockIdx.x, s = b >> 3, v = b & 7;
    const float* T = g_ts + (long)b*MS*MS;
    int lane = threadIdx.x;
    float cs = 0.f, cv = 0.f;
    for (int k = 0; k < MS; k++) { cs += m1[s*MS+k]; cv += m1[v*MS+k]; }
    float max1 = -INFINITY, max2 = -INFINITY;
    if (lane < MS) {
        float rm = 0.f;
        for (int j = 0; j < MS; j++) rm += T[lane*MS+j]*m1[v*MS+j];
        rm /= cv;
        if (m1[s*MS+lane] > 0.f) max1 = rm;
        float cm = 0.f;
        for (int i = 0; i < MS; i++) cm += T[i*MS+lane]*m1[s*MS+i];
        cm /= cs;
        if (m1[v*MS+lane] > 0.f) max2 = cm;
    }
    for (int o = 16; o > 0; o >>= 1) {
        max1 = fmaxf(max1, __shfl_xor_sync(0xffffffffu, max1, o));
        max2 = fmaxf(max2, __shfl_xor_sync(0xffffffffu, max2, o));
    }
    if (lane == 0) g_Sc[b] = 0.5f*(max1 + max2);
}

// ---------------- final loss ----------------
__global__ void loss_kernel(float* __restrict__ out)
{
    if (threadIdx.x != 0) return;
    float mg[8][8], mgT[8][8], mc[8][8];
    for (int s = 0; s < 8; s++) {
        float mx = -INFINITY;
        for (int v = 0; v < 8; v++) mx = fmaxf(mx, g_Sg[s*8+v]);
        float sum = 0.f;
        for (int v = 0; v < 8; v++) { mg[s][v] = expf(g_Sg[s*8+v]-mx); sum += mg[s][v]; }
        for (int v = 0; v < 8; v++) mg[s][v] /= sum;
    }
    for (int v = 0; v < 8; v++) {
        float mx = -INFINITY;
        for (int s = 0; s < 8; s++) mx = fmaxf(mx, g_Sg[s*8+v]);
        float sum = 0.f;
        for (int s = 0; s < 8; s++) { mgT[v][s] = expf(g_Sg[s*8+v]-mx); sum += mgT[v][s]; }
        for (int s = 0; s < 8; s++) mgT[v][s] /= sum;
    }
    for (int s = 0; s < 8; s++) {
        float mx = -INFINITY;
        for (int v = 0; v < 8; v++) mx = fmaxf(mx, g_Sc[s*8+v]);
        float sum = 0.f;
        for (int v = 0; v < 8; v++) { mc[s][v] = expf(g_Sc[s*8+v]-mx); sum += mc[s][v]; }
        for (int v = 0; v < 8; v++) mc[s][v] /= sum;
    }
    float loss = 0.f;
    for (int s = 0; s < 8; s++) {
        float t = 0.f;
        for (int v = 0; v < 8; v++) t += mg[s][v]*mc[s][v];
        loss += logf(t);
    }
    for (int v = 0; v < 8; v++) {
        float t = 0.f;
        for (int s = 0; s < 8; s++) t += mgT[v][s]*mc[v][s];
        loss += logf(t);
    }
    out[0] = -loss/(float)ND;
}

// ---------------- host ----------------
extern "C" void kernel_launch(void* const* d_in, const int* in_sizes, int n_in,
                              void* d_out, int out_size)
{
    const float* doc  = (const float*)d_in[0];
    const float* img  = (const float*)d_in[1];
    const float* tm   = (const float*)d_in[2];
    const float* im   = (const float*)d_in[3];
    const float* se   = (const float*)d_in[4];
    const float* cont = (const float*)d_in[5];
    const int*   width= (const int*)  d_in[6];
    const float* m1   = (const float*)d_in[7];
    const float* aw1  = (const float*)d_in[8];
    const float* ab1  = (const float*)d_in[9];
    const float* aw2  = (const float*)d_in[10];
    const float* ab2  = (const float*)d_in[11];
    const float* wemb = (const float*)d_in[12];
    const float* pw1  = (const float*)d_in[13];
    const float* pb1  = (const float*)d_in[14];
    const float* pw2  = (const float*)d_in[15];
    const float* pb2  = (const float*)d_in[16];
    const float* pw3  = (const float*)d_in[17];
    const float* pb3  = (const float*)d_in[18];

    cudaFuncSetAttribute(h1_mma_kernel, cudaFuncAttributeMaxDynamicSharedMemorySize, DSMEM_MMA);
    cudaFuncSetAttribute(h2_mma_kernel, cudaFuncAttributeMaxDynamicSharedMemorySize, DSMEM_MMA);

    // (1) W1c/W2 -> fp16 [n][k]; g_ts = pb3
    int prep_total = PREP_G1 + PREP_G2 + NPAIR;
    prep_kernel<<<(prep_total + 255)/256, 256>>>(pw1, pw2, pb3);
    // (2) span attention hidden (also zeroes g_a/g_b)
    span_gemm_kernel<<<dim3(HH/BN, 1280/BM), 256>>>(cont, aw1, ab1);
    // (3) span scores
    matvec_scores<<<(1280*32+255)/256, 256>>>(aw2, ab2);
    // (4) assemble spans
    assemble_kernel<<<NSPAN, 256>>>(se, cont, width, wemb);
    // (5) a,b = spans @ w1 halves (split-K)
    gemm_ab_kernel<<<dim3(2048/BN, KS), 256>>>(pw1);
    // (6) h1 = relu(prod @ W1c + a + b + b1)  [HMMA fp16 1-term]
    h1_mma_kernel<<<dim3(8, 128), 256, DSMEM_MMA>>>(pb1);
    // (7) ts += relu(h1 @ W2 + b2) @ w3  [HMMA fp16 1-term, fused]
    h2_mma_kernel<<<dim3(8, 128), 256, DSMEM_MMA>>>(pb2, pw3);

    // grounding (independent)
    att_kernel<<<64, 256>>>(doc, img);
    ground_reduce<<<64, 64>>>(tm, im);

    // adaptive S_c + final loss
    sc_kernel<<<64, 32>>>(m1);
    loss_kernel<<<1, 32>>>((float*)d_out);
}

// round 13
// speedup vs baseline: 1.8215x; 1.1259x over previous
#include <cuda_runtime.h>
#include <cuda_bf16.h>
#include <cuda_fp16.h>
#include <math.h>
#include <stdint.h>

// ---------------- problem constants ----------------
#define ND   8
#define FF   64
#define RR   36
#define DD   1024
#define MS   16
#define WW   10
#define BH   768
#define HH   1024
#define ED   20
#define SD   2324
#define NSPAN (ND*MS)          // 128
#define NPAIR (NSPAN*NSPAN)    // 16384
#define NEGV (-1e10f)

#define KPAD1 2368             // 74 * 32
#define KPAD2 1024             // 32 * 32
#define KSP   768              // span GEMM K
#define NT1   (KPAD1/32)
#define NT2   (KPAD2/32)
#define NTS   (KSP/32)

// ---------------- scratch ----------------
__device__ __align__(16) float g_scores[1280];
__device__ __align__(16) float g_spans[NSPAN*SD + 64];
__device__ __align__(16) __half g_spansh[NSPAN*KPAD1];  // fp16 spans, zero-padded
__device__ __align__(16) float g_a[NSPAN*HH];
__device__ __align__(16) float g_b[NSPAN*HH];
__device__ __align__(16) __half g_B1[HH*KPAD1];         // [n][k] = fp16(pw1[2SD+k][n])
__device__ __align__(16) __half g_W2[HH*KPAD2];         // [n][k] = fp16(pw2[k][n])
__device__ __align__(16) __half g_W1T[HH*KSP];          // [n][k] = fp16(aw1[k][n])
__device__ __align__(16) __half g_h1[(long)NPAIR*HH];
__device__ __align__(16) float g_ts[NPAIR];
__device__ __align__(16) float g_att[64*FF*RR];
__device__ float g_Sg[64];
__device__ float g_Sc[64];

#define FMA2(d,a,b) asm("fma.rn.f32x2 %0, %1, %2, %0;" : "+l"(d) : "l"(a), "l"(b))

// ---------------- warp MMA helpers ----------------
__device__ __forceinline__ unsigned smem_u32(const void* p) {
    unsigned a;
    asm("{ .reg .u64 t; cvta.to.shared.u64 t, %1; cvt.u32.u64 %0, t; }" : "=r"(a) : "l"(p));
    return a;
}
__device__ __forceinline__ void ldsm_x4(unsigned& r0, unsigned& r1, unsigned& r2, unsigned& r3,
                                        unsigned addr) {
    asm volatile("ldmatrix.sync.aligned.m8n8.x4.shared.b16 {%0,%1,%2,%3}, [%4];"
                 : "=r"(r0), "=r"(r1), "=r"(r2), "=r"(r3) : "r"(addr));
}
__device__ __forceinline__ void mma_f16(float (&c)[4], const unsigned (&a)[4],
                                        unsigned b0, unsigned b1) {
    asm volatile(
        "mma.sync.aligned.m16n8k16.row.col.f32.f16.f16.f32 "
        "{%0,%1,%2,%3}, {%4,%5,%6,%7}, {%8,%9}, {%0,%1,%2,%3};"
        : "+f"(c[0]), "+f"(c[1]), "+f"(c[2]), "+f"(c[3])
        : "r"(a[0]), "r"(a[1]), "r"(a[2]), "r"(a[3]), "r"(b0), "r"(b1));
}
#define CP_ASYNC16(saddr, gptr) \
    asm volatile("cp.async.cg.shared.global [%0], [%1], 16;" :: "r"(saddr), "l"(gptr) : "memory")
#define CP_COMMIT() asm volatile("cp.async.commit_group;" ::: "memory")
#define CP_WAIT0()  asm volatile("cp.async.wait_group 0;" ::: "memory")

#define TROW 40
#define MATB 10240
#define MATE (128*TROW)
#define DSMEM_MMA (4*MATB)          // 40960

// ---------------- prep: weights -> fp16 [n][k]; init g_ts, g_scores ----------------
#define PREP_G1 (HH*(KPAD1/8))
#define PREP_G2 (HH*(KPAD2/8))
#define PREP_G3 (HH*(KSP/8))
__global__ void prep_kernel(const float* __restrict__ pw1, const float* __restrict__ pw2,
                            const float* __restrict__ aw1, const float* __restrict__ pb3,
                            const float* __restrict__ ab2)
{
    int gid = blockIdx.x*256 + threadIdx.x;
    if (gid < PREP_G1) {
        int n = gid % HH, kg = gid / HH;
        union { uint4 q; unsigned short us[8]; } H;
        #pragma unroll
        for (int e = 0; e < 8; e++) {
            int k = kg*8 + e;
            float v = (k < SD) ? pw1[((long)(2*SD + k))*HH + n] : 0.f;
            H.us[e] = __half_as_ushort(__float2half_rn(v));
        }
        *(uint4*)(g_B1 + (long)n*KPAD1 + kg*8) = H.q;
    } else if (gid < PREP_G1 + PREP_G2) {
        int j = gid - PREP_G1;
        int n = j % HH, kg = j / HH;
        union { uint4 q; unsigned short us[8]; } H;
        #pragma unroll
        for (int e = 0; e < 8; e++) {
            int k = kg*8 + e;
            H.us[e] = __half_as_ushort(__float2half_rn(pw2[(long)k*HH + n]));
        }
        *(uint4*)(g_W2 + (long)n*KPAD2 + kg*8) = H.q;
    } else if (gid < PREP_G1 + PREP_G2 + PREP_G3) {
        int j = gid - PREP_G1 - PREP_G2;
        int n = j % HH, kg = j / HH;
        union { uint4 q; unsigned short us[8]; } H;
        #pragma unroll
        for (int e = 0; e < 8; e++) {
            int k = kg*8 + e;
            H.us[e] = __half_as_ushort(__float2half_rn(aw1[(long)k*HH + n]));
        }
        *(uint4*)(g_W1T + (long)n*KSP + kg*8) = H.q;
    } else {
        int i = gid - PREP_G1 - PREP_G2 - PREP_G3;
        if (i < NPAIR) g_ts[i] = pb3[0];
        else if (i < NPAIR + 1280) g_scores[i - NPAIR] = ab2[0];
    }
}

// ---------------- span HMMA kernel: scores += relu(cont@W1T + b1) . aw2 ----------------
__global__ void __launch_bounds__(256)
span_mma_kernel(const float* __restrict__ cont, const float* __restrict__ ab1,
                const float* __restrict__ aw2)
{
    extern __shared__ __align__(16) char dsm8[];
    __half* dsm = (__half*)dsm8;
    unsigned sb = smem_u32(dsm8);
    __shared__ float w2s[128], b1s[128];

    int tid = threadIdx.x, lane = tid & 31, wid = tid >> 5;
    int wy = wid & 3, wx = wid >> 2;
    int m0 = blockIdx.y*128, n0 = blockIdx.x*128;

    if (tid < 128) { w2s[tid] = aw2[n0 + tid]; b1s[tid] = ab1[n0 + tid]; }

    int lrow = tid >> 1, lks = (tid & 1)*16;
    const float* asrc = cont + (long)(m0 + lrow)*KSP;
    const __half* bsrc = g_W1T + (long)(n0 + lrow)*KSP;
    unsigned srow = (unsigned)(lrow*TROW + lks)*2;

    float c[2][8][4];
    #pragma unroll
    for (int i = 0; i < 2; i++)
        #pragma unroll
        for (int j = 0; j < 8; j++)
            #pragma unroll
            for (int e = 0; e < 4; e++) c[i][j][e] = 0.f;

    // prologue: stage 0 (A converted inline, B via cp.async)
    {
        CP_ASYNC16(sb + 2*MATB + srow,      bsrc + lks);
        CP_ASYNC16(sb + 2*MATB + srow + 16, bsrc + lks + 8);
        CP_COMMIT();
        union { uint4 q[2]; unsigned short us[16]; } H;
        #pragma unroll
        for (int q = 0; q < 4; q++) {
            float4 x = *(const float4*)(asrc + lks + q*4);
            H.us[q*4+0] = __half_as_ushort(__float2half_rn(x.x));
            H.us[q*4+1] = __half_as_ushort(__float2half_rn(x.y));
            H.us[q*4+2] = __half_as_ushort(__float2half_rn(x.z));
            H.us[q*4+3] = __half_as_ushort(__float2half_rn(x.w));
        }
        *(uint4*)&dsm[0*MATE + lrow*TROW + lks]     = H.q[0];
        *(uint4*)&dsm[0*MATE + lrow*TROW + lks + 8] = H.q[1];
        CP_WAIT0();
    }
    __syncthreads();

    for (int t = 0; t < NTS; t++) {
        int cur = t & 1, nxt = cur ^ 1;
        bool more = (t + 1 < NTS);

        if (more) {
            int kk = (t+1)*32 + lks;
            CP_ASYNC16(sb + (2+nxt)*MATB + srow,      bsrc + kk);
            CP_ASYNC16(sb + (2+nxt)*MATB + srow + 16, bsrc + kk + 8);
            CP_COMMIT();
        }

        unsigned sbA = sb + cur*MATB, sbB = sb + (2+cur)*MATB;
        #pragma unroll
        for (int kt = 0; kt < 2; kt++) {
            unsigned a[2][4], b[4][4];
            int arow = lane & 15, acol = (lane >> 4)*8;
            #pragma unroll
            for (int mt = 0; mt < 2; mt++) {
                unsigned off = (unsigned)(((wy*32 + mt*16 + arow)*TROW + kt*16 + acol)*2);
                ldsm_x4(a[mt][0], a[mt][1], a[mt][2], a[mt][3], sbA + off);
            }
            int nrow = (lane & 7) + ((lane >> 4) << 3), kc = lane & 8;
            #pragma unroll
            for (int np = 0; np < 4; np++) {
                unsigned off = (unsigned)(((wx*64 + np*16 + nrow)*TROW + kt*16 + kc)*2);
                ldsm_x4(b[np][0], b[np][1], b[np][2], b[np][3], sbB + off);
            }
            #pragma unroll
            for (int mt = 0; mt < 2; mt++)
                #pragma unroll
                for (int nt = 0; nt < 8; nt++) {
                    int np = nt >> 1, h = (nt & 1)*2;
                    mma_f16(c[mt][nt], a[mt], b[np][h], b[np][h+1]);
                }
        }

        if (more) {
            int kk = (t+1)*32 + lks;
            union { uint4 q[2]; unsigned short us[16]; } H;
            #pragma unroll
            for (int q = 0; q < 4; q++) {
                float4 x = *(const float4*)(asrc + kk + q*4);
                H.us[q*4+0] = __half_as_ushort(__float2half_rn(x.x));
                H.us[q*4+1] = __half_as_ushort(__float2half_rn(x.y));
                H.us[q*4+2] = __half_as_ushort(__float2half_rn(x.z));
                H.us[q*4+3] = __half_as_ushort(__float2half_rn(x.w));
            }
            *(uint4*)&dsm[nxt*MATE + lrow*TROW + lks]     = H.q[0];
            *(uint4*)&dsm[nxt*MATE + lrow*TROW + lks + 8] = H.q[1];
        }
        CP_WAIT0();
        __syncthreads();
    }

    // epilogue: relu(+b1) dot aw2; quad reduce; atomicAdd into g_scores
    int g = lane >> 2, t4 = lane & 3;
    #pragma unroll
    for (int mt = 0; mt < 2; mt++) {
        float p0 = 0.f, p1 = 0.f;
        #pragma unroll
        for (int nt = 0; nt < 8; nt++) {
            int lc = wx*64 + nt*8 + 2*t4;
            p0 += fmaxf(c[mt][nt][0] + b1s[lc],   0.f)*w2s[lc]
                + fmaxf(c[mt][nt][1] + b1s[lc+1], 0.f)*w2s[lc+1];
            p1 += fmaxf(c[mt][nt][2] + b1s[lc],   0.f)*w2s[lc]
                + fmaxf(c[mt][nt][3] + b1s[lc+1], 0.f)*w2s[lc+1];
        }
        p0 += __shfl_xor_sync(0xffffffffu, p0, 1);
        p0 += __shfl_xor_sync(0xffffffffu, p0, 2);
        p1 += __shfl_xor_sync(0xffffffffu, p1, 1);
        p1 += __shfl_xor_sync(0xffffffffu, p1, 2);
        if (t4 == 0) {
            atomicAdd(&g_scores[m0 + wy*32 + mt*16 + g],     p0);
            atomicAdd(&g_scores[m0 + wy*32 + mt*16 + 8 + g], p1);
        }
    }
}

// ---------------- h1 HMMA kernel (fp16 products from g_spansh) ----------------
__global__ void __launch_bounds__(256)
h1_mma_kernel(const float* __restrict__ pb1)
{
    extern __shared__ __align__(16) char dsm8[];
    __half* dsm = (__half*)dsm8;
    unsigned sb = smem_u32(dsm8);

    int tid = threadIdx.x, lane = tid & 31, wid = tid >> 5;
    int wy = wid & 3, wx = wid >> 2;
    int m0 = blockIdx.y*128, n0 = blockIdx.x*128;

    int lrow = tid >> 1, lks = (tid & 1)*16;
    int lgrow = m0 + lrow;
    int lii = (lgrow >> 4) & 15, ljj = lgrow & 15, lsv = lgrow >> 8;
    const __half* pa  = g_spansh + (long)((lsv >> 3)*MS + lii)*KPAD1;
    const __half* pbs = g_spansh + (long)((lsv & 7)*MS + ljj)*KPAD1;
    const __half* bsrc = g_B1 + (long)(n0 + lrow)*KPAD1;
    unsigned srow = (unsigned)(lrow*TROW + lks)*2;

    float c[2][8][4];
    #pragma unroll
    for (int i = 0; i < 2; i++)
        #pragma unroll
        for (int j = 0; j < 8; j++)
            #pragma unroll
            for (int e = 0; e < 4; e++) c[i][j][e] = 0.f;

    // prologue: stage 0
    {
        CP_ASYNC16(sb + 2*MATB + srow,      bsrc + lks);
        CP_ASYNC16(sb + 2*MATB + srow + 16, bsrc + lks + 8);
        CP_COMMIT();
        union { uint4 q; __half2 h2[4]; } xa0, xa1, xb0, xb1, r0, r1;
        xa0.q = *(const uint4*)(pa + lks);     xa1.q = *(const uint4*)(pa + lks + 8);
        xb0.q = *(const uint4*)(pbs + lks);    xb1.q = *(const uint4*)(pbs + lks + 8);
        #pragma unroll
        for (int e = 0; e < 4; e++) {
            r0.h2[e] = __hmul2(xa0.h2[e], xb0.h2[e]);
            r1.h2[e] = __hmul2(xa1.h2[e], xb1.h2[e]);
        }
        *(uint4*)&dsm[0*MATE + lrow*TROW + lks]     = r0.q;
        *(uint4*)&dsm[0*MATE + lrow*TROW + lks + 8] = r1.q;
        CP_WAIT0();
    }
    __syncthreads();

    for (int t = 0; t < NT1; t++) {
        int cur = t & 1, nxt = cur ^ 1;
        bool more = (t + 1 < NT1);

        if (more) {
            int kk = (t+1)*32 + lks;
            CP_ASYNC16(sb + (2+nxt)*MATB + srow,      bsrc + kk);
            CP_ASYNC16(sb + (2+nxt)*MATB + srow + 16, bsrc + kk + 8);
            CP_COMMIT();
        }

        unsigned sbA = sb + cur*MATB, sbB = sb + (2+cur)*MATB;
        #pragma unroll
        for (int kt = 0; kt < 2; kt++) {
            unsigned a[2][4], b[4][4];
            int arow = lane & 15, acol = (lane >> 4)*8;
            #pragma unroll
            for (int mt = 0; mt < 2; mt++) {
                unsigned off = (unsigned)(((wy*32 + mt*16 + arow)*TROW + kt*16 + acol)*2);
                ldsm_x4(a[mt][0], a[mt][1], a[mt][2], a[mt][3], sbA + off);
            }
            int nrow = (lane & 7) + ((lane >> 4) << 3), kc = lane & 8;
            #pragma unroll
            for (int np = 0; np < 4; np++) {
                unsigned off = (unsigned)(((wx*64 + np*16 + nrow)*TROW + kt*16 + kc)*2);
                ldsm_x4(b[np][0], b[np][1], b[np][2], b[np][3], sbB + off);
            }
            #pragma unroll
            for (int mt = 0; mt < 2; mt++)
                #pragma unroll
                for (int nt = 0; nt < 8; nt++) {
                    int np = nt >> 1, h = (nt & 1)*2;
                    mma_f16(c[mt][nt], a[mt], b[np][h], b[np][h+1]);
                }
        }

        if (more) {
            int kk = (t+1)*32 + lks;
            union { uint4 q; __half2 h2[4]; } xa0, xa1, xb0, xb1, r0, r1;
            xa0.q = *(const uint4*)(pa + kk);     xa1.q = *(const uint4*)(pa + kk + 8);
            xb0.q = *(const uint4*)(pbs + kk);    xb1.q = *(const uint4*)(pbs + kk + 8);
            #pragma unroll
            for (int e = 0; e < 4; e++) {
                r0.h2[e] = __hmul2(xa0.h2[e], xb0.h2[e]);
                r1.h2[e] = __hmul2(xa1.h2[e], xb1.h2[e]);
            }
            *(uint4*)&dsm[nxt*MATE + lrow*TROW + lks]     = r0.q;
            *(uint4*)&dsm[nxt*MATE + lrow*TROW + lks + 8] = r1.q;
        }
        CP_WAIT0();
        __syncthreads();
    }

    // epilogue: +bias +a +b, relu, store fp16
    int g = lane >> 2, t4 = lane & 3;
    #pragma unroll
    for (int mt = 0; mt < 2; mt++) {
        #pragma unroll
        for (int rr = 0; rr < 2; rr++) {
            int grow = m0 + wy*32 + mt*16 + rr*8 + g;
            int ii = (grow >> 4) & 15, jj = grow & 15, sv = grow >> 8;
            int rA = (sv >> 3)*MS + ii, rB = (sv & 7)*MS + jj;
            #pragma unroll
            for (int nt = 0; nt < 8; nt++) {
                int col = n0 + wx*64 + nt*8 + 2*t4;
                float v0 = c[mt][nt][rr*2+0] + pb1[col]
                         + g_a[rA*HH + col] + g_b[rB*HH + col];
                float v1 = c[mt][nt][rr*2+1] + pb1[col+1]
                         + g_a[rA*HH + col+1] + g_b[rB*HH + col+1];
                v0 = fmaxf(v0, 0.f); v1 = fmaxf(v1, 0.f);
                unsigned short h0 = __half_as_ushort(__float2half_rn(v0));
                unsigned short h1 = __half_as_ushort(__float2half_rn(v1));
                *(unsigned*)&g_h1[(long)grow*HH + col] = (unsigned)h0 | ((unsigned)h1 << 16);
            }
        }
    }
}

// ---------------- h2 HMMA kernel (unchanged from R12) ----------------
__global__ void __launch_bounds__(256)
h2_mma_kernel(const float* __restrict__ pb2, const float* __restrict__ pw3)
{
    extern __shared__ __align__(16) char dsm8[];
    unsigned sb = smem_u32(dsm8);
    __shared__ float w3s[128], pb2s[128];

    int tid = threadIdx.x, lane = tid & 31, wid = tid >> 5;
    int wy = wid & 3, wx = wid >> 2;
    int m0 = blockIdx.y*128, n0 = blockIdx.x*128;

    if (tid < 128) { w3s[tid] = pw3[n0 + tid]; pb2s[tid] = pb2[n0 + tid]; }

    int lrow = tid >> 1, lks = (tid & 1)*16;
    const __half* asrc = g_h1 + (long)(m0 + lrow)*HH;
    const __half* bsrc = g_W2 + (long)(n0 + lrow)*KPAD2;
    unsigned srow = (unsigned)(lrow*TROW + lks)*2;

    float c[2][8][4];
    #pragma unroll
    for (int i = 0; i < 2; i++)
        #pragma unroll
        for (int j = 0; j < 8; j++)
            #pragma unroll
            for (int e = 0; e < 4; e++) c[i][j][e] = 0.f;

    {
        CP_ASYNC16(sb + 0*MATB + srow,      asrc + lks);
        CP_ASYNC16(sb + 0*MATB + srow + 16, asrc + lks + 8);
        CP_ASYNC16(sb + 2*MATB + srow,      bsrc + lks);
        CP_ASYNC16(sb + 2*MATB + srow + 16, bsrc + lks + 8);
        CP_COMMIT(); CP_WAIT0();
    }
    __syncthreads();

    for (int t = 0; t < NT2; t++) {
        int cur = t & 1, nxt = cur ^ 1;
        bool more = (t + 1 < NT2);

        if (more) {
            int kk = (t+1)*32 + lks;
            CP_ASYNC16(sb + nxt*MATB + srow,          asrc + kk);
            CP_ASYNC16(sb + nxt*MATB + srow + 16,     asrc + kk + 8);
            CP_ASYNC16(sb + (2+nxt)*MATB + srow,      bsrc + kk);
            CP_ASYNC16(sb + (2+nxt)*MATB + srow + 16, bsrc + kk + 8);
            CP_COMMIT();
        }

        unsigned sbA = sb + cur*MATB, sbB = sb + (2+cur)*MATB;
        #pragma unroll
        for (int kt = 0; kt < 2; kt++) {
            unsigned a[2][4], b[4][4];
            int arow = lane & 15, acol = (lane >> 4)*8;
            #pragma unroll
            for (int mt = 0; mt < 2; mt++) {
                unsigned off = (unsigned)(((wy*32 + mt*16 + arow)*TROW + kt*16 + acol)*2);
                ldsm_x4(a[mt][0], a[mt][1], a[mt][2], a[mt][3], sbA + off);
            }
            int nrow = (lane & 7) + ((lane >> 4) << 3), kc = lane & 8;
            #pragma unroll
            for (int np = 0; np < 4; np++) {
                unsigned off = (unsigned)(((wx*64 + np*16 + nrow)*TROW + kt*16 + kc)*2);
                ldsm_x4(b[np][0], b[np][1], b[np][2], b[np][3], sbB + off);
            }
            #pragma unroll
            for (int mt = 0; mt < 2; mt++)
                #pragma unroll
                for (int nt = 0; nt < 8; nt++) {
                    int np = nt >> 1, h = (nt & 1)*2;
                    mma_f16(c[mt][nt], a[mt], b[np][h], b[np][h+1]);
                }
        }
        CP_WAIT0();
        __syncthreads();
    }

    int g = lane >> 2, t4 = lane & 3;
    #pragma unroll
    for (int mt = 0; mt < 2; mt++) {
        float p0 = 0.f, p1 = 0.f;
        #pragma unroll
        for (int nt = 0; nt < 8; nt++) {
            int lc = wx*64 + nt*8 + 2*t4;
            p0 += fmaxf(c[mt][nt][0] + pb2s[lc],   0.f)*w3s[lc]
                + fmaxf(c[mt][nt][1] + pb2s[lc+1], 0.f)*w3s[lc+1];
            p1 += fmaxf(c[mt][nt][2] + pb2s[lc],   0.f)*w3s[lc]
                + fmaxf(c[mt][nt][3] + pb2s[lc+1], 0.f)*w3s[lc+1];
        }
        p0 += __shfl_xor_sync(0xffffffffu, p0, 1);
        p0 += __shfl_xor_sync(0xffffffffu, p0, 2);
        p1 += __shfl_xor_sync(0xffffffffu, p1, 1);
        p1 += __shfl_xor_sync(0xffffffffu, p1, 2);
        if (t4 == 0) {
            atomicAdd(&g_ts[m0 + wy*32 + mt*16 + g],     p0);
            atomicAdd(&g_ts[m0 + wy*32 + mt*16 + 8 + g], p1);
        }
    }
}

// ---------------- split-K fp32 GEMM computing g_a and g_b (unchanged) ----------------
#define BM 128
#define BN 128
#define BK 16
#define TM 8
#define TN 8
#define KS 8
#define KSLC 292

__global__ __launch_bounds__(256, 2)
void gemm_ab_kernel(const float* __restrict__ pw1)
{
    __shared__ __align__(16) float2 As2[BK][BM];
    __shared__ __align__(16) float  Bs[BK][BN];

    int tid = threadIdx.x;
    {   // zero g_a/g_b for the atomics (moved here from span_gemm)
        float4 z = make_float4(0.f,0.f,0.f,0.f);
        if (blockIdx.y == 0) {
            int gt = blockIdx.x*256 + tid;        // 16 blocks * 256 = 4096 threads
            for (int i = gt; i < NSPAN*HH/4; i += 16*256) {
                ((float4*)g_a)[i] = z;
                ((float4*)g_b)[i] = z;
            }
        }
    }
    // grid-sync-free: blockIdx.y==0 blocks zero BEFORE accumulating their own partials?
    // NOT safe across blocks; instead all blocks use atomicAdd and zeroing is done in prep-stage
    // (see note below: zeroing actually happens in assemble grid, which runs before this kernel)

    int n0 = blockIdx.x * BN;
    int kstart = blockIdx.y * KSLC;
    int kend = min(kstart + KSLC, SD);

    const float* Bsel = (n0 < HH) ? pw1 + n0 : pw1 + (long)SD*HH + (n0 - HH);
    float* Cout = (n0 < HH) ? g_a + n0 : g_b + (n0 - HH);

    int la_row = tid >> 1, la_cb = (tid & 1) * 8;
    int lb_row = tid >> 4, lb_col = (tid & 15) * 8;

    unsigned long long acc2[TM][TN/2];
    #pragma unroll
    for (int i = 0; i < TM; i++)
        #pragma unroll
        for (int j = 0; j < TN/2; j++) acc2[i][j] = 0ull;

    int tx = tid & 15, ty = tid >> 4;

    for (int k0 = kstart; k0 < kend; k0 += BK) {
        #pragma unroll
        for (int c = 0; c < 2; c++) {
            int k = k0 + la_cb + c*4;
            float4 v = make_float4(0.f,0.f,0.f,0.f);
            if (k < kend) v = *(const float4*)(g_spans + (long)la_row*SD + k);
            int kc = la_cb + c*4;
            As2[kc+0][la_row] = make_float2(v.x, v.x);
            As2[kc+1][la_row] = make_float2(v.y, v.y);
            As2[kc+2][la_row] = make_float2(v.z, v.z);
            As2[kc+3][la_row] = make_float2(v.w, v.w);
            int kb = k0 + lb_row;
            float4 w = make_float4(0.f,0.f,0.f,0.f);
            if (kb < kend) w = *(const float4*)(Bsel + (long)kb*HH + lb_col + c*4);
            *(float4*)&Bs[lb_row][lb_col + c*4] = w;
        }
        __syncthreads();
        #pragma unroll
        for (int kk = 0; kk < BK; kk++) {
            unsigned long long rm2[TM], rb2[TN/2];
            #pragma unroll
            for (int i = 0; i < TM; i += 2) {
                ulonglong2 v = *(const ulonglong2*)&As2[kk][ty*TM + i];
                rm2[i] = v.x; rm2[i+1] = v.y;
            }
            #pragma unroll
            for (int j = 0; j < TN/2; j += 2) {
                ulonglong2 v = *(const ulonglong2*)&Bs[kk][tx*TN + 2*j];
                rb2[j] = v.x; rb2[j+1] = v.y;
            }
            #pragma unroll
            for (int i = 0; i < TM; i++)
                #pragma unroll
                for (int j = 0; j < TN/2; j++)
                    FMA2(acc2[i][j], rm2[i], rb2[j]);
        }
        __syncthreads();
    }

    #pragma unroll
    for (int i = 0; i < TM; i++) {
        int row = ty*TM + i;
        #pragma unroll
        for (int j = 0; j < TN/2; j++) {
            int col = tx*TN + 2*j;
            float v0 = __uint_as_float((unsigned)(acc2[i][j] & 0xffffffffull));
            float v1 = __uint_as_float((unsigned)(acc2[i][j] >> 32));
            atomicAdd(Cout + (long)row*HH + col,     v0);
            atomicAdd(Cout + (long)row*HH + col + 1, v1);
        }
    }
}

// ---------------- span softmax + assemble spans (fp32 + fp16 copies; zeroes g_a/g_b) ----------------
__global__ void assemble_kernel(const float* __restrict__ se, const float* __restrict__ cont,
                                const int* __restrict__ width, const float* __restrict__ wemb)
{
    int b = blockIdx.x;
    int tid = threadIdx.x;
    __shared__ float attn[WW];
    int w = width[b];
    // zero g_a/g_b (runs before gemm_ab; 128 blocks x 256 threads)
    {
        float4 z = make_float4(0.f,0.f,0.f,0.f);
        int gt = b*256 + tid;
        for (int i = gt; i < NSPAN*HH/4; i += 128*256) {
            ((float4*)g_a)[i] = z;
            ((float4*)g_b)[i] = z;
        }
    }
    if (tid == 0) {
        float sc[WW]; float mx = -INFINITY;
        for (int t = 0; t < WW; t++) {
            sc[t] = (t < w) ? g_scores[b*WW + t] : NEGV;
            mx = fmaxf(mx, sc[t]);
        }
        float sum = 0.f;
        for (int t = 0; t < WW; t++) { sc[t] = expf(sc[t] - mx); sum += sc[t]; }
        for (int t = 0; t < WW; t++) attn[t] = sc[t]/sum;
    }
    __syncthreads();
    float* row = g_spans + (long)b*SD;
    for (int k = tid; k < 2*BH; k += 256) row[k] = se[(long)b*2*BH + k];
    for (int d = tid; d < BH; d += 256) {
        float acc = 0.f;
        #pragma unroll
        for (int t = 0; t < WW; t++) acc += attn[t]*cont[((long)b*WW + t)*BH + d];
        row[2*BH + d] = acc;
    }
    if (tid < ED) row[2*BH + BH + tid] = wemb[min(w,4)*ED + tid];
    __syncthreads();
    // fp16 copy with zero padding to KPAD1
    __half* rh = g_spansh + (long)b*KPAD1;
    for (int k = tid; k < KPAD1; k += 256)
        rh[k] = __float2half_rn((k < SD) ? row[k] : 0.f);
}

// ---------------- grounding: att[s,v,i,j] = doc[s,i,:]·img[v,j,:] ----------------
__global__ void att_kernel(const float* __restrict__ doc, const float* __restrict__ img)
{
    int b = blockIdx.x, s = b >> 3, v = b & 7;
    for (int idx = threadIdx.x; idx < FF*RR; idx += blockDim.x) {
        int i = idx / RR, j = idx % RR;
        const float4* dr = (const float4*)(doc + (long)(s*FF + i)*DD);
        const float4* ir = (const float4*)(img + (long)(v*RR + j)*DD);
        float acc = 0.f;
        #pragma unroll 8
        for (int c = 0; c < DD/4; c++) {
            float4 x = dr[c], y = ir[c];
            acc += x.x*y.x + x.y*y.y + x.z*y.z + x.w*y.w;
        }
        g_att[((long)b*FF + i)*RR + j] = acc;
    }
}

// ---------------- grounding reduce -> S_g ----------------
__global__ void ground_reduce(const float* __restrict__ tm, const float* __restrict__ im)
{
    __shared__ float sh[FF][RR+1];
    __shared__ float stm[FF], sim[RR];
    __shared__ float red[FF];
    int b = blockIdx.x, s = b >> 3, v = b & 7;
    int tid = threadIdx.x; // 64
    if (tid < FF) stm[tid] = tm[s*FF + tid];
    if (tid < RR) sim[tid] = im[v*RR + tid];
    __syncthreads();
    for (int idx = tid; idx < FF*RR; idx += 64) {
        int i = idx / RR, j = idx % RR;
        float a = g_att[((long)b*FF + i)*RR + j];
        float m = stm[i]*sim[j];
        a *= m;
        if (a == 0.f) a = NEGV;
        sh[i][j] = a;
    }
    __syncthreads();
    float part = 0.f;
    {
        int i = tid;
        float mx = -INFINITY;
        for (int j = 0; j < RR; j++) mx = fmaxf(mx, sh[i][j]*sim[j]);
        float ssum = 0.f;
        for (int j = 0; j < RR; j++) ssum += expf(sh[i][j]*sim[j] - mx);
        for (int j = 0; j < RR; j++) {
            float aw = expf(sh[i][j]*sim[j] - mx)/ssum * stm[i]*sim[j];
            part += aw * sh[i][j];
        }
    }
    if (tid < RR) {
        int j = tid;
        float mx = -INFINITY;
        for (int i = 0; i < FF; i++) mx = fmaxf(mx, sh[i][j]);
        float ssum = 0.f;
        for (int i = 0; i < FF; i++) ssum += expf(sh[i][j] - mx);
        for (int i = 0; i < FF; i++) {
            float aw = expf(sh[i][j] - mx)/ssum * stm[i]*sim[j];
            part += aw * sh[i][j];
        }
    }
    red[tid] = part;
    __syncthreads();
    for (int o = 32; o > 0; o >>= 1) {
        if (tid < o) red[tid] += red[tid+o];
        __syncthreads();
    }
    if (tid == 0) g_Sg[b] = red[0];
}

// ---------------- adaptive S_c ----------------
__global__ void sc_kernel(const float* __restrict__ m1)
{
    int b = blockIdx.x, s = b >> 3, v = b & 7;
    const float* T = g_ts + (long)b*MS*MS;
    int lane = threadIdx.x;
    float cs = 0.f, cv = 0.f;
    for (int k = 0; k < MS; k++) { cs += m1[s*MS+k]; cv += m1[v*MS+k]; }
    float max1 = -INFINITY, max2 = -INFINITY;
    if (lane < MS) {
        float rm = 0.f;
        for (int j = 0; j < MS; j++) rm += T[lane*MS+j]*m1[v*MS+j];
        rm /= cv;
        if (m1[s*MS+lane] > 0.f) max1 = rm;
        float cm = 0.f;
        for (int i = 0; i < MS; i++) cm += T[i*MS+lane]*m1[s*MS+i];
        cm /= cs;
        if (m1[v*MS+lane] > 0.f) max2 = cm;
    }
    for (int o = 16; o > 0; o >>= 1) {
        max1 = fmaxf(max1, __shfl_xor_sync(0xffffffffu, max1, o));
        max2 = fmaxf(max2, __shfl_xor_sync(0xffffffffu, max2, o));
    }
    if (lane == 0) g_Sc[b] = 0.5f*(max1 + max2);
}

// ---------------- final loss ----------------
__global__ void loss_kernel(float* __restrict__ out)
{
    if (threadIdx.x != 0) return;
    float mg[8][8], mgT[8][8], mc[8][8];
    for (int s = 0; s < 8; s++) {
        float mx = -INFINITY;
        for (int v = 0; v < 8; v++) mx = fmaxf(mx, g_Sg[s*8+v]);
        float sum = 0.f;
        for (int v = 0; v < 8; v++) { mg[s][v] = expf(g_Sg[s*8+v]-mx); sum += mg[s][v]; }
        for (int v = 0; v < 8; v++) mg[s][v] /= sum;
    }
    for (int v = 0; v < 8; v++) {
        float mx = -INFINITY;
        for (int s = 0; s < 8; s++) mx = fmaxf(mx, g_Sg[s*8+v]);
        float sum = 0.f;
        for (int s = 0; s < 8; s++) { mgT[v][s] = expf(g_Sg[s*8+v]-mx); sum += mgT[v][s]; }
        for (int s = 0; s < 8; s++) mgT[v][s] /= sum;
    }
    for (int s = 0; s < 8; s++) {
        float mx = -INFINITY;
        for (int v = 0; v < 8; v++) mx = fmaxf(mx, g_Sc[s*8+v]);
        float sum = 0.f;
        for (int v = 0; v < 8; v++) { mc[s][v] = expf(g_Sc[s*8+v]-mx); sum += mc[s][v]; }
        for (int v = 0; v < 8; v++) mc[s][v] /= sum;
    }
    float loss = 0.f;
    for (int s = 0; s < 8; s++) {
        float t = 0.f;
        for (int v = 0; v < 8; v++) t += mg[s][v]*mc[s][v];
        loss += logf(t);
    }
    for (int v = 0; v < 8; v++) {
        float t = 0.f;
        for (int s = 0; s < 8; s++) t += mgT[v][s]*mc[v][s];
        loss += logf(t);
    }
    out[0] = -loss/(float)ND;
}

// ---------------- host ----------------
extern "C" void kernel_launch(void* const* d_in, const int* in_sizes, int n_in,
                              void* d_out, int out_size)
{
    const float* doc  = (const float*)d_in[0];
    const float* img  = (const float*)d_in[1];
    const float* tm   = (const float*)d_in[2];
    const float* im   = (const float*)d_in[3];
    const float* se   = (const float*)d_in[4];
    const float* cont = (const float*)d_in[5];
    const int*   width= (const int*)  d_in[6];
    const float* m1   = (const float*)d_in[7];
    const float* aw1  = (const float*)d_in[8];
    const float* ab1  = (const float*)d_in[9];
    const float* aw2  = (const float*)d_in[10];
    const float* ab2  = (const float*)d_in[11];
    const float* wemb = (const float*)d_in[12];
    const float* pw1  = (const float*)d_in[13];
    const float* pb1  = (const float*)d_in[14];
    const float* pw2  = (const float*)d_in[15];
    const float* pb2  = (const float*)d_in[16];
    const float* pw3  = (const float*)d_in[17];
    const float* pb3  = (const float*)d_in[18];

    cudaFuncSetAttribute(span_mma_kernel, cudaFuncAttributeMaxDynamicSharedMemorySize, DSMEM_MMA);
    cudaFuncSetAttribute(h1_mma_kernel, cudaFuncAttributeMaxDynamicSharedMemorySize, DSMEM_MMA);
    cudaFuncSetAttribute(h2_mma_kernel, cudaFuncAttributeMaxDynamicSharedMemorySize, DSMEM_MMA);

    // (1) weights -> fp16; init g_ts, g_scores
    int prep_total = PREP_G1 + PREP_G2 + PREP_G3 + NPAIR + 1280;
    prep_kernel<<<(prep_total + 255)/256, 256>>>(pw1, pw2, aw1, pb3, ab2);
    // (2) scores += relu(cont@W1T + b1).aw2  [fp16 HMMA, fused matvec]
    span_mma_kernel<<<dim3(HH/128, 1280/128), 256, DSMEM_MMA>>>(cont, ab1, aw2);
    // (3) assemble spans (fp32 + fp16, zero g_a/g_b)
    assemble_kernel<<<NSPAN, 256>>>(se, cont, width, wemb);
    // (4) a,b = spans @ w1 halves (split-K fp32)
    gemm_ab_kernel<<<dim3(2048/BN, KS), 256>>>(pw1);
    // (5) h1 = relu(prod @ W1c + a + b + b1)  [fp16 HMMA, fp16 products]
    h1_mma_kernel<<<dim3(8, 128), 256, DSMEM_MMA>>>(pb1);
    // (6) ts += relu(h1 @ W2 + b2) @ w3  [fp16 HMMA, fused]
    h2_mma_kernel<<<dim3(8, 128), 256, DSMEM_MMA>>>(pb2, pw3);

    // grounding (independent)
    att_kernel<<<64, 256>>>(doc, img);
    ground_reduce<<<64, 64>>>(tm, im);

    // adaptive S_c + final loss
    sc_kernel<<<64, 32>>>(m1);
    loss_kernel<<<1, 32>>>((float*)d_out);
}

// round 14
// speedup vs baseline: 1.8883x; 1.0367x over previous
#include <cuda_runtime.h>
#include <cuda_bf16.h>
#include <cuda_fp16.h>
#include <math.h>
#include <stdint.h>

// ---------------- problem constants ----------------
#define ND   8
#define FF   64
#define RR   36
#define DD   1024
#define MS   16
#define WW   10
#define BH   768
#define HH   1024
#define ED   20
#define SD   2324
#define NSPAN (ND*MS)          // 128
#define NPAIR (NSPAN*NSPAN)    // 16384
#define NEGV (-1e10f)

#define KPAD1 2368             // 74 * 32
#define KPAD2 1024             // 32 * 32
#define KSP   768              // span GEMM K
#define NT1   (KPAD1/32)
#define NT2   (KPAD2/32)
#define NTS   (KSP/32)

// ---------------- scratch ----------------
__device__ __align__(16) float g_scores[1280];
__device__ __align__(16) float g_spans[NSPAN*SD + 64];
__device__ __align__(16) __half g_spansh[NSPAN*KPAD1];  // fp16 spans, zero-padded
__device__ __align__(16) float g_a[NSPAN*HH];
__device__ __align__(16) float g_b[NSPAN*HH];
__device__ __align__(16) __half g_B1[HH*KPAD1];         // [n][k] = fp16(pw1[2SD+k][n])
__device__ __align__(16) __half g_W2[HH*KPAD2];         // [n][k] = fp16(pw2[k][n])
__device__ __align__(16) __half g_W1T[HH*KSP];          // [n][k] = fp16(aw1[k][n])
__device__ __align__(16) __half g_prod[(long)NPAIR*KPAD1]; // fp16 pair products
__device__ __align__(16) __half g_h1[(long)NPAIR*HH];
__device__ __align__(16) float g_ts[NPAIR];
__device__ __align__(16) float g_att[64*FF*RR];
__device__ float g_Sg[64];
__device__ float g_Sc[64];

#define FMA2(d,a,b) asm("fma.rn.f32x2 %0, %1, %2, %0;" : "+l"(d) : "l"(a), "l"(b))

// ---------------- warp MMA helpers ----------------
__device__ __forceinline__ unsigned smem_u32(const void* p) {
    unsigned a;
    asm("{ .reg .u64 t; cvta.to.shared.u64 t, %1; cvt.u32.u64 %0, t; }" : "=r"(a) : "l"(p));
    return a;
}
__device__ __forceinline__ void ldsm_x4(unsigned& r0, unsigned& r1, unsigned& r2, unsigned& r3,
                                        unsigned addr) {
    asm volatile("ldmatrix.sync.aligned.m8n8.x4.shared.b16 {%0,%1,%2,%3}, [%4];"
                 : "=r"(r0), "=r"(r1), "=r"(r2), "=r"(r3) : "r"(addr));
}
__device__ __forceinline__ void mma_f16(float (&c)[4], const unsigned (&a)[4],
                                        unsigned b0, unsigned b1) {
    asm volatile(
        "mma.sync.aligned.m16n8k16.row.col.f32.f16.f16.f32 "
        "{%0,%1,%2,%3}, {%4,%5,%6,%7}, {%8,%9}, {%0,%1,%2,%3};"
        : "+f"(c[0]), "+f"(c[1]), "+f"(c[2]), "+f"(c[3])
        : "r"(a[0]), "r"(a[1]), "r"(a[2]), "r"(a[3]), "r"(b0), "r"(b1));
}
#define CP_ASYNC16(saddr, gptr) \
    asm volatile("cp.async.cg.shared.global [%0], [%1], 16;" :: "r"(saddr), "l"(gptr) : "memory")
#define CP_COMMIT() asm volatile("cp.async.commit_group;" ::: "memory")
#define CP_WAIT0()  asm volatile("cp.async.wait_group 0;" ::: "memory")

#define TROW 40
#define MATB 10240
#define MATE (128*TROW)
#define DSMEM_MMA (4*MATB)          // 40960

// ---------------- prep: weights -> fp16 [n][k]; init g_ts, g_scores ----------------
#define PREP_G1 (HH*(KPAD1/8))
#define PREP_G2 (HH*(KPAD2/8))
#define PREP_G3 (HH*(KSP/8))
__global__ void prep_kernel(const float* __restrict__ pw1, const float* __restrict__ pw2,
                            const float* __restrict__ aw1, const float* __restrict__ pb3,
                            const float* __restrict__ ab2)
{
    int gid = blockIdx.x*256 + threadIdx.x;
    if (gid < PREP_G1) {
        int n = gid % HH, kg = gid / HH;
        union { uint4 q; unsigned short us[8]; } H;
        #pragma unroll
        for (int e = 0; e < 8; e++) {
            int k = kg*8 + e;
            float v = (k < SD) ? pw1[((long)(2*SD + k))*HH + n] : 0.f;
            H.us[e] = __half_as_ushort(__float2half_rn(v));
        }
        *(uint4*)(g_B1 + (long)n*KPAD1 + kg*8) = H.q;
    } else if (gid < PREP_G1 + PREP_G2) {
        int j = gid - PREP_G1;
        int n = j % HH, kg = j / HH;
        union { uint4 q; unsigned short us[8]; } H;
        #pragma unroll
        for (int e = 0; e < 8; e++) {
            int k = kg*8 + e;
            H.us[e] = __half_as_ushort(__float2half_rn(pw2[(long)k*HH + n]));
        }
        *(uint4*)(g_W2 + (long)n*KPAD2 + kg*8) = H.q;
    } else if (gid < PREP_G1 + PREP_G2 + PREP_G3) {
        int j = gid - PREP_G1 - PREP_G2;
        int n = j % HH, kg = j / HH;
        union { uint4 q; unsigned short us[8]; } H;
        #pragma unroll
        for (int e = 0; e < 8; e++) {
            int k = kg*8 + e;
            H.us[e] = __half_as_ushort(__float2half_rn(aw1[(long)k*HH + n]));
        }
        *(uint4*)(g_W1T + (long)n*KSP + kg*8) = H.q;
    } else {
        int i = gid - PREP_G1 - PREP_G2 - PREP_G3;
        if (i < NPAIR) g_ts[i] = pb3[0];
        else if (i < NPAIR + 1280) g_scores[i - NPAIR] = ab2[0];
    }
}

// ---------------- prodgen: g_prod[row,k] = spansh[rA,k]*spansh[rB,k] ----------------
#define PRODG ((long)NPAIR*(KPAD1/8))      // 4,849,664 uint4 stores
__global__ void prodgen_kernel()
{
    long gid = (long)blockIdx.x*256 + threadIdx.x;
    if (gid >= PRODG) return;
    int row = (int)(gid / (KPAD1/8));
    int kg  = (int)(gid % (KPAD1/8));
    int ii = (row >> 4) & 15, jj = row & 15, sv = row >> 8;
    int rA = (sv >> 3)*MS + ii, rB = (sv & 7)*MS + jj;
    union { uint4 q; __half2 h2[4]; } xa, xb, r;
    xa.q = *(const uint4*)(g_spansh + (long)rA*KPAD1 + kg*8);
    xb.q = *(const uint4*)(g_spansh + (long)rB*KPAD1 + kg*8);
    #pragma unroll
    for (int e = 0; e < 4; e++) r.h2[e] = __hmul2(xa.h2[e], xb.h2[e]);
    *(uint4*)(g_prod + (long)row*KPAD1 + kg*8) = r.q;
}

// ---------------- generic fp16 HMMA mainloop body (all-cp.async, double-buffered) ----------------
// (expanded inline in each kernel for NCU attribution)

// ---------------- span HMMA kernel: scores += relu(cont@W1T + b1) . aw2 ----------------
__global__ void __launch_bounds__(256)
span_mma_kernel(const float* __restrict__ cont, const float* __restrict__ ab1,
                const float* __restrict__ aw2)
{
    extern __shared__ __align__(16) char dsm8[];
    __half* dsm = (__half*)dsm8;
    unsigned sb = smem_u32(dsm8);
    __shared__ float w2s[128], b1s[128];

    int tid = threadIdx.x, lane = tid & 31, wid = tid >> 5;
    int wy = wid & 3, wx = wid >> 2;
    int m0 = blockIdx.y*128, n0 = blockIdx.x*128;

    if (tid < 128) { w2s[tid] = aw2[n0 + tid]; b1s[tid] = ab1[n0 + tid]; }

    int lrow = tid >> 1, lks = (tid & 1)*16;
    const float* asrc = cont + (long)(m0 + lrow)*KSP;
    const __half* bsrc = g_W1T + (long)(n0 + lrow)*KSP;
    unsigned srow = (unsigned)(lrow*TROW + lks)*2;

    float c[2][8][4];
    #pragma unroll
    for (int i = 0; i < 2; i++)
        #pragma unroll
        for (int j = 0; j < 8; j++)
            #pragma unroll
            for (int e = 0; e < 4; e++) c[i][j][e] = 0.f;

    {
        CP_ASYNC16(sb + 2*MATB + srow,      bsrc + lks);
        CP_ASYNC16(sb + 2*MATB + srow + 16, bsrc + lks + 8);
        CP_COMMIT();
        union { uint4 q[2]; unsigned short us[16]; } H;
        #pragma unroll
        for (int q = 0; q < 4; q++) {
            float4 x = *(const float4*)(asrc + lks + q*4);
            H.us[q*4+0] = __half_as_ushort(__float2half_rn(x.x));
            H.us[q*4+1] = __half_as_ushort(__float2half_rn(x.y));
            H.us[q*4+2] = __half_as_ushort(__float2half_rn(x.z));
            H.us[q*4+3] = __half_as_ushort(__float2half_rn(x.w));
        }
        *(uint4*)&dsm[0*MATE + lrow*TROW + lks]     = H.q[0];
        *(uint4*)&dsm[0*MATE + lrow*TROW + lks + 8] = H.q[1];
        CP_WAIT0();
    }
    __syncthreads();

    for (int t = 0; t < NTS; t++) {
        int cur = t & 1, nxt = cur ^ 1;
        bool more = (t + 1 < NTS);

        if (more) {
            int kk = (t+1)*32 + lks;
            CP_ASYNC16(sb + (2+nxt)*MATB + srow,      bsrc + kk);
            CP_ASYNC16(sb + (2+nxt)*MATB + srow + 16, bsrc + kk + 8);
            CP_COMMIT();
        }

        unsigned sbA = sb + cur*MATB, sbB = sb + (2+cur)*MATB;
        #pragma unroll
        for (int kt = 0; kt < 2; kt++) {
            unsigned a[2][4], b[4][4];
            int arow = lane & 15, acol = (lane >> 4)*8;
            #pragma unroll
            for (int mt = 0; mt < 2; mt++) {
                unsigned off = (unsigned)(((wy*32 + mt*16 + arow)*TROW + kt*16 + acol)*2);
                ldsm_x4(a[mt][0], a[mt][1], a[mt][2], a[mt][3], sbA + off);
            }
            int nrow = (lane & 7) + ((lane >> 4) << 3), kc = lane & 8;
            #pragma unroll
            for (int np = 0; np < 4; np++) {
                unsigned off = (unsigned)(((wx*64 + np*16 + nrow)*TROW + kt*16 + kc)*2);
                ldsm_x4(b[np][0], b[np][1], b[np][2], b[np][3], sbB + off);
            }
            #pragma unroll
            for (int mt = 0; mt < 2; mt++)
                #pragma unroll
                for (int nt = 0; nt < 8; nt++) {
                    int np = nt >> 1, h = (nt & 1)*2;
                    mma_f16(c[mt][nt], a[mt], b[np][h], b[np][h+1]);
                }
        }

        if (more) {
            int kk = (t+1)*32 + lks;
            union { uint4 q[2]; unsigned short us[16]; } H;
            #pragma unroll
            for (int q = 0; q < 4; q++) {
                float4 x = *(const float4*)(asrc + kk + q*4);
                H.us[q*4+0] = __half_as_ushort(__float2half_rn(x.x));
                H.us[q*4+1] = __half_as_ushort(__float2half_rn(x.y));
                H.us[q*4+2] = __half_as_ushort(__float2half_rn(x.z));
                H.us[q*4+3] = __half_as_ushort(__float2half_rn(x.w));
            }
            *(uint4*)&dsm[nxt*MATE + lrow*TROW + lks]     = H.q[0];
            *(uint4*)&dsm[nxt*MATE + lrow*TROW + lks + 8] = H.q[1];
        }
        CP_WAIT0();
        __syncthreads();
    }

    int g = lane >> 2, t4 = lane & 3;
    #pragma unroll
    for (int mt = 0; mt < 2; mt++) {
        float p0 = 0.f, p1 = 0.f;
        #pragma unroll
        for (int nt = 0; nt < 8; nt++) {
            int lc = wx*64 + nt*8 + 2*t4;
            p0 += fmaxf(c[mt][nt][0] + b1s[lc],   0.f)*w2s[lc]
                + fmaxf(c[mt][nt][1] + b1s[lc+1], 0.f)*w2s[lc+1];
            p1 += fmaxf(c[mt][nt][2] + b1s[lc],   0.f)*w2s[lc]
                + fmaxf(c[mt][nt][3] + b1s[lc+1], 0.f)*w2s[lc+1];
        }
        p0 += __shfl_xor_sync(0xffffffffu, p0, 1);
        p0 += __shfl_xor_sync(0xffffffffu, p0, 2);
        p1 += __shfl_xor_sync(0xffffffffu, p1, 1);
        p1 += __shfl_xor_sync(0xffffffffu, p1, 2);
        if (t4 == 0) {
            atomicAdd(&g_scores[m0 + wy*32 + mt*16 + g],     p0);
            atomicAdd(&g_scores[m0 + wy*32 + mt*16 + 8 + g], p1);
        }
    }
}

// ---------------- h1 HMMA kernel (A from g_prod, all-cp.async) ----------------
__global__ void __launch_bounds__(256)
h1_mma_kernel(const float* __restrict__ pb1)
{
    extern __shared__ __align__(16) char dsm8[];
    unsigned sb = smem_u32(dsm8);

    int tid = threadIdx.x, lane = tid & 31, wid = tid >> 5;
    int wy = wid & 3, wx = wid >> 2;
    int m0 = blockIdx.y*128, n0 = blockIdx.x*128;

    int lrow = tid >> 1, lks = (tid & 1)*16;
    const __half* asrc = g_prod + (long)(m0 + lrow)*KPAD1;
    const __half* bsrc = g_B1 + (long)(n0 + lrow)*KPAD1;
    unsigned srow = (unsigned)(lrow*TROW + lks)*2;

    float c[2][8][4];
    #pragma unroll
    for (int i = 0; i < 2; i++)
        #pragma unroll
        for (int j = 0; j < 8; j++)
            #pragma unroll
            for (int e = 0; e < 4; e++) c[i][j][e] = 0.f;

    {
        CP_ASYNC16(sb + 0*MATB + srow,      asrc + lks);
        CP_ASYNC16(sb + 0*MATB + srow + 16, asrc + lks + 8);
        CP_ASYNC16(sb + 2*MATB + srow,      bsrc + lks);
        CP_ASYNC16(sb + 2*MATB + srow + 16, bsrc + lks + 8);
        CP_COMMIT(); CP_WAIT0();
    }
    __syncthreads();

    for (int t = 0; t < NT1; t++) {
        int cur = t & 1, nxt = cur ^ 1;
        bool more = (t + 1 < NT1);

        if (more) {
            int kk = (t+1)*32 + lks;
            CP_ASYNC16(sb + nxt*MATB + srow,          asrc + kk);
            CP_ASYNC16(sb + nxt*MATB + srow + 16,     asrc + kk + 8);
            CP_ASYNC16(sb + (2+nxt)*MATB + srow,      bsrc + kk);
            CP_ASYNC16(sb + (2+nxt)*MATB + srow + 16, bsrc + kk + 8);
            CP_COMMIT();
        }

        unsigned sbA = sb + cur*MATB, sbB = sb + (2+cur)*MATB;
        #pragma unroll
        for (int kt = 0; kt < 2; kt++) {
            unsigned a[2][4], b[4][4];
            int arow = lane & 15, acol = (lane >> 4)*8;
            #pragma unroll
            for (int mt = 0; mt < 2; mt++) {
                unsigned off = (unsigned)(((wy*32 + mt*16 + arow)*TROW + kt*16 + acol)*2);
                ldsm_x4(a[mt][0], a[mt][1], a[mt][2], a[mt][3], sbA + off);
            }
            int nrow = (lane & 7) + ((lane >> 4) << 3), kc = lane & 8;
            #pragma unroll
            for (int np = 0; np < 4; np++) {
                unsigned off = (unsigned)(((wx*64 + np*16 + nrow)*TROW + kt*16 + kc)*2);
                ldsm_x4(b[np][0], b[np][1], b[np][2], b[np][3], sbB + off);
            }
            #pragma unroll
            for (int mt = 0; mt < 2; mt++)
                #pragma unroll
                for (int nt = 0; nt < 8; nt++) {
                    int np = nt >> 1, h = (nt & 1)*2;
                    mma_f16(c[mt][nt], a[mt], b[np][h], b[np][h+1]);
                }
        }
        CP_WAIT0();
        __syncthreads();
    }

    // epilogue: +bias +a +b, relu, store fp16
    int g = lane >> 2, t4 = lane & 3;
    #pragma unroll
    for (int mt = 0; mt < 2; mt++) {
        #pragma unroll
        for (int rr = 0; rr < 2; rr++) {
            int grow = m0 + wy*32 + mt*16 + rr*8 + g;
            int ii = (grow >> 4) & 15, jj = grow & 15, sv = grow >> 8;
            int rA = (sv >> 3)*MS + ii, rB = (sv & 7)*MS + jj;
            #pragma unroll
            for (int nt = 0; nt < 8; nt++) {
                int col = n0 + wx*64 + nt*8 + 2*t4;
                float v0 = c[mt][nt][rr*2+0] + pb1[col]
                         + g_a[rA*HH + col] + g_b[rB*HH + col];
                float v1 = c[mt][nt][rr*2+1] + pb1[col+1]
                         + g_a[rA*HH + col+1] + g_b[rB*HH + col+1];
                v0 = fmaxf(v0, 0.f); v1 = fmaxf(v1, 0.f);
                unsigned short h0 = __half_as_ushort(__float2half_rn(v0));
                unsigned short h1 = __half_as_ushort(__float2half_rn(v1));
                *(unsigned*)&g_h1[(long)grow*HH + col] = (unsigned)h0 | ((unsigned)h1 << 16);
            }
        }
    }
}

// ---------------- h2 HMMA kernel (all-cp.async; fused ts matvec) ----------------
__global__ void __launch_bounds__(256)
h2_mma_kernel(const float* __restrict__ pb2, const float* __restrict__ pw3)
{
    extern __shared__ __align__(16) char dsm8[];
    unsigned sb = smem_u32(dsm8);
    __shared__ float w3s[128], pb2s[128];

    int tid = threadIdx.x, lane = tid & 31, wid = tid >> 5;
    int wy = wid & 3, wx = wid >> 2;
    int m0 = blockIdx.y*128, n0 = blockIdx.x*128;

    if (tid < 128) { w3s[tid] = pw3[n0 + tid]; pb2s[tid] = pb2[n0 + tid]; }

    int lrow = tid >> 1, lks = (tid & 1)*16;
    const __half* asrc = g_h1 + (long)(m0 + lrow)*HH;
    const __half* bsrc = g_W2 + (long)(n0 + lrow)*KPAD2;
    unsigned srow = (unsigned)(lrow*TROW + lks)*2;

    float c[2][8][4];
    #pragma unroll
    for (int i = 0; i < 2; i++)
        #pragma unroll
        for (int j = 0; j < 8; j++)
            #pragma unroll
            for (int e = 0; e < 4; e++) c[i][j][e] = 0.f;

    {
        CP_ASYNC16(sb + 0*MATB + srow,      asrc + lks);
        CP_ASYNC16(sb + 0*MATB + srow + 16, asrc + lks + 8);
        CP_ASYNC16(sb + 2*MATB + srow,      bsrc + lks);
        CP_ASYNC16(sb + 2*MATB + srow + 16, bsrc + lks + 8);
        CP_COMMIT(); CP_WAIT0();
    }
    __syncthreads();

    for (int t = 0; t < NT2; t++) {
        int cur = t & 1, nxt = cur ^ 1;
        bool more = (t + 1 < NT2);

        if (more) {
            int kk = (t+1)*32 + lks;
            CP_ASYNC16(sb + nxt*MATB + srow,          asrc + kk);
            CP_ASYNC16(sb + nxt*MATB + srow + 16,     asrc + kk + 8);
            CP_ASYNC16(sb + (2+nxt)*MATB + srow,      bsrc + kk);
            CP_ASYNC16(sb + (2+nxt)*MATB + srow + 16, bsrc + kk + 8);
            CP_COMMIT();
        }

        unsigned sbA = sb + cur*MATB, sbB = sb + (2+cur)*MATB;
        #pragma unroll
        for (int kt = 0; kt < 2; kt++) {
            unsigned a[2][4], b[4][4];
            int arow = lane & 15, acol = (lane >> 4)*8;
            #pragma unroll
            for (int mt = 0; mt < 2; mt++) {
                unsigned off = (unsigned)(((wy*32 + mt*16 + arow)*TROW + kt*16 + acol)*2);
                ldsm_x4(a[mt][0], a[mt][1], a[mt][2], a[mt][3], sbA + off);
            }
            int nrow = (lane & 7) + ((lane >> 4) << 3), kc = lane & 8;
            #pragma unroll
            for (int np = 0; np < 4; np++) {
                unsigned off = (unsigned)(((wx*64 + np*16 + nrow)*TROW + kt*16 + kc)*2);
                ldsm_x4(b[np][0], b[np][1], b[np][2], b[np][3], sbB + off);
            }
            #pragma unroll
            for (int mt = 0; mt < 2; mt++)
                #pragma unroll
                for (int nt = 0; nt < 8; nt++) {
                    int np = nt >> 1, h = (nt & 1)*2;
                    mma_f16(c[mt][nt], a[mt], b[np][h], b[np][h+1]);
                }
        }
        CP_WAIT0();
        __syncthreads();
    }

    int g = lane >> 2, t4 = lane & 3;
    #pragma unroll
    for (int mt = 0; mt < 2; mt++) {
        float p0 = 0.f, p1 = 0.f;
        #pragma unroll
        for (int nt = 0; nt < 8; nt++) {
            int lc = wx*64 + nt*8 + 2*t4;
            p0 += fmaxf(c[mt][nt][0] + pb2s[lc],   0.f)*w3s[lc]
                + fmaxf(c[mt][nt][1] + pb2s[lc+1], 0.f)*w3s[lc+1];
            p1 += fmaxf(c[mt][nt][2] + pb2s[lc],   0.f)*w3s[lc]
                + fmaxf(c[mt][nt][3] + pb2s[lc+1], 0.f)*w3s[lc+1];
        }
        p0 += __shfl_xor_sync(0xffffffffu, p0, 1);
        p0 += __shfl_xor_sync(0xffffffffu, p0, 2);
        p1 += __shfl_xor_sync(0xffffffffu, p1, 1);
        p1 += __shfl_xor_sync(0xffffffffu, p1, 2);
        if (t4 == 0) {
            atomicAdd(&g_ts[m0 + wy*32 + mt*16 + g],     p0);
            atomicAdd(&g_ts[m0 + wy*32 + mt*16 + 8 + g], p1);
        }
    }
}

// ---------------- split-K fp32 GEMM computing g_a and g_b ----------------
#define BM 128
#define BN 128
#define BK 16
#define TM 8
#define TN 8
#define KS 16
#define KSLC 148   // multiple of 4; 16*148 = 2368 >= 2324

__global__ __launch_bounds__(256, 2)
void gemm_ab_kernel(const float* __restrict__ pw1)
{
    __shared__ __align__(16) float2 As2[BK][BM];
    __shared__ __align__(16) float  Bs[BK][BN];

    int tid = threadIdx.x;
    int n0 = blockIdx.x * BN;
    int kstart = blockIdx.y * KSLC;
    int kend = min(kstart + KSLC, SD);

    const float* Bsel = (n0 < HH) ? pw1 + n0 : pw1 + (long)SD*HH + (n0 - HH);
    float* Cout = (n0 < HH) ? g_a + n0 : g_b + (n0 - HH);

    int la_row = tid >> 1, la_cb = (tid & 1) * 8;
    int lb_row = tid >> 4, lb_col = (tid & 15) * 8;

    unsigned long long acc2[TM][TN/2];
    #pragma unroll
    for (int i = 0; i < TM; i++)
        #pragma unroll
        for (int j = 0; j < TN/2; j++) acc2[i][j] = 0ull;

    int tx = tid & 15, ty = tid >> 4;

    for (int k0 = kstart; k0 < kend; k0 += BK) {
        #pragma unroll
        for (int c = 0; c < 2; c++) {
            int k = k0 + la_cb + c*4;
            float4 v = make_float4(0.f,0.f,0.f,0.f);
            if (k < kend) v = *(const float4*)(g_spans + (long)la_row*SD + k);
            int kc = la_cb + c*4;
            As2[kc+0][la_row] = make_float2(v.x, v.x);
            As2[kc+1][la_row] = make_float2(v.y, v.y);
            As2[kc+2][la_row] = make_float2(v.z, v.z);
            As2[kc+3][la_row] = make_float2(v.w, v.w);
            int kb = k0 + lb_row;
            float4 w = make_float4(0.f,0.f,0.f,0.f);
            if (kb < kend) w = *(const float4*)(Bsel + (long)kb*HH + lb_col + c*4);
            *(float4*)&Bs[lb_row][lb_col + c*4] = w;
        }
        __syncthreads();
        #pragma unroll
        for (int kk = 0; kk < BK; kk++) {
            unsigned long long rm2[TM], rb2[TN/2];
            #pragma unroll
            for (int i = 0; i < TM; i += 2) {
                ulonglong2 v = *(const ulonglong2*)&As2[kk][ty*TM + i];
                rm2[i] = v.x; rm2[i+1] = v.y;
            }
            #pragma unroll
            for (int j = 0; j < TN/2; j += 2) {
                ulonglong2 v = *(const ulonglong2*)&Bs[kk][tx*TN + 2*j];
                rb2[j] = v.x; rb2[j+1] = v.y;
            }
            #pragma unroll
            for (int i = 0; i < TM; i++)
                #pragma unroll
                for (int j = 0; j < TN/2; j++)
                    FMA2(acc2[i][j], rm2[i], rb2[j]);
        }
        __syncthreads();
    }

    #pragma unroll
    for (int i = 0; i < TM; i++) {
        int row = ty*TM + i;
        #pragma unroll
        for (int j = 0; j < TN/2; j++) {
            int col = tx*TN + 2*j;
            float v0 = __uint_as_float((unsigned)(acc2[i][j] & 0xffffffffull));
            float v1 = __uint_as_float((unsigned)(acc2[i][j] >> 32));
            atomicAdd(Cout + (long)row*HH + col,     v0);
            atomicAdd(Cout + (long)row*HH + col + 1, v1);
        }
    }
}

// ---------------- span softmax + assemble spans (zeroes g_a/g_b) ----------------
__global__ void assemble_kernel(const float* __restrict__ se, const float* __restrict__ cont,
                                const int* __restrict__ width, const float* __restrict__ wemb)
{
    int b = blockIdx.x;
    int tid = threadIdx.x;
    __shared__ float attn[WW];
    int w = width[b];
    {   // zero g_a/g_b (runs strictly before gemm_ab)
        float4 z = make_float4(0.f,0.f,0.f,0.f);
        int gt = b*256 + tid;
        for (int i = gt; i < NSPAN*HH/4; i += 128*256) {
            ((float4*)g_a)[i] = z;
            ((float4*)g_b)[i] = z;
        }
    }
    if (tid == 0) {
        float sc[WW]; float mx = -INFINITY;
        for (int t = 0; t < WW; t++) {
            sc[t] = (t < w) ? g_scores[b*WW + t] : NEGV;
            mx = fmaxf(mx, sc[t]);
        }
        float sum = 0.f;
        for (int t = 0; t < WW; t++) { sc[t] = expf(sc[t] - mx); sum += sc[t]; }
        for (int t = 0; t < WW; t++) attn[t] = sc[t]/sum;
    }
    __syncthreads();
    float* row = g_spans + (long)b*SD;
    for (int k = tid; k < 2*BH; k += 256) row[k] = se[(long)b*2*BH + k];
    for (int d = tid; d < BH; d += 256) {
        float acc = 0.f;
        #pragma unroll
        for (int t = 0; t < WW; t++) acc += attn[t]*cont[((long)b*WW + t)*BH + d];
        row[2*BH + d] = acc;
    }
    if (tid < ED) row[2*BH + BH + tid] = wemb[min(w,4)*ED + tid];
    __syncthreads();
    __half* rh = g_spansh + (long)b*KPAD1;
    for (int k = tid; k < KPAD1; k += 256)
        rh[k] = __float2half_rn((k < SD) ? row[k] : 0.f);
}

// ---------------- grounding: att[s,v,i,j] = doc[s,i,:]·img[v,j,:] ----------------
__global__ void att_kernel(const float* __restrict__ doc, const float* __restrict__ img)
{
    int b = blockIdx.x, s = b >> 3, v = b & 7;
    for (int idx = threadIdx.x; idx < FF*RR; idx += blockDim.x) {
        int i = idx / RR, j = idx % RR;
        const float4* dr = (const float4*)(doc + (long)(s*FF + i)*DD);
        const float4* ir = (const float4*)(img + (long)(v*RR + j)*DD);
        float acc = 0.f;
        #pragma unroll 8
        for (int c = 0; c < DD/4; c++) {
            float4 x = dr[c], y = ir[c];
            acc += x.x*y.x + x.y*y.y + x.z*y.z + x.w*y.w;
        }
        g_att[((long)b*FF + i)*RR + j] = acc;
    }
}

// ---------------- grounding reduce -> S_g ----------------
__global__ void ground_reduce(const float* __restrict__ tm, const float* __restrict__ im)
{
    __shared__ float sh[FF][RR+1];
    __shared__ float stm[FF], sim[RR];
    __shared__ float red[FF];
    int b = blockIdx.x, s = b >> 3, v = b & 7;
    int tid = threadIdx.x; // 64
    if (tid < FF) stm[tid] = tm[s*FF + tid];
    if (tid < RR) sim[tid] = im[v*RR + tid];
    __syncthreads();
    for (int idx = tid; idx < FF*RR; idx += 64) {
        int i = idx / RR, j = idx % RR;
        float a = g_att[((long)b*FF + i)*RR + j];
        float m = stm[i]*sim[j];
        a *= m;
        if (a == 0.f) a = NEGV;
        sh[i][j] = a;
    }
    __syncthreads();
    float part = 0.f;
    {
        int i = tid;
        float mx = -INFINITY;
        for (int j = 0; j < RR; j++) mx = fmaxf(mx, sh[i][j]*sim[j]);
        float ssum = 0.f;
        for (int j = 0; j < RR; j++) ssum += expf(sh[i][j]*sim[j] - mx);
        for (int j = 0; j < RR; j++) {
            float aw = expf(sh[i][j]*sim[j] - mx)/ssum * stm[i]*sim[j];
            part += aw * sh[i][j];
        }
    }
    if (tid < RR) {
        int j = tid;
        float mx = -INFINITY;
        for (int i = 0; i < FF; i++) mx = fmaxf(mx, sh[i][j]);
        float ssum = 0.f;
        for (int i = 0; i < FF; i++) ssum += expf(sh[i][j] - mx);
        for (int i = 0; i < FF; i++) {
            float aw = expf(sh[i][j] - mx)/ssum * stm[i]*sim[j];
            part += aw * sh[i][j];
        }
    }
    red[tid] = part;
    __syncthreads();
    for (int o = 32; o > 0; o >>= 1) {
        if (tid < o) red[tid] += red[tid+o];
        __syncthreads();
    }
    if (tid == 0) g_Sg[b] = red[0];
}

// ---------------- adaptive S_c ----------------
__global__ void sc_kernel(const float* __restrict__ m1)
{
    int b = blockIdx.x, s = b >> 3, v = b & 7;
    const float* T = g_ts + (long)b*MS*MS;
    int lane = threadIdx.x;
    float cs = 0.f, cv = 0.f;
    for (int k = 0; k < MS; k++) { cs += m1[s*MS+k]; cv += m1[v*MS+k]; }
    float max1 = -INFINITY, max2 = -INFINITY;
    if (lane < MS) {
        float rm = 0.f;
        for (int j = 0; j < MS; j++) rm += T[lane*MS+j]*m1[v*MS+j];
        rm /= cv;
        if (m1[s*MS+lane] > 0.f) max1 = rm;
        float cm = 0.f;
        for (int i = 0; i < MS; i++) cm += T[i*MS+lane]*m1[s*MS+i];
        cm /= cs;
        if (m1[v*MS+lane] > 0.f) max2 = cm;
    }
    for (int o = 16; o > 0; o >>= 1) {
        max1 = fmaxf(max1, __shfl_xor_sync(0xffffffffu, max1, o));
        max2 = fmaxf(max2, __shfl_xor_sync(0xffffffffu, max2, o));
    }
    if (lane == 0) g_Sc[b] = 0.5f*(max1 + max2);
}

// ---------------- final loss ----------------
__global__ void loss_kernel(float* __restrict__ out)
{
    if (threadIdx.x != 0) return;
    float mg[8][8], mgT[8][8], mc[8][8];
    for (int s = 0; s < 8; s++) {
        float mx = -INFINITY;
        for (int v = 0; v < 8; v++) mx = fmaxf(mx, g_Sg[s*8+v]);
        float sum = 0.f;
        for (int v = 0; v < 8; v++) { mg[s][v] = expf(g_Sg[s*8+v]-mx); sum += mg[s][v]; }
        for (int v = 0; v < 8; v++) mg[s][v] /= sum;
    }
    for (int v = 0; v < 8; v++) {
        float mx = -INFINITY;
        for (int s = 0; s < 8; s++) mx = fmaxf(mx, g_Sg[s*8+v]);
        float sum = 0.f;
        for (int s = 0; s < 8; s++) { mgT[v][s] = expf(g_Sg[s*8+v]-mx); sum += mgT[v][s]; }
        for (int s = 0; s < 8; s++) mgT[v][s] /= sum;
    }
    for (int s = 0; s < 8; s++) {
        float mx = -INFINITY;
        for (int v = 0; v < 8; v++) mx = fmaxf(mx, g_Sc[s*8+v]);
        float sum = 0.f;
        for (int v = 0; v < 8; v++) { mc[s][v] = expf(g_Sc[s*8+v]-mx); sum += mc[s][v]; }
        for (int v = 0; v < 8; v++) mc[s][v] /= sum;
    }
    float loss = 0.f;
    for (int s = 0; s < 8; s++) {
        float t = 0.f;
        for (int v = 0; v < 8; v++) t += mg[s][v]*mc[s][v];
        loss += logf(t);
    }
    for (int v = 0; v < 8; v++) {
        float t = 0.f;
        for (int s = 0; s < 8; s++) t += mgT[v][s]*mc[v][s];
        loss += logf(t);
    }
    out[0] = -loss/(float)ND;
}

// ---------------- host ----------------
extern "C" void kernel_launch(void* const* d_in, const int* in_sizes, int n_in,
                              void* d_out, int out_size)
{
    const float* doc  = (const float*)d_in[0];
    const float* img  = (const float*)d_in[1];
    const float* tm   = (const float*)d_in[2];
    const float* im   = (const float*)d_in[3];
    const float* se   = (const float*)d_in[4];
    const float* cont = (const float*)d_in[5];
    const int*   width= (const int*)  d_in[6];
    const float* m1   = (const float*)d_in[7];
    const float* aw1  = (const float*)d_in[8];
    const float* ab1  = (const float*)d_in[9];
    const float* aw2  = (const float*)d_in[10];
    const float* ab2  = (const float*)d_in[11];
    const float* wemb = (const float*)d_in[12];
    const float* pw1  = (const float*)d_in[13];
    const float* pb1  = (const float*)d_in[14];
    const float* pw2  = (const float*)d_in[15];
    const float* pb2  = (const float*)d_in[16];
    const float* pw3  = (const float*)d_in[17];
    const float* pb3  = (const float*)d_in[18];

    cudaFuncSetAttribute(span_mma_kernel, cudaFuncAttributeMaxDynamicSharedMemorySize, DSMEM_MMA);
    cudaFuncSetAttribute(h1_mma_kernel, cudaFuncAttributeMaxDynamicSharedMemorySize, DSMEM_MMA);
    cudaFuncSetAttribute(h2_mma_kernel, cudaFuncAttributeMaxDynamicSharedMemorySize, DSMEM_MMA);

    // (1) weights -> fp16; init g_ts, g_scores
    int prep_total = PREP_G1 + PREP_G2 + PREP_G3 + NPAIR + 1280;
    prep_kernel<<<(prep_total + 255)/256, 256>>>(pw1, pw2, aw1, pb3, ab2);
    // (2) scores += relu(cont@W1T + b1).aw2  [fp16 HMMA, fused matvec]
    span_mma_kernel<<<dim3(HH/128, 1280/128), 256, DSMEM_MMA>>>(cont, ab1, aw2);
    // (3) assemble spans (fp32 + fp16, zero g_a/g_b)
    assemble_kernel<<<NSPAN, 256>>>(se, cont, width, wemb);
    // (4) materialize fp16 pair products
    prodgen_kernel<<<(int)((PRODG + 255)/256), 256>>>();
    // (5) a,b = spans @ w1 halves (split-K fp32, KS=16)
    gemm_ab_kernel<<<dim3(2048/BN, KS), 256>>>(pw1);
    // (6) h1 = relu(prod @ W1c + a + b + b1)  [fp16 HMMA, all-cp.async]
    h1_mma_kernel<<<dim3(8, 128), 256, DSMEM_MMA>>>(pb1);
    // (7) ts += relu(h1 @ W2 + b2) @ w3  [fp16 HMMA, fused]
    h2_mma_kernel<<<dim3(8, 128), 256, DSMEM_MMA>>>(pb2, pw3);

    // grounding (independent)
    att_kernel<<<64, 256>>>(doc, img);
    ground_reduce<<<64, 64>>>(tm, im);

    // adaptive S_c + final loss
    sc_kernel<<<64, 32>>>(m1);
    loss_kernel<<<1, 32>>>((float*)d_out);
}

// round 15
// speedup vs baseline: 1.9118x; 1.0125x over previous
#include <cuda_runtime.h>
#include <cuda_bf16.h>
#include <cuda_fp16.h>
#include <math.h>
#include <stdint.h>

// ---------------- problem constants ----------------
#define ND   8
#define FF   64
#define RR   36
#define DD   1024
#define MS   16
#define WW   10
#define BH   768
#define HH   1024
#define ED   20
#define SD   2324
#define NSPAN (ND*MS)          // 128
#define NPAIR (NSPAN*NSPAN)    // 16384
#define NEGV (-1e10f)

#define KPAD1 2368             // 74*32; fp8 bytes per h1 K-row
#define KPAD2 1024
#define KSP   768
#define NT1B  (KPAD1/64)       // 37 fp8 stages (64 bytes K per stage)
#define NT2   (KPAD2/32)
#define NTS   (KSP/32)
#define BSCALE 64.0f           // e4m3 scale for W1c
#define BINV  (1.0f/64.0f)

// ---------------- scratch ----------------
__device__ __align__(16) float g_scores[1280];
__device__ __align__(16) float g_spans[NSPAN*SD + 64];
__device__ __align__(16) __half g_spansh[NSPAN*KPAD1];
__device__ __align__(16) float g_a[NSPAN*HH];
__device__ __align__(16) float g_b[NSPAN*HH];
__device__ __align__(16) uint8_t g_B1[HH*KPAD1];        // e4m3, [n][k], scaled by 64
__device__ __align__(16) __half g_W2[HH*KPAD2];
__device__ __align__(16) __half g_W1T[HH*KSP];
__device__ __align__(16) uint8_t g_prod[(long)NPAIR*KPAD1]; // e4m3 pair products
__device__ __align__(16) __half g_h1[(long)NPAIR*HH];
__device__ __align__(16) float g_ts[NPAIR];
__device__ __align__(16) float g_att[64*FF*RR];
__device__ float g_Sg[64];
__device__ float g_Sc[64];

#define FMA2(d,a,b) asm("fma.rn.f32x2 %0, %1, %2, %0;" : "+l"(d) : "l"(a), "l"(b))

// ---------------- warp MMA helpers ----------------
__device__ __forceinline__ unsigned smem_u32(const void* p) {
    unsigned a;
    asm("{ .reg .u64 t; cvta.to.shared.u64 t, %1; cvt.u32.u64 %0, t; }" : "=r"(a) : "l"(p));
    return a;
}
__device__ __forceinline__ void ldsm_x4(unsigned& r0, unsigned& r1, unsigned& r2, unsigned& r3,
                                        unsigned addr) {
    asm volatile("ldmatrix.sync.aligned.m8n8.x4.shared.b16 {%0,%1,%2,%3}, [%4];"
                 : "=r"(r0), "=r"(r1), "=r"(r2), "=r"(r3) : "r"(addr));
}
__device__ __forceinline__ void mma_f16(float (&c)[4], const unsigned (&a)[4],
                                        unsigned b0, unsigned b1) {
    asm volatile(
        "mma.sync.aligned.m16n8k16.row.col.f32.f16.f16.f32 "
        "{%0,%1,%2,%3}, {%4,%5,%6,%7}, {%8,%9}, {%0,%1,%2,%3};"
        : "+f"(c[0]), "+f"(c[1]), "+f"(c[2]), "+f"(c[3])
        : "r"(a[0]), "r"(a[1]), "r"(a[2]), "r"(a[3]), "r"(b0), "r"(b1));
}
__device__ __forceinline__ void mma_fp8(float (&c)[4], const unsigned (&a)[4],
                                        unsigned b0, unsigned b1) {
    asm volatile(
        "mma.sync.aligned.m16n8k32.row.col.f32.e4m3.e4m3.f32 "
        "{%0,%1,%2,%3}, {%4,%5,%6,%7}, {%8,%9}, {%0,%1,%2,%3};"
        : "+f"(c[0]), "+f"(c[1]), "+f"(c[2]), "+f"(c[3])
        : "r"(a[0]), "r"(a[1]), "r"(a[2]), "r"(a[3]), "r"(b0), "r"(b1));
}
// pack 2 floats -> e4m3x2 (lo = first arg)
__device__ __forceinline__ unsigned short e4m3x2_f32(float lo, float hi) {
    unsigned short r;
    asm("cvt.rn.satfinite.e4m3x2.f32 %0, %1, %2;" : "=h"(r) : "f"(hi), "f"(lo));
    return r;
}
__device__ __forceinline__ unsigned short e4m3x2_h2(__half2 v) {
    unsigned short r;
    asm("cvt.rn.satfinite.e4m3x2.f16x2 %0, %1;" : "=h"(r) : "r"(*(unsigned*)&v));
    return r;
}
#define CP_ASYNC16(saddr, gptr) \
    asm volatile("cp.async.cg.shared.global [%0], [%1], 16;" :: "r"(saddr), "l"(gptr) : "memory")
#define CP_COMMIT() asm volatile("cp.async.commit_group;" ::: "memory")
#define CP_WAIT0()  asm volatile("cp.async.wait_group 0;" ::: "memory")

#define TROW 40                 // halfs; 80-byte row stride (same geometry for fp8)
#define MATB 10240
#define MATE (128*TROW)
#define DSMEM_MMA (4*MATB)      // 40960

// ---------------- prep: weights -> fp16/fp8 [n][k]; init g_ts, g_scores ----------------
#define PREP_G1 (HH*(KPAD1/8))
#define PREP_G2 (HH*(KPAD2/8))
#define PREP_G3 (HH*(KSP/8))
__global__ void prep_kernel(const float* __restrict__ pw1, const float* __restrict__ pw2,
                            const float* __restrict__ aw1, const float* __restrict__ pb3,
                            const float* __restrict__ ab2)
{
    int gid = blockIdx.x*256 + threadIdx.x;
    if (gid < PREP_G1) {
        // W1c -> e4m3 scaled by 64, [n][k]; 8 bytes per thread
        int n = gid % HH, kg = gid / HH;
        unsigned short us[4];
        #pragma unroll
        for (int e2 = 0; e2 < 4; e2++) {
            int k0 = kg*8 + e2*2;
            float v0 = (k0   < SD) ? pw1[((long)(2*SD + k0  ))*HH + n]*BSCALE : 0.f;
            float v1 = (k0+1 < SD) ? pw1[((long)(2*SD + k0+1))*HH + n]*BSCALE : 0.f;
            us[e2] = e4m3x2_f32(v0, v1);
        }
        *(unsigned long long*)(g_B1 + (long)n*KPAD1 + kg*8) =
            (unsigned long long)us[0] | ((unsigned long long)us[1] << 16)
          | ((unsigned long long)us[2] << 32) | ((unsigned long long)us[3] << 48);
    } else if (gid < PREP_G1 + PREP_G2) {
        int j = gid - PREP_G1;
        int n = j % HH, kg = j / HH;
        union { uint4 q; unsigned short us[8]; } H;
        #pragma unroll
        for (int e = 0; e < 8; e++) {
            int k = kg*8 + e;
            H.us[e] = __half_as_ushort(__float2half_rn(pw2[(long)k*HH + n]));
        }
        *(uint4*)(g_W2 + (long)n*KPAD2 + kg*8) = H.q;
    } else if (gid < PREP_G1 + PREP_G2 + PREP_G3) {
        int j = gid - PREP_G1 - PREP_G2;
        int n = j % HH, kg = j / HH;
        union { uint4 q; unsigned short us[8]; } H;
        #pragma unroll
        for (int e = 0; e < 8; e++) {
            int k = kg*8 + e;
            H.us[e] = __half_as_ushort(__float2half_rn(aw1[(long)k*HH + n]));
        }
        *(uint4*)(g_W1T + (long)n*KSP + kg*8) = H.q;
    } else {
        int i = gid - PREP_G1 - PREP_G2 - PREP_G3;
        if (i < NPAIR) g_ts[i] = pb3[0];
        else if (i < NPAIR + 1280) g_scores[i - NPAIR] = ab2[0];
    }
}

// ---------------- prodgen: g_prod[row,k] = e4m3(spansh[rA,k]*spansh[rB,k]) ----------------
#define PRODG ((long)NPAIR*(KPAD1/16))
__global__ void prodgen_kernel()
{
    long gid = (long)blockIdx.x*256 + threadIdx.x;
    if (gid >= PRODG) return;
    int row = (int)(gid / (KPAD1/16));
    int kg  = (int)(gid % (KPAD1/16));
    int k = kg*16;
    int ii = (row >> 4) & 15, jj = row & 15, sv = row >> 8;
    int rA = (sv >> 3)*MS + ii, rB = (sv & 7)*MS + jj;
    union { uint4 q[2]; __half2 h2[8]; } xa, xb;
    xa.q[0] = *(const uint4*)(g_spansh + (long)rA*KPAD1 + k);
    xa.q[1] = *(const uint4*)(g_spansh + (long)rA*KPAD1 + k + 8);
    xb.q[0] = *(const uint4*)(g_spansh + (long)rB*KPAD1 + k);
    xb.q[1] = *(const uint4*)(g_spansh + (long)rB*KPAD1 + k + 8);
    union { uint4 q; unsigned short us[8]; } r;
    #pragma unroll
    for (int e = 0; e < 8; e++)
        r.us[e] = e4m3x2_h2(__hmul2(xa.h2[e], xb.h2[e]));
    *(uint4*)(g_prod + (long)row*KPAD1 + k) = r.q;
}

// ---------------- span HMMA kernel: scores += relu(cont@W1T + b1) . aw2 ----------------
__global__ void __launch_bounds__(256)
span_mma_kernel(const float* __restrict__ cont, const float* __restrict__ ab1,
                const float* __restrict__ aw2)
{
    extern __shared__ __align__(16) char dsm8[];
    __half* dsm = (__half*)dsm8;
    unsigned sb = smem_u32(dsm8);
    __shared__ float w2s[128], b1s[128];

    int tid = threadIdx.x, lane = tid & 31, wid = tid >> 5;
    int wy = wid & 3, wx = wid >> 2;
    int m0 = blockIdx.y*128, n0 = blockIdx.x*128;

    if (tid < 128) { w2s[tid] = aw2[n0 + tid]; b1s[tid] = ab1[n0 + tid]; }

    int lrow = tid >> 1, lks = (tid & 1)*16;
    const float* asrc = cont + (long)(m0 + lrow)*KSP;
    const __half* bsrc = g_W1T + (long)(n0 + lrow)*KSP;
    unsigned srow = (unsigned)(lrow*TROW + lks)*2;

    float c[2][8][4];
    #pragma unroll
    for (int i = 0; i < 2; i++)
        #pragma unroll
        for (int j = 0; j < 8; j++)
            #pragma unroll
            for (int e = 0; e < 4; e++) c[i][j][e] = 0.f;

    {
        CP_ASYNC16(sb + 2*MATB + srow,      bsrc + lks);
        CP_ASYNC16(sb + 2*MATB + srow + 16, bsrc + lks + 8);
        CP_COMMIT();
        union { uint4 q[2]; unsigned short us[16]; } H;
        #pragma unroll
        for (int q = 0; q < 4; q++) {
            float4 x = *(const float4*)(asrc + lks + q*4);
            H.us[q*4+0] = __half_as_ushort(__float2half_rn(x.x));
            H.us[q*4+1] = __half_as_ushort(__float2half_rn(x.y));
            H.us[q*4+2] = __half_as_ushort(__float2half_rn(x.z));
            H.us[q*4+3] = __half_as_ushort(__float2half_rn(x.w));
        }
        *(uint4*)&dsm[0*MATE + lrow*TROW + lks]     = H.q[0];
        *(uint4*)&dsm[0*MATE + lrow*TROW + lks + 8] = H.q[1];
        CP_WAIT0();
    }
    __syncthreads();

    for (int t = 0; t < NTS; t++) {
        int cur = t & 1, nxt = cur ^ 1;
        bool more = (t + 1 < NTS);

        if (more) {
            int kk = (t+1)*32 + lks;
            CP_ASYNC16(sb + (2+nxt)*MATB + srow,      bsrc + kk);
            CP_ASYNC16(sb + (2+nxt)*MATB + srow + 16, bsrc + kk + 8);
            CP_COMMIT();
        }

        unsigned sbA = sb + cur*MATB, sbB = sb + (2+cur)*MATB;
        #pragma unroll
        for (int kt = 0; kt < 2; kt++) {
            unsigned a[2][4], b[4][4];
            int arow = lane & 15, acol = (lane >> 4)*8;
            #pragma unroll
            for (int mt = 0; mt < 2; mt++) {
                unsigned off = (unsigned)(((wy*32 + mt*16 + arow)*TROW + kt*16 + acol)*2);
                ldsm_x4(a[mt][0], a[mt][1], a[mt][2], a[mt][3], sbA + off);
            }
            int nrow = (lane & 7) + ((lane >> 4) << 3), kc = lane & 8;
            #pragma unroll
            for (int np = 0; np < 4; np++) {
                unsigned off = (unsigned)(((wx*64 + np*16 + nrow)*TROW + kt*16 + kc)*2);
                ldsm_x4(b[np][0], b[np][1], b[np][2], b[np][3], sbB + off);
            }
            #pragma unroll
            for (int mt = 0; mt < 2; mt++)
                #pragma unroll
                for (int nt = 0; nt < 8; nt++) {
                    int np = nt >> 1, h = (nt & 1)*2;
                    mma_f16(c[mt][nt], a[mt], b[np][h], b[np][h+1]);
                }
        }

        if (more) {
            int kk = (t+1)*32 + lks;
            union { uint4 q[2]; unsigned short us[16]; } H;
            #pragma unroll
            for (int q = 0; q < 4; q++) {
                float4 x = *(const float4*)(asrc + kk + q*4);
                H.us[q*4+0] = __half_as_ushort(__float2half_rn(x.x));
                H.us[q*4+1] = __half_as_ushort(__float2half_rn(x.y));
                H.us[q*4+2] = __half_as_ushort(__float2half_rn(x.z));
                H.us[q*4+3] = __half_as_ushort(__float2half_rn(x.w));
            }
            *(uint4*)&dsm[nxt*MATE + lrow*TROW + lks]     = H.q[0];
            *(uint4*)&dsm[nxt*MATE + lrow*TROW + lks + 8] = H.q[1];
        }
        CP_WAIT0();
        __syncthreads();
    }

    int g = lane >> 2, t4 = lane & 3;
    #pragma unroll
    for (int mt = 0; mt < 2; mt++) {
        float p0 = 0.f, p1 = 0.f;
        #pragma unroll
        for (int nt = 0; nt < 8; nt++) {
            int lc = wx*64 + nt*8 + 2*t4;
            p0 += fmaxf(c[mt][nt][0] + b1s[lc],   0.f)*w2s[lc]
                + fmaxf(c[mt][nt][1] + b1s[lc+1], 0.f)*w2s[lc+1];
            p1 += fmaxf(c[mt][nt][2] + b1s[lc],   0.f)*w2s[lc]
                + fmaxf(c[mt][nt][3] + b1s[lc+1], 0.f)*w2s[lc+1];
        }
        p0 += __shfl_xor_sync(0xffffffffu, p0, 1);
        p0 += __shfl_xor_sync(0xffffffffu, p0, 2);
        p1 += __shfl_xor_sync(0xffffffffu, p1, 1);
        p1 += __shfl_xor_sync(0xffffffffu, p1, 2);
        if (t4 == 0) {
            atomicAdd(&g_scores[m0 + wy*32 + mt*16 + g],     p0);
            atomicAdd(&g_scores[m0 + wy*32 + mt*16 + 8 + g], p1);
        }
    }
}

// ---------------- h1 MMA kernel (e4m3, all-cp.async, 64-byte K stages) ----------------
__global__ void __launch_bounds__(256)
h1_mma_kernel(const float* __restrict__ pb1)
{
    extern __shared__ __align__(16) char dsm8[];
    unsigned sb = smem_u32(dsm8);

    int tid = threadIdx.x, lane = tid & 31, wid = tid >> 5;
    int wy = wid & 3, wx = wid >> 2;
    int m0 = blockIdx.y*128, n0 = blockIdx.x*128;

    int lrow = tid >> 1, lkb = (tid & 1)*32;   // byte offset within 64-byte K payload
    const uint8_t* asrc = g_prod + (long)(m0 + lrow)*KPAD1;
    const uint8_t* bsrc = g_B1 + (long)(n0 + lrow)*KPAD1;
    unsigned srow = (unsigned)(lrow*80 + lkb);

    float c[2][8][4];
    #pragma unroll
    for (int i = 0; i < 2; i++)
        #pragma unroll
        for (int j = 0; j < 8; j++)
            #pragma unroll
            for (int e = 0; e < 4; e++) c[i][j][e] = 0.f;

    {
        CP_ASYNC16(sb + 0*MATB + srow,      asrc + lkb);
        CP_ASYNC16(sb + 0*MATB + srow + 16, asrc + lkb + 16);
        CP_ASYNC16(sb + 2*MATB + srow,      bsrc + lkb);
        CP_ASYNC16(sb + 2*MATB + srow + 16, bsrc + lkb + 16);
        CP_COMMIT(); CP_WAIT0();
    }
    __syncthreads();

    for (int t = 0; t < NT1B; t++) {
        int cur = t & 1, nxt = cur ^ 1;
        bool more = (t + 1 < NT1B);

        if (more) {
            int kk = (t+1)*64 + lkb;
            CP_ASYNC16(sb + nxt*MATB + srow,          asrc + kk);
            CP_ASYNC16(sb + nxt*MATB + srow + 16,     asrc + kk + 16);
            CP_ASYNC16(sb + (2+nxt)*MATB + srow,      bsrc + kk);
            CP_ASYNC16(sb + (2+nxt)*MATB + srow + 16, bsrc + kk + 16);
            CP_COMMIT();
        }

        unsigned sbA = sb + cur*MATB, sbB = sb + (2+cur)*MATB;
        #pragma unroll
        for (int kt = 0; kt < 2; kt++) {           // kt selects 32-byte K half
            unsigned a[2][4], b[4][4];
            int arow = lane & 15, acolb = (lane >> 4)*16;
            #pragma unroll
            for (int mt = 0; mt < 2; mt++) {
                unsigned off = (unsigned)((wy*32 + mt*16 + arow)*80 + kt*32 + acolb);
                ldsm_x4(a[mt][0], a[mt][1], a[mt][2], a[mt][3], sbA + off);
            }
            int nrow = (lane & 7) + ((lane >> 4) << 3), kcb = (lane & 8)*2;
            #pragma unroll
            for (int np = 0; np < 4; np++) {
                unsigned off = (unsigned)((wx*64 + np*16 + nrow)*80 + kt*32 + kcb);
                ldsm_x4(b[np][0], b[np][1], b[np][2], b[np][3], sbB + off);
            }
            #pragma unroll
            for (int mt = 0; mt < 2; mt++)
                #pragma unroll
                for (int nt = 0; nt < 8; nt++) {
                    int np = nt >> 1, h = (nt & 1)*2;
                    mma_fp8(c[mt][nt], a[mt], b[np][h], b[np][h+1]);
                }
        }
        CP_WAIT0();
        __syncthreads();
    }

    // epilogue: unscale, +bias +a +b, relu, store fp16
    int g = lane >> 2, t4 = lane & 3;
    #pragma unroll
    for (int mt = 0; mt < 2; mt++) {
        #pragma unroll
        for (int rr = 0; rr < 2; rr++) {
            int grow = m0 + wy*32 + mt*16 + rr*8 + g;
            int ii = (grow >> 4) & 15, jj = grow & 15, sv = grow >> 8;
            int rA = (sv >> 3)*MS + ii, rB = (sv & 7)*MS + jj;
            #pragma unroll
            for (int nt = 0; nt < 8; nt++) {
                int col = n0 + wx*64 + nt*8 + 2*t4;
                float v0 = c[mt][nt][rr*2+0]*BINV + pb1[col]
                         + g_a[rA*HH + col] + g_b[rB*HH + col];
                float v1 = c[mt][nt][rr*2+1]*BINV + pb1[col+1]
                         + g_a[rA*HH + col+1] + g_b[rB*HH + col+1];
                v0 = fmaxf(v0, 0.f); v1 = fmaxf(v1, 0.f);
                unsigned short h0 = __half_as_ushort(__float2half_rn(v0));
                unsigned short h1 = __half_as_ushort(__float2half_rn(v1));
                *(unsigned*)&g_h1[(long)grow*HH + col] = (unsigned)h0 | ((unsigned)h1 << 16);
            }
        }
    }
}

// ---------------- h2 HMMA kernel (fp16, all-cp.async; fused ts matvec) ----------------
__global__ void __launch_bounds__(256)
h2_mma_kernel(const float* __restrict__ pb2, const float* __restrict__ pw3)
{
    extern __shared__ __align__(16) char dsm8[];
    unsigned sb = smem_u32(dsm8);
    __shared__ float w3s[128], pb2s[128];

    int tid = threadIdx.x, lane = tid & 31, wid = tid >> 5;
    int wy = wid & 3, wx = wid >> 2;
    int m0 = blockIdx.y*128, n0 = blockIdx.x*128;

    if (tid < 128) { w3s[tid] = pw3[n0 + tid]; pb2s[tid] = pb2[n0 + tid]; }

    int lrow = tid >> 1, lks = (tid & 1)*16;
    const __half* asrc = g_h1 + (long)(m0 + lrow)*HH;
    const __half* bsrc = g_W2 + (long)(n0 + lrow)*KPAD2;
    unsigned srow = (unsigned)(lrow*TROW + lks)*2;

    float c[2][8][4];
    #pragma unroll
    for (int i = 0; i < 2; i++)
        #pragma unroll
        for (int j = 0; j < 8; j++)
            #pragma unroll
            for (int e = 0; e < 4; e++) c[i][j][e] = 0.f;

    {
        CP_ASYNC16(sb + 0*MATB + srow,      asrc + lks);
        CP_ASYNC16(sb + 0*MATB + srow + 16, asrc + lks + 8);
        CP_ASYNC16(sb + 2*MATB + srow,      bsrc + lks);
        CP_ASYNC16(sb + 2*MATB + srow + 16, bsrc + lks + 8);
        CP_COMMIT(); CP_WAIT0();
    }
    __syncthreads();

    for (int t = 0; t < NT2; t++) {
        int cur = t & 1, nxt = cur ^ 1;
        bool more = (t + 1 < NT2);

        if (more) {
            int kk = (t+1)*32 + lks;
            CP_ASYNC16(sb + nxt*MATB + srow,          asrc + kk);
            CP_ASYNC16(sb + nxt*MATB + srow + 16,     asrc + kk + 8);
            CP_ASYNC16(sb + (2+nxt)*MATB + srow,      bsrc + kk);
            CP_ASYNC16(sb + (2+nxt)*MATB + srow + 16, bsrc + kk + 8);
            CP_COMMIT();
        }

        unsigned sbA = sb + cur*MATB, sbB = sb + (2+cur)*MATB;
        #pragma unroll
        for (int kt = 0; kt < 2; kt++) {
            unsigned a[2][4], b[4][4];
            int arow = lane & 15, acol = (lane >> 4)*8;
            #pragma unroll
            for (int mt = 0; mt < 2; mt++) {
                unsigned off = (unsigned)(((wy*32 + mt*16 + arow)*TROW + kt*16 + acol)*2);
                ldsm_x4(a[mt][0], a[mt][1], a[mt][2], a[mt][3], sbA + off);
            }
            int nrow = (lane & 7) + ((lane >> 4) << 3), kc = lane & 8;
            #pragma unroll
            for (int np = 0; np < 4; np++) {
                unsigned off = (unsigned)(((wx*64 + np*16 + nrow)*TROW + kt*16 + kc)*2);
                ldsm_x4(b[np][0], b[np][1], b[np][2], b[np][3], sbB + off);
            }
            #pragma unroll
            for (int mt = 0; mt < 2; mt++)
                #pragma unroll
                for (int nt = 0; nt < 8; nt++) {
                    int np = nt >> 1, h = (nt & 1)*2;
                    mma_f16(c[mt][nt], a[mt], b[np][h], b[np][h+1]);
                }
        }
        CP_WAIT0();
        __syncthreads();
    }

    int g = lane >> 2, t4 = lane & 3;
    #pragma unroll
    for (int mt = 0; mt < 2; mt++) {
        float p0 = 0.f, p1 = 0.f;
        #pragma unroll
        for (int nt = 0; nt < 8; nt++) {
            int lc = wx*64 + nt*8 + 2*t4;
            p0 += fmaxf(c[mt][nt][0] + pb2s[lc],   0.f)*w3s[lc]
                + fmaxf(c[mt][nt][1] + pb2s[lc+1], 0.f)*w3s[lc+1];
            p1 += fmaxf(c[mt][nt][2] + pb2s[lc],   0.f)*w3s[lc]
                + fmaxf(c[mt][nt][3] + pb2s[lc+1], 0.f)*w3s[lc+1];
        }
        p0 += __shfl_xor_sync(0xffffffffu, p0, 1);
        p0 += __shfl_xor_sync(0xffffffffu, p0, 2);
        p1 += __shfl_xor_sync(0xffffffffu, p1, 1);
        p1 += __shfl_xor_sync(0xffffffffu, p1, 2);
        if (t4 == 0) {
            atomicAdd(&g_ts[m0 + wy*32 + mt*16 + g],     p0);
            atomicAdd(&g_ts[m0 + wy*32 + mt*16 + 8 + g], p1);
        }
    }
}

// ---------------- split-K fp32 GEMM computing g_a and g_b ----------------
#define BM 128
#define BN 128
#define BK 16
#define TM 8
#define TN 8
#define KS 16
#define KSLC 148

__global__ __launch_bounds__(256, 2)
void gemm_ab_kernel(const float* __restrict__ pw1)
{
    __shared__ __align__(16) float2 As2[BK][BM];
    __shared__ __align__(16) float  Bs[BK][BN];

    int tid = threadIdx.x;
    int n0 = blockIdx.x * BN;
    int kstart = blockIdx.y * KSLC;
    int kend = min(kstart + KSLC, SD);

    const float* Bsel = (n0 < HH) ? pw1 + n0 : pw1 + (long)SD*HH + (n0 - HH);
    float* Cout = (n0 < HH) ? g_a + n0 : g_b + (n0 - HH);

    int la_row = tid >> 1, la_cb = (tid & 1) * 8;
    int lb_row = tid >> 4, lb_col = (tid & 15) * 8;

    unsigned long long acc2[TM][TN/2];
    #pragma unroll
    for (int i = 0; i < TM; i++)
        #pragma unroll
        for (int j = 0; j < TN/2; j++) acc2[i][j] = 0ull;

    int tx = tid & 15, ty = tid >> 4;

    for (int k0 = kstart; k0 < kend; k0 += BK) {
        #pragma unroll
        for (int c = 0; c < 2; c++) {
            int k = k0 + la_cb + c*4;
            float4 v = make_float4(0.f,0.f,0.f,0.f);
            if (k < kend) v = *(const float4*)(g_spans + (long)la_row*SD + k);
            int kc = la_cb + c*4;
            As2[kc+0][la_row] = make_float2(v.x, v.x);
            As2[kc+1][la_row] = make_float2(v.y, v.y);
            As2[kc+2][la_row] = make_float2(v.z, v.z);
            As2[kc+3][la_row] = make_float2(v.w, v.w);
            int kb = k0 + lb_row;
            float4 w = make_float4(0.f,0.f,0.f,0.f);
            if (kb < kend) w = *(const float4*)(Bsel + (long)kb*HH + lb_col + c*4);
            *(float4*)&Bs[lb_row][lb_col + c*4] = w;
        }
        __syncthreads();
        #pragma unroll
        for (int kk = 0; kk < BK; kk++) {
            unsigned long long rm2[TM], rb2[TN/2];
            #pragma unroll
            for (int i = 0; i < TM; i += 2) {
                ulonglong2 v = *(const ulonglong2*)&As2[kk][ty*TM + i];
                rm2[i] = v.x; rm2[i+1] = v.y;
            }
            #pragma unroll
            for (int j = 0; j < TN/2; j += 2) {
                ulonglong2 v = *(const ulonglong2*)&Bs[kk][tx*TN + 2*j];
                rb2[j] = v.x; rb2[j+1] = v.y;
            }
            #pragma unroll
            for (int i = 0; i < TM; i++)
                #pragma unroll
                for (int j = 0; j < TN/2; j++)
                    FMA2(acc2[i][j], rm2[i], rb2[j]);
        }
        __syncthreads();
    }

    #pragma unroll
    for (int i = 0; i < TM; i++) {
        int row = ty*TM + i;
        #pragma unroll
        for (int j = 0; j < TN/2; j++) {
            int col = tx*TN + 2*j;
            float v0 = __uint_as_float((unsigned)(acc2[i][j] & 0xffffffffull));
            float v1 = __uint_as_float((unsigned)(acc2[i][j] >> 32));
            atomicAdd(Cout + (long)row*HH + col,     v0);
            atomicAdd(Cout + (long)row*HH + col + 1, v1);
        }
    }
}

// ---------------- span softmax + assemble spans (zeroes g_a/g_b) ----------------
__global__ void assemble_kernel(const float* __restrict__ se, const float* __restrict__ cont,
                                const int* __restrict__ width, const float* __restrict__ wemb)
{
    int b = blockIdx.x;
    int tid = threadIdx.x;
    __shared__ float attn[WW];
    int w = width[b];
    {
        float4 z = make_float4(0.f,0.f,0.f,0.f);
        int gt = b*256 + tid;
        for (int i = gt; i < NSPAN*HH/4; i += 128*256) {
            ((float4*)g_a)[i] = z;
            ((float4*)g_b)[i] = z;
        }
    }
    if (tid == 0) {
        float sc[WW]; float mx = -INFINITY;
        for (int t = 0; t < WW; t++) {
            sc[t] = (t < w) ? g_scores[b*WW + t] : NEGV;
            mx = fmaxf(mx, sc[t]);
        }
        float sum = 0.f;
        for (int t = 0; t < WW; t++) { sc[t] = expf(sc[t] - mx); sum += sc[t]; }
        for (int t = 0; t < WW; t++) attn[t] = sc[t]/sum;
    }
    __syncthreads();
    float* row = g_spans + (long)b*SD;
    for (int k = tid; k < 2*BH; k += 256) row[k] = se[(long)b*2*BH + k];
    for (int d = tid; d < BH; d += 256) {
        float acc = 0.f;
        #pragma unroll
        for (int t = 0; t < WW; t++) acc += attn[t]*cont[((long)b*WW + t)*BH + d];
        row[2*BH + d] = acc;
    }
    if (tid < ED) row[2*BH + BH + tid] = wemb[min(w,4)*ED + tid];
    __syncthreads();
    __half* rh = g_spansh + (long)b*KPAD1;
    for (int k = tid; k < KPAD1; k += 256)
        rh[k] = __float2half_rn((k < SD) ? row[k] : 0.f);
}

// ---------------- grounding: att[s,v,i,j] = doc[s,i,:]·img[v,j,:] ----------------
__global__ void att_kernel(const float* __restrict__ doc, const float* __restrict__ img)
{
    int b = blockIdx.x, s = b >> 3, v = b & 7;
    for (int idx = threadIdx.x; idx < FF*RR; idx += blockDim.x) {
        int i = idx / RR, j = idx % RR;
        const float4* dr = (const float4*)(doc + (long)(s*FF + i)*DD);
        const float4* ir = (const float4*)(img + (long)(v*RR + j)*DD);
        float acc = 0.f;
        #pragma unroll 8
        for (int c = 0; c < DD/4; c++) {
            float4 x = dr[c], y = ir[c];
            acc += x.x*y.x + x.y*y.y + x.z*y.z + x.w*y.w;
        }
        g_att[((long)b*FF + i)*RR + j] = acc;
    }
}

// ---------------- grounding reduce -> S_g ----------------
__global__ void ground_reduce(const float* __restrict__ tm, const float* __restrict__ im)
{
    __shared__ float sh[FF][RR+1];
    __shared__ float stm[FF], sim[RR];
    __shared__ float red[FF];
    int b = blockIdx.x, s = b >> 3, v = b & 7;
    int tid = threadIdx.x; // 64
    if (tid < FF) stm[tid] = tm[s*FF + tid];
    if (tid < RR) sim[tid] = im[v*RR + tid];
    __syncthreads();
    for (int idx = tid; idx < FF*RR; idx += 64) {
        int i = idx / RR, j = idx % RR;
        float a = g_att[((long)b*FF + i)*RR + j];
        float m = stm[i]*sim[j];
        a *= m;
        if (a == 0.f) a = NEGV;
        sh[i][j] = a;
    }
    __syncthreads();
    float part = 0.f;
    {
        int i = tid;
        float mx = -INFINITY;
        for (int j = 0; j < RR; j++) mx = fmaxf(mx, sh[i][j]*sim[j]);
        float ssum = 0.f;
        for (int j = 0; j < RR; j++) ssum += expf(sh[i][j]*sim[j] - mx);
        for (int j = 0; j < RR; j++) {
            float aw = expf(sh[i][j]*sim[j] - mx)/ssum * stm[i]*sim[j];
            part += aw * sh[i][j];
        }
    }
    if (tid < RR) {
        int j = tid;
        float mx = -INFINITY;
        for (int i = 0; i < FF; i++) mx = fmaxf(mx, sh[i][j]);
        float ssum = 0.f;
        for (int i = 0; i < FF; i++) ssum += expf(sh[i][j] - mx);
        for (int i = 0; i < FF; i++) {
            float aw = expf(sh[i][j] - mx)/ssum * stm[i]*sim[j];
            part += aw * sh[i][j];
        }
    }
    red[tid] = part;
    __syncthreads();
    for (int o = 32; o > 0; o >>= 1) {
        if (tid < o) red[tid] += red[tid+o];
        __syncthreads();
    }
    if (tid == 0) g_Sg[b] = red[0];
}

// ---------------- adaptive S_c ----------------
__global__ void sc_kernel(const float* __restrict__ m1)
{
    int b = blockIdx.x, s = b >> 3, v = b & 7;
    const float* T = g_ts + (long)b*MS*MS;
    int lane = threadIdx.x;
    float cs = 0.f, cv = 0.f;
    for (int k = 0; k < MS; k++) { cs += m1[s*MS+k]; cv += m1[v*MS+k]; }
    float max1 = -INFINITY, max2 = -INFINITY;
    if (lane < MS) {
        float rm = 0.f;
        for (int j = 0; j < MS; j++) rm += T[lane*MS+j]*m1[v*MS+j];
        rm /= cv;
        if (m1[s*MS+lane] > 0.f) max1 = rm;
        float cm = 0.f;
        for (int i = 0; i < MS; i++) cm += T[i*MS+lane]*m1[s*MS+i];
        cm /= cs;
        if (m1[v*MS+lane] > 0.f) max2 = cm;
    }
    for (int o = 16; o > 0; o >>= 1) {
        max1 = fmaxf(max1, __shfl_xor_sync(0xffffffffu, max1, o));
        max2 = fmaxf(max2, __shfl_xor_sync(0xffffffffu, max2, o));
    }
    if (lane == 0) g_Sc[b] = 0.5f*(max1 + max2);
}

// ---------------- final loss ----------------
__global__ void loss_kernel(float* __restrict__ out)
{
    if (threadIdx.x != 0) return;
    float mg[8][8], mgT[8][8], mc[8][8];
    for (int s = 0; s < 8; s++) {
        float mx = -INFINITY;
        for (int v = 0; v < 8; v++) mx = fmaxf(mx, g_Sg[s*8+v]);
        float sum = 0.f;
        for (int v = 0; v < 8; v++) { mg[s][v] = expf(g_Sg[s*8+v]-mx); sum += mg[s][v]; }
        for (int v = 0; v < 8; v++) mg[s][v] /= sum;
    }
    for (int v = 0; v < 8; v++) {
        float mx = -INFINITY;
        for (int s = 0; s < 8; s++) mx = fmaxf(mx, g_Sg[s*8+v]);
        float sum = 0.f;
        for (int s = 0; s < 8; s++) { mgT[v][s] = expf(g_Sg[s*8+v]-mx); sum += mgT[v][s]; }
        for (int s = 0; s < 8; s++) mgT[v][s] /= sum;
    }
    for (int s = 0; s < 8; s++) {
        float mx = -INFINITY;
        for (int v = 0; v < 8; v++) mx = fmaxf(mx, g_Sc[s*8+v]);
        float sum = 0.f;
        for (int v = 0; v < 8; v++) { mc[s][v] = expf(g_Sc[s*8+v]-mx); sum += mc[s][v]; }
        for (int v = 0; v < 8; v++) mc[s][v] /= sum;
    }
    float loss = 0.f;
    for (int s = 0; s < 8; s++) {
        float t = 0.f;
        for (int v = 0; v < 8; v++) t += mg[s][v]*mc[s][v];
        loss += logf(t);
    }
    for (int v = 0; v < 8; v++) {
        float t = 0.f;
        for (int s = 0; s < 8; s++) t += mgT[v][s]*mc[v][s];
        loss += logf(t);
    }
    out[0] = -loss/(float)ND;
}

// ---------------- host ----------------
extern "C" void kernel_launch(void* const* d_in, const int* in_sizes, int n_in,
                              void* d_out, int out_size)
{
    const float* doc  = (const float*)d_in[0];
    const float* img  = (const float*)d_in[1];
    const float* tm   = (const float*)d_in[2];
    const float* im   = (const float*)d_in[3];
    const float* se   = (const float*)d_in[4];
    const float* cont = (const float*)d_in[5];
    const int*   width= (const int*)  d_in[6];
    const float* m1   = (const float*)d_in[7];
    const float* aw1  = (const float*)d_in[8];
    const float* ab1  = (const float*)d_in[9];
    const float* aw2  = (const float*)d_in[10];
    const float* ab2  = (const float*)d_in[11];
    const float* wemb = (const float*)d_in[12];
    const float* pw1  = (const float*)d_in[13];
    const float* pb1  = (const float*)d_in[14];
    const float* pw2  = (const float*)d_in[15];
    const float* pb2  = (const float*)d_in[16];
    const float* pw3  = (const float*)d_in[17];
    const float* pb3  = (const float*)d_in[18];

    cudaFuncSetAttribute(span_mma_kernel, cudaFuncAttributeMaxDynamicSharedMemorySize, DSMEM_MMA);
    cudaFuncSetAttribute(h1_mma_kernel, cudaFuncAttributeMaxDynamicSharedMemorySize, DSMEM_MMA);
    cudaFuncSetAttribute(h2_mma_kernel, cudaFuncAttributeMaxDynamicSharedMemorySize, DSMEM_MMA);

    // (1) weights -> fp16/fp8; init g_ts, g_scores
    int prep_total = PREP_G1 + PREP_G2 + PREP_G3 + NPAIR + 1280;
    prep_kernel<<<(prep_total + 255)/256, 256>>>(pw1, pw2, aw1, pb3, ab2);
    // (2) scores += relu(cont@W1T + b1).aw2  [fp16 HMMA, fused matvec]
    span_mma_kernel<<<dim3(HH/128, 1280/128), 256, DSMEM_MMA>>>(cont, ab1, aw2);
    // (3) assemble spans (fp32 + fp16, zero g_a/g_b)
    assemble_kernel<<<NSPAN, 256>>>(se, cont, width, wemb);
    // (4) materialize e4m3 pair products
    prodgen_kernel<<<(int)((PRODG + 255)/256), 256>>>();
    // (5) a,b = spans @ w1 halves (split-K fp32)
    gemm_ab_kernel<<<dim3(2048/BN, KS), 256>>>(pw1);
    // (6) h1 = relu(prod @ W1c + a + b + b1)  [e4m3 QMMA, all-cp.async]
    h1_mma_kernel<<<dim3(8, 128), 256, DSMEM_MMA>>>(pb1);
    // (7) ts += relu(h1 @ W2 + b2) @ w3  [fp16 HMMA, fused]
    h2_mma_kernel<<<dim3(8, 128), 256, DSMEM_MMA>>>(pb2, pw3);

    // grounding (independent)
    att_kernel<<<64, 256>>>(doc, img);
    ground_reduce<<<64, 64>>>(tm, im);

    // adaptive S_c + final loss
    sc_kernel<<<64, 32>>>(m1);
    loss_kernel<<<1, 32>>>((float*)d_out);
}